// round 1
// baseline (speedup 1.0000x reference)
#include <cuda_runtime.h>
#include <cstdint>

// Problem constants
#define MTOT   200704          // nW*49 = 4096*49
#define CC     256
#define NQKV   768
#define NWIN   4096
#define NTOK   49
#define HEADS  8
#define HD     32

// Scratch (device globals; no cudaMalloc allowed)
__device__ float g_qkv[154140672];   // [MTOT][768]  (616 MB)
__device__ float g_att[ 51380224];   // [MTOT][256]  (205 MB)

// Map a token row r (window-major order) to the element offset of its pixel row in x[B,224,224,256]
__device__ __forceinline__ int xrow_offset(int r) {
    int w   = r / 49;
    int t   = r - w * 49;
    int b   = w >> 10;          // 1024 windows per batch (32*32)
    int rem = w & 1023;
    int wh  = rem >> 5;
    int ww  = rem & 31;
    int i   = t / 7;
    int j   = t - i * 7;
    int row = (b * 224 + wh * 7 + i) * 224 + (ww * 7 + j);
    return row << 8;            // * 256 channels
}

// ---------------------------------------------------------------------------
// K1: qkv = gather(x) @ w_qkv + b_qkv     [200704 x 768], K=256
// Tile 128x128, BK=16, 256 threads, 8x8 per thread.
// ---------------------------------------------------------------------------
__global__ __launch_bounds__(256, 2)
void qkv_gemm(const float* __restrict__ x,
              const float* __restrict__ w,
              const float* __restrict__ bias)
{
    __shared__ float As[16][128];
    __shared__ float Bs[16][128];
    __shared__ int   arow[128];

    const int tid = threadIdx.x;
    const int m0  = blockIdx.y * 128;
    const int n0  = blockIdx.x * 128;
    if (tid < 128) arow[tid] = xrow_offset(m0 + tid);

    const int ty = tid >> 4;   // 0..15
    const int tx = tid & 15;   // 0..15

    float acc[8][8];
    #pragma unroll
    for (int i = 0; i < 8; i++)
        #pragma unroll
        for (int j = 0; j < 8; j++) acc[i][j] = 0.f;

    __syncthreads();

    for (int kt = 0; kt < 256; kt += 16) {
        #pragma unroll
        for (int q = 0; q < 2; q++) {
            int f   = q * 256 + tid;          // 512 float4 for A (128 rows x 4)
            int row = f >> 2;
            int kq  = (f & 3) << 2;
            float4 av = *(const float4*)(x + arow[row] + kt + kq);
            As[kq + 0][row] = av.x;
            As[kq + 1][row] = av.y;
            As[kq + 2][row] = av.z;
            As[kq + 3][row] = av.w;

            int kr = f >> 5;                  // 512 float4 for B (16 rows x 32)
            int c4 = (f & 31) << 2;
            *(float4*)&Bs[kr][c4] = *(const float4*)(w + (kt + kr) * 768 + n0 + c4);
        }
        __syncthreads();

        #pragma unroll
        for (int k = 0; k < 16; k++) {
            float a[8], b[8];
            *(float4*)(a)     = *(float4*)&As[k][ty * 8];
            *(float4*)(a + 4) = *(float4*)&As[k][ty * 8 + 4];
            *(float4*)(b)     = *(float4*)&Bs[k][tx * 8];
            *(float4*)(b + 4) = *(float4*)&Bs[k][tx * 8 + 4];
            #pragma unroll
            for (int i = 0; i < 8; i++)
                #pragma unroll
                for (int j = 0; j < 8; j++)
                    acc[i][j] += a[i] * b[j];
        }
        __syncthreads();
    }

    float bq[8];
    #pragma unroll
    for (int j = 0; j < 8; j++) bq[j] = bias[n0 + tx * 8 + j];

    #pragma unroll
    for (int i = 0; i < 8; i++) {
        size_t ro = (size_t)(m0 + ty * 8 + i) * 768 + n0 + tx * 8;
        float4 o0 = make_float4(acc[i][0] + bq[0], acc[i][1] + bq[1],
                                acc[i][2] + bq[2], acc[i][3] + bq[3]);
        float4 o1 = make_float4(acc[i][4] + bq[4], acc[i][5] + bq[5],
                                acc[i][6] + bq[6], acc[i][7] + bq[7]);
        *(float4*)(g_qkv + ro)     = o0;
        *(float4*)(g_qkv + ro + 4) = o1;
    }
}

// ---------------------------------------------------------------------------
// K2: per-(window, head) attention. softmax(q k^T * 0.5 + bias) v
// One block = one (window, head). 128 threads.
// ---------------------------------------------------------------------------
__global__ __launch_bounds__(128)
void attn_kernel(const float* __restrict__ bias_table)
{
    __shared__ float qs[49][33];
    __shared__ float ks[49][33];
    __shared__ float vs[49][33];
    __shared__ float sm[49][50];

    const int tid = threadIdx.x;
    const int w   = blockIdx.x;
    const int h   = blockIdx.y;

    const float* qb = g_qkv + (size_t)w * 49 * 768 + h * 32;

    // load q,k,v tiles (49x32 each) as float4, scalar-store into padded smem
    for (int idx = tid; idx < 392; idx += 128) {   // 49*32/4
        int t = idx >> 3;
        int d = (idx & 7) << 2;
        const float* rp = qb + t * 768 + d;
        float4 qv = *(const float4*)(rp);
        float4 kv = *(const float4*)(rp + 256);
        float4 vv = *(const float4*)(rp + 512);
        qs[t][d] = qv.x; qs[t][d+1] = qv.y; qs[t][d+2] = qv.z; qs[t][d+3] = qv.w;
        ks[t][d] = kv.x; ks[t][d+1] = kv.y; ks[t][d+2] = kv.z; ks[t][d+3] = kv.w;
        vs[t][d] = vv.x; vs[t][d+1] = vv.y; vs[t][d+2] = vv.z; vs[t][d+3] = vv.w;
    }
    __syncthreads();

    // scores + relative position bias
    for (int e = tid; e < 2401; e += 128) {
        int qi = e / 49;
        int ki = e - qi * 49;
        float acc = 0.f;
        #pragma unroll
        for (int d = 0; d < 32; d++) acc += qs[qi][d] * ks[ki][d];
        int i1 = qi / 7, j1 = qi - i1 * 7;
        int i2 = ki / 7, j2 = ki - i2 * 7;
        int bidx = (i1 - i2 + 6) * 13 + (j1 - j2 + 6);
        sm[qi][ki] = acc * 0.5f + bias_table[bidx * 8 + h];
    }
    __syncthreads();

    // row softmax: one warp per row, rows strided by 4
    const int warp = tid >> 5;
    const int lane = tid & 31;
    for (int r = warp; r < 49; r += 4) {
        float v0 = (lane < 49)      ? sm[r][lane]      : -1e30f;
        float v1 = (lane + 32 < 49) ? sm[r][lane + 32] : -1e30f;
        float mx = fmaxf(v0, v1);
        #pragma unroll
        for (int o = 16; o; o >>= 1) mx = fmaxf(mx, __shfl_xor_sync(0xffffffffu, mx, o));
        float e0 = (lane < 49)      ? __expf(v0 - mx) : 0.f;
        float e1 = (lane + 32 < 49) ? __expf(v1 - mx) : 0.f;
        float s  = e0 + e1;
        #pragma unroll
        for (int o = 16; o; o >>= 1) s += __shfl_xor_sync(0xffffffffu, s, o);
        float inv = 1.0f / s;
        if (lane < 49)      sm[r][lane]      = e0 * inv;
        if (lane + 32 < 49) sm[r][lane + 32] = e1 * inv;
    }
    __syncthreads();

    // out = P @ V, write to g_att[w*49+t][h*32+d]
    for (int e = tid; e < 1568; e += 128) {   // 49*32
        int t = e >> 5;
        int d = e & 31;
        float acc = 0.f;
        #pragma unroll
        for (int k = 0; k < 49; k++) acc += sm[t][k] * vs[k][d];
        g_att[((size_t)w * 49 + t) * 256 + h * 32 + d] = acc;
    }
}

// ---------------------------------------------------------------------------
// K3: out = g_att @ w_out + b_out; y = out + x(gathered); LayerNorm(y)
// Tile 64x256 (full row -> LN fused), BK=16, 256 threads, 8x8 per thread.
// Each warp owns 8 full rows -> LN reduction is a warp shuffle.
// ---------------------------------------------------------------------------
__global__ __launch_bounds__(256, 2)
void out_gemm_ln(const float* __restrict__ wout,
                 const float* __restrict__ bout,
                 const float* __restrict__ x,
                 const float* __restrict__ gamma,
                 const float* __restrict__ beta,
                 float* __restrict__ out)
{
    __shared__ float As[16][64];
    __shared__ float Bs[16][256];
    __shared__ int   arow[64];

    const int tid = threadIdx.x;
    const int m0  = blockIdx.x * 64;
    if (tid < 64) arow[tid] = xrow_offset(m0 + tid);

    const int ty = tid >> 5;   // 0..7  (== warp id)
    const int tx = tid & 31;   // 0..31

    float acc[8][8];
    #pragma unroll
    for (int i = 0; i < 8; i++)
        #pragma unroll
        for (int j = 0; j < 8; j++) acc[i][j] = 0.f;

    __syncthreads();

    for (int kt = 0; kt < 256; kt += 16) {
        {
            int f   = tid;                 // 256 float4 for A (64 rows x 4)
            int row = f >> 2;
            int kq  = (f & 3) << 2;
            float4 av = *(const float4*)(g_att + (size_t)(m0 + row) * 256 + kt + kq);
            As[kq + 0][row] = av.x;
            As[kq + 1][row] = av.y;
            As[kq + 2][row] = av.z;
            As[kq + 3][row] = av.w;
        }
        #pragma unroll
        for (int q = 0; q < 4; q++) {
            int f  = q * 256 + tid;        // 1024 float4 for B (16 rows x 64)
            int kr = f >> 6;
            int c4 = (f & 63) << 2;
            *(float4*)&Bs[kr][c4] = *(const float4*)(wout + (kt + kr) * 256 + c4);
        }
        __syncthreads();

        #pragma unroll
        for (int k = 0; k < 16; k++) {
            float a[8], b[8];
            *(float4*)(a)     = *(float4*)&As[k][ty * 8];
            *(float4*)(a + 4) = *(float4*)&As[k][ty * 8 + 4];
            *(float4*)(b)     = *(float4*)&Bs[k][tx * 8];
            *(float4*)(b + 4) = *(float4*)&Bs[k][tx * 8 + 4];
            #pragma unroll
            for (int i = 0; i < 8; i++)
                #pragma unroll
                for (int j = 0; j < 8; j++)
                    acc[i][j] += a[i] * b[j];
        }
        __syncthreads();
    }

    float g8[8], be8[8], bo8[8];
    #pragma unroll
    for (int j = 0; j < 8; j++) {
        int n = tx * 8 + j;
        g8[j]  = gamma[n];
        be8[j] = beta[n];
        bo8[j] = bout[n];
    }

    #pragma unroll
    for (int i = 0; i < 8; i++) {
        int m = m0 + ty * 8 + i;
        const float* xr = x + arow[ty * 8 + i];
        float4 r0 = *(const float4*)(xr + tx * 8);
        float4 r1 = *(const float4*)(xr + tx * 8 + 4);
        float y[8];
        y[0] = acc[i][0] + bo8[0] + r0.x;
        y[1] = acc[i][1] + bo8[1] + r0.y;
        y[2] = acc[i][2] + bo8[2] + r0.z;
        y[3] = acc[i][3] + bo8[3] + r0.w;
        y[4] = acc[i][4] + bo8[4] + r1.x;
        y[5] = acc[i][5] + bo8[5] + r1.y;
        y[6] = acc[i][6] + bo8[6] + r1.z;
        y[7] = acc[i][7] + bo8[7] + r1.w;

        float s1 = 0.f, s2 = 0.f;
        #pragma unroll
        for (int j = 0; j < 8; j++) { s1 += y[j]; s2 += y[j] * y[j]; }
        #pragma unroll
        for (int o = 16; o; o >>= 1) {
            s1 += __shfl_xor_sync(0xffffffffu, s1, o);
            s2 += __shfl_xor_sync(0xffffffffu, s2, o);
        }
        float mean = s1 * (1.0f / 256.0f);
        float var  = s2 * (1.0f / 256.0f) - mean * mean;
        float rstd = rsqrtf(var + 1e-5f);

        float4 o0 = make_float4((y[0] - mean) * rstd * g8[0] + be8[0],
                                (y[1] - mean) * rstd * g8[1] + be8[1],
                                (y[2] - mean) * rstd * g8[2] + be8[2],
                                (y[3] - mean) * rstd * g8[3] + be8[3]);
        float4 o1 = make_float4((y[4] - mean) * rstd * g8[4] + be8[4],
                                (y[5] - mean) * rstd * g8[5] + be8[5],
                                (y[6] - mean) * rstd * g8[6] + be8[6],
                                (y[7] - mean) * rstd * g8[7] + be8[7]);
        *(float4*)(out + (size_t)m * 256 + tx * 8)     = o0;
        *(float4*)(out + (size_t)m * 256 + tx * 8 + 4) = o1;
    }
}

// ---------------------------------------------------------------------------
extern "C" void kernel_launch(void* const* d_in, const int* in_sizes, int n_in,
                              void* d_out, int out_size)
{
    const float* x          = (const float*)d_in[0];
    const float* w_qkv      = (const float*)d_in[1];
    const float* b_qkv      = (const float*)d_in[2];
    const float* bias_table = (const float*)d_in[3];
    const float* w_out      = (const float*)d_in[4];
    const float* b_out      = (const float*)d_in[5];
    const float* ln_gamma   = (const float*)d_in[6];
    const float* ln_beta    = (const float*)d_in[7];
    float* out = (float*)d_out;

    qkv_gemm  <<<dim3(6, 1568), 256>>>(x, w_qkv, b_qkv);
    attn_kernel<<<dim3(NWIN, HEADS), 128>>>(bias_table);
    out_gemm_ln<<<dim3(MTOT / 64), 256>>>(w_out, b_out, x, ln_gamma, ln_beta, out);
}

// round 3
// speedup vs baseline: 1.7738x; 1.7738x over previous
#include <cuda_runtime.h>
#include <cstdint>

#define MTOT  200704
#define NWIN  4096
#define HEADS 8

// Scratch (device globals; no cudaMalloc allowed)
__device__ float g_qkv[154140672];      // [MTOT][768]
__device__ float g_att[ 51380224];      // [MTOT][256]
__device__ float g_wqkvT[768 * 256];    // w_qkv transposed to [N][K], tf32-rounded
__device__ float g_woutT[256 * 256];    // w_out  transposed to [N][K], tf32-rounded

// ===========================================================================
// Helpers
// ===========================================================================
__device__ __forceinline__ uint32_t rna_tf32(float x) {
    uint32_t r;
    asm("cvt.rna.tf32.f32 %0, %1;" : "=r"(r) : "f"(x));
    return r;
}

__device__ __forceinline__ void sts4_tf32(float* p, float4 v) {
    uint4 u = make_uint4(rna_tf32(v.x), rna_tf32(v.y), rna_tf32(v.z), rna_tf32(v.w));
    *(uint4*)p = u;
}

// m16n8k8 tf32 MMA (Ampere-class HMMA, valid at sm_103 base target)
__device__ __forceinline__ void mma8(float d[4],
                                     uint32_t a0, uint32_t a1, uint32_t a2, uint32_t a3,
                                     uint32_t b0, uint32_t b1) {
    asm volatile(
        "mma.sync.aligned.m16n8k8.row.col.f32.tf32.tf32.f32 "
        "{%0,%1,%2,%3}, {%4,%5,%6,%7}, {%8,%9}, {%0,%1,%2,%3};"
        : "+f"(d[0]), "+f"(d[1]), "+f"(d[2]), "+f"(d[3])
        : "r"(a0), "r"(a1), "r"(a2), "r"(a3), "r"(b0), "r"(b1));
}

// Map token row r (window-major) to element offset of its pixel row in x[4,224,224,256]
__device__ __forceinline__ int xrow_offset(int r) {
    int w   = r / 49;
    int t   = r - w * 49;
    int b   = w >> 10;
    int rem = w & 1023;
    int wh  = rem >> 5;
    int ww  = rem & 31;
    int i   = t / 7;
    int j   = t - i * 7;
    int row = (b * 224 + wh * 7 + i) * 224 + (ww * 7 + j);
    return row << 8;
}

// ===========================================================================
// W transpose + tf32 rounding:  w[K][N] -> wT[N][K]
// ===========================================================================
__global__ void prep_wT(const float* __restrict__ w, int K, int N, int which) {
    float* wT = which ? g_woutT : g_wqkvT;
    int idx = blockIdx.x * 256 + threadIdx.x;
    if (idx < K * N) {
        int k = idx / N;
        int n = idx - k * N;
        wT[(size_t)n * K + k] = __uint_as_float(rna_tf32(w[idx]));
    }
}

// ===========================================================================
// K1: qkv = gather(x) @ w_qkv + b_qkv   via mma.sync tf32
// CTA 128x128, BK=32, 8 warps (2m x 4n), warp tile 64x32.
// ===========================================================================
__global__ __launch_bounds__(256, 2)
void qkv_mma(const float* __restrict__ x, const float* __restrict__ bias)
{
    __shared__ float As[128][36];   // [m][k], stride 144B (16B aligned, conflict-free frags)
    __shared__ float Bs[128][36];   // [n][k]
    __shared__ int   arow[128];

    const int tid  = threadIdx.x;
    const int wid  = tid >> 5;
    const int lane = tid & 31;
    const int m0   = blockIdx.y * 128;
    const int n0   = blockIdx.x * 128;
    if (tid < 128) arow[tid] = xrow_offset(m0 + tid);

    const int wm = (wid >> 2) * 64;
    const int wn = (wid & 3) * 32;
    const int r0 = lane >> 2;
    const int kc = lane & 3;

    float acc[4][4][4];
    #pragma unroll
    for (int i = 0; i < 4; i++)
        #pragma unroll
        for (int j = 0; j < 4; j++)
            #pragma unroll
            for (int q = 0; q < 4; q++) acc[i][j][q] = 0.f;

    __syncthreads();

    for (int kt = 0; kt < 256; kt += 32) {
        #pragma unroll
        for (int i = 0; i < 4; i++) {
            int f   = tid + i * 256;
            int row = f >> 3;
            int c4  = (f & 7) << 2;
            float4 v = *(const float4*)(x + arow[row] + kt + c4);
            sts4_tf32(&As[row][c4], v);
            float4 b = *(const float4*)(g_wqkvT + (size_t)(n0 + row) * 256 + kt + c4);
            *(float4*)&Bs[row][c4] = b;
        }
        __syncthreads();

        #pragma unroll
        for (int k8 = 0; k8 < 32; k8 += 8) {
            uint32_t a[4][4], b[4][2];
            #pragma unroll
            for (int im = 0; im < 4; im++) {
                int r = wm + im * 16 + r0;
                a[im][0] = __float_as_uint(As[r    ][k8 + kc]);
                a[im][1] = __float_as_uint(As[r + 8][k8 + kc]);
                a[im][2] = __float_as_uint(As[r    ][k8 + kc + 4]);
                a[im][3] = __float_as_uint(As[r + 8][k8 + kc + 4]);
            }
            #pragma unroll
            for (int in_ = 0; in_ < 4; in_++) {
                int n = wn + in_ * 8 + r0;
                b[in_][0] = __float_as_uint(Bs[n][k8 + kc]);
                b[in_][1] = __float_as_uint(Bs[n][k8 + kc + 4]);
            }
            #pragma unroll
            for (int im = 0; im < 4; im++)
                #pragma unroll
                for (int in_ = 0; in_ < 4; in_++)
                    mma8(acc[im][in_], a[im][0], a[im][1], a[im][2], a[im][3],
                         b[in_][0], b[in_][1]);
        }
        __syncthreads();
    }

    #pragma unroll
    for (int im = 0; im < 4; im++) {
        int r = m0 + wm + im * 16 + r0;
        #pragma unroll
        for (int in_ = 0; in_ < 4; in_++) {
            int c = n0 + wn + in_ * 8 + kc * 2;
            float b0 = bias[c], b1 = bias[c + 1];
            float2 o0 = make_float2(acc[im][in_][0] + b0, acc[im][in_][1] + b1);
            float2 o1 = make_float2(acc[im][in_][2] + b0, acc[im][in_][3] + b1);
            *(float2*)(g_qkv + (size_t)r * 768 + c)       = o0;
            *(float2*)(g_qkv + (size_t)(r + 8) * 768 + c) = o1;
        }
    }
}

// ===========================================================================
// K2: per-(window, head) attention, register-blocked 4x4 tiles
// ===========================================================================
__global__ __launch_bounds__(128)
void attn2(const float* __restrict__ bias_table)
{
    __shared__ float qs[52][36];
    __shared__ float ks[52][36];
    __shared__ float vs[52][36];
    __shared__ float sm[52][56];
    __shared__ float bsh[169];

    const int tid = threadIdx.x;
    const int w   = blockIdx.x;
    const int h   = blockIdx.y;

    const float* qb = g_qkv + (size_t)w * 49 * 768 + h * 32;

    for (int idx = tid; idx < 52 * 8; idx += 128) {
        int t  = idx >> 3;
        int d4 = (idx & 7) << 2;
        float4 qv, kv, vv;
        if (t < 49) {
            const float* rp = qb + t * 768 + d4;
            qv = *(const float4*)(rp);
            kv = *(const float4*)(rp + 256);
            vv = *(const float4*)(rp + 512);
            qv.x *= 0.5f; qv.y *= 0.5f; qv.z *= 0.5f; qv.w *= 0.5f;
        } else {
            qv = kv = vv = make_float4(0.f, 0.f, 0.f, 0.f);
        }
        *(float4*)&qs[t][d4] = qv;
        *(float4*)&ks[t][d4] = kv;
        *(float4*)&vs[t][d4] = vv;
    }
    for (int idx = tid; idx < 169; idx += 128) bsh[idx] = bias_table[idx * 8 + h];
    for (int idx = tid; idx < 3 * 56; idx += 128) sm[49 + idx / 56][idx % 56] = 0.f;
    __syncthreads();

    for (int t = tid; t < 169; t += 128) {
        int ti = t / 13, tj = t - ti * 13;
        int qi0 = ti * 4, ki0 = tj * 4;
        float acc[4][4];
        #pragma unroll
        for (int i = 0; i < 4; i++)
            #pragma unroll
            for (int j = 0; j < 4; j++) acc[i][j] = 0.f;
        #pragma unroll
        for (int d = 0; d < 32; d += 4) {
            float4 qv[4], kv[4];
            #pragma unroll
            for (int i = 0; i < 4; i++) qv[i] = *(float4*)&qs[qi0 + i][d];
            #pragma unroll
            for (int j = 0; j < 4; j++) kv[j] = *(float4*)&ks[ki0 + j][d];
            #pragma unroll
            for (int i = 0; i < 4; i++)
                #pragma unroll
                for (int j = 0; j < 4; j++)
                    acc[i][j] += qv[i].x * kv[j].x + qv[i].y * kv[j].y
                               + qv[i].z * kv[j].z + qv[i].w * kv[j].w;
        }
        #pragma unroll
        for (int i = 0; i < 4; i++) {
            int qi = qi0 + i;
            if (qi >= 49) continue;
            int i1 = qi / 7, j1 = qi - i1 * 7;
            #pragma unroll
            for (int j = 0; j < 4; j++) {
                int ki = ki0 + j;
                if (ki < 49) {
                    int i2 = ki / 7, j2 = ki - i2 * 7;
                    sm[qi][ki] = acc[i][j] + bsh[(i1 - i2 + 6) * 13 + (j1 - j2 + 6)];
                } else {
                    sm[qi][ki] = -1e30f;
                }
            }
        }
    }
    __syncthreads();

    const int warp = tid >> 5;
    const int lane = tid & 31;
    for (int r = warp; r < 49; r += 4) {
        float v0 = sm[r][lane];
        float v1 = (lane + 32 < 52) ? sm[r][lane + 32] : -1e30f;
        float mx = fmaxf(v0, v1);
        #pragma unroll
        for (int o = 16; o; o >>= 1) mx = fmaxf(mx, __shfl_xor_sync(0xffffffffu, mx, o));
        float e0 = __expf(v0 - mx);
        float e1 = (lane + 32 < 52) ? __expf(v1 - mx) : 0.f;
        float s  = e0 + e1;
        #pragma unroll
        for (int o = 16; o; o >>= 1) s += __shfl_xor_sync(0xffffffffu, s, o);
        float inv = 1.0f / s;
        sm[r][lane] = e0 * inv;
        if (lane + 32 < 52) sm[r][lane + 32] = e1 * inv;
    }
    __syncthreads();

    for (int t = tid; t < 104; t += 128) {
        int ti = t >> 3, tdj = t & 7;
        int qi0 = ti * 4, d0 = tdj * 4;
        float acc[4][4];
        #pragma unroll
        for (int i = 0; i < 4; i++)
            #pragma unroll
            for (int j = 0; j < 4; j++) acc[i][j] = 0.f;
        for (int kb = 0; kb < 52; kb += 4) {
            float4 p[4];
            #pragma unroll
            for (int i = 0; i < 4; i++) p[i] = *(float4*)&sm[qi0 + i][kb];
            #pragma unroll
            for (int kk = 0; kk < 4; kk++) {
                float4 vr = *(float4*)&vs[kb + kk][d0];
                #pragma unroll
                for (int i = 0; i < 4; i++) {
                    float pv = (kk == 0) ? p[i].x : (kk == 1) ? p[i].y
                             : (kk == 2) ? p[i].z : p[i].w;
                    acc[i][0] += pv * vr.x;
                    acc[i][1] += pv * vr.y;
                    acc[i][2] += pv * vr.z;
                    acc[i][3] += pv * vr.w;
                }
            }
        }
        #pragma unroll
        for (int i = 0; i < 4; i++) {
            int qi = qi0 + i;
            if (qi >= 49) continue;
            float4 ov = make_float4(acc[i][0], acc[i][1], acc[i][2], acc[i][3]);
            *(float4*)(g_att + ((size_t)w * 49 + qi) * 256 + h * 32 + d0) = ov;
        }
    }
}

// ===========================================================================
// K3: out = LN(g_att @ w_out + b_out + gather(x))  via mma.sync tf32
// CTA 128x256 (full rows), BK=32, 8 warps (2m x 4n), warp tile 64x64.
// ===========================================================================
#define K3_SMEM 56832
__global__ __launch_bounds__(256, 1)
void out_mma(const float* __restrict__ x,
             const float* __restrict__ bout,
             const float* __restrict__ gamma,
             const float* __restrict__ beta,
             float* __restrict__ out)
{
    extern __shared__ char smem[];
    float (*As)[36] = (float (*)[36])(smem);                 // 128 x 36
    float (*Bs)[36] = (float (*)[36])(smem + 18432);         // 256 x 36
    int*   arow     = (int*)(smem + 55296);                  // 128
    float* s1       = (float*)(smem + 55808);                // 128
    float* s2       = (float*)(smem + 56320);                // 128

    const int tid  = threadIdx.x;
    const int wid  = tid >> 5;
    const int lane = tid & 31;
    const int m0   = blockIdx.x * 128;
    if (tid < 128) { arow[tid] = xrow_offset(m0 + tid); s1[tid] = 0.f; s2[tid] = 0.f; }

    const int wm = (wid >> 2) * 64;
    const int wn = (wid & 3) * 64;
    const int r0 = lane >> 2;
    const int kc = lane & 3;

    float acc[4][8][4];
    #pragma unroll
    for (int i = 0; i < 4; i++)
        #pragma unroll
        for (int j = 0; j < 8; j++)
            #pragma unroll
            for (int q = 0; q < 4; q++) acc[i][j][q] = 0.f;

    __syncthreads();

    for (int kt = 0; kt < 256; kt += 32) {
        #pragma unroll
        for (int i = 0; i < 4; i++) {
            int f   = tid + i * 256;
            int row = f >> 3;
            int c4  = (f & 7) << 2;
            float4 v = *(const float4*)(g_att + (size_t)(m0 + row) * 256 + kt + c4);
            sts4_tf32(&As[row][c4], v);
        }
        #pragma unroll
        for (int i = 0; i < 8; i++) {
            int f   = tid + i * 256;
            int row = f >> 3;
            int c4  = (f & 7) << 2;
            float4 b = *(const float4*)(g_woutT + (size_t)row * 256 + kt + c4);
            *(float4*)&Bs[row][c4] = b;
        }
        __syncthreads();

        #pragma unroll
        for (int k8 = 0; k8 < 32; k8 += 8) {
            uint32_t a[4][4], b[8][2];
            #pragma unroll
            for (int im = 0; im < 4; im++) {
                int r = wm + im * 16 + r0;
                a[im][0] = __float_as_uint(As[r    ][k8 + kc]);
                a[im][1] = __float_as_uint(As[r + 8][k8 + kc]);
                a[im][2] = __float_as_uint(As[r    ][k8 + kc + 4]);
                a[im][3] = __float_as_uint(As[r + 8][k8 + kc + 4]);
            }
            #pragma unroll
            for (int in_ = 0; in_ < 8; in_++) {
                int n = wn + in_ * 8 + r0;
                b[in_][0] = __float_as_uint(Bs[n][k8 + kc]);
                b[in_][1] = __float_as_uint(Bs[n][k8 + kc + 4]);
            }
            #pragma unroll
            for (int im = 0; im < 4; im++)
                #pragma unroll
                for (int in_ = 0; in_ < 8; in_++)
                    mma8(acc[im][in_], a[im][0], a[im][1], a[im][2], a[im][3],
                         b[in_][0], b[in_][1]);
        }
        __syncthreads();
    }

    // ---- epilogue: y = acc + bias + residual; LN over full 256-col rows ----
    #pragma unroll
    for (int im = 0; im < 4; im++) {
        #pragma unroll
        for (int half = 0; half < 2; half++) {
            int rl = wm + im * 16 + r0 + half * 8;
            const float* xr = x + arow[rl];
            float p1 = 0.f, p2 = 0.f;
            #pragma unroll
            for (int in_ = 0; in_ < 8; in_++) {
                int c = wn + in_ * 8 + kc * 2;
                float2 xv = *(const float2*)(xr + c);
                float y0 = acc[im][in_][half * 2 + 0] + bout[c]     + xv.x;
                float y1 = acc[im][in_][half * 2 + 1] + bout[c + 1] + xv.y;
                acc[im][in_][half * 2 + 0] = y0;
                acc[im][in_][half * 2 + 1] = y1;
                p1 += y0 + y1;
                p2 += y0 * y0 + y1 * y1;
            }
            p1 += __shfl_xor_sync(0xffffffffu, p1, 1);
            p2 += __shfl_xor_sync(0xffffffffu, p2, 1);
            p1 += __shfl_xor_sync(0xffffffffu, p1, 2);
            p2 += __shfl_xor_sync(0xffffffffu, p2, 2);
            if (kc == 0) {
                atomicAdd(&s1[rl], p1);
                atomicAdd(&s2[rl], p2);
            }
        }
    }
    __syncthreads();

    #pragma unroll
    for (int im = 0; im < 4; im++) {
        #pragma unroll
        for (int half = 0; half < 2; half++) {
            int rl = wm + im * 16 + r0 + half * 8;
            int m  = m0 + rl;
            float mean = s1[rl] * (1.0f / 256.0f);
            float var  = s2[rl] * (1.0f / 256.0f) - mean * mean;
            float rstd = rsqrtf(var + 1e-5f);
            #pragma unroll
            for (int in_ = 0; in_ < 8; in_++) {
                int c = wn + in_ * 8 + kc * 2;
                float y0 = acc[im][in_][half * 2 + 0];
                float y1 = acc[im][in_][half * 2 + 1];
                float2 o = make_float2((y0 - mean) * rstd * gamma[c]     + beta[c],
                                       (y1 - mean) * rstd * gamma[c + 1] + beta[c + 1]);
                *(float2*)(out + (size_t)m * 256 + c) = o;
            }
        }
    }
}

// ===========================================================================
extern "C" void kernel_launch(void* const* d_in, const int* in_sizes, int n_in,
                              void* d_out, int out_size)
{
    const float* x          = (const float*)d_in[0];
    const float* w_qkv      = (const float*)d_in[1];
    const float* b_qkv      = (const float*)d_in[2];
    const float* bias_table = (const float*)d_in[3];
    const float* w_out      = (const float*)d_in[4];
    const float* b_out      = (const float*)d_in[5];
    const float* ln_gamma   = (const float*)d_in[6];
    const float* ln_beta    = (const float*)d_in[7];
    float* out = (float*)d_out;

    cudaFuncSetAttribute(out_mma, cudaFuncAttributeMaxDynamicSharedMemorySize, K3_SMEM);

    prep_wT<<<(256 * 768 + 255) / 256, 256>>>(w_qkv, 256, 768, 0);
    prep_wT<<<(256 * 256 + 255) / 256, 256>>>(w_out, 256, 256, 1);
    qkv_mma<<<dim3(6, 1568), 256>>>(x, b_qkv);
    attn2<<<dim3(NWIN, HEADS), 128>>>(bias_table);
    out_mma<<<1568, 256, K3_SMEM>>>(x, b_out, ln_gamma, ln_beta, out);
}

// round 4
// speedup vs baseline: 3.1797x; 1.7926x over previous
#include <cuda_runtime.h>
#include <cstdint>

#define MTOT  200704
#define NWIN  4096
#define HEADS 8

// Scratch (device globals; no cudaMalloc allowed)
__device__ float g_qkv[154140672];      // [MTOT][768]
__device__ float g_att[ 51380224];      // [MTOT][256]
__device__ float g_wqkvT[768 * 256];    // w_qkv transposed to [N][K], tf32-rounded
__device__ float g_woutT[256 * 256];    // w_out  transposed to [N][K], tf32-rounded

// ===========================================================================
// Helpers
// ===========================================================================
__device__ __forceinline__ uint32_t smem_u32(const void* p) {
    uint32_t a;
    asm("{ .reg .u64 t; cvta.to.shared.u64 t, %1; cvt.u32.u64 %0, t; }"
        : "=r"(a) : "l"(p));
    return a;
}

__device__ __forceinline__ uint32_t rna_tf32(float x) {
    uint32_t r;
    asm("cvt.rna.tf32.f32 %0, %1;" : "=r"(r) : "f"(x));
    return r;
}

__device__ __forceinline__ void sts4_tf32(float* p, float4 v) {
    uint4 u = make_uint4(rna_tf32(v.x), rna_tf32(v.y), rna_tf32(v.z), rna_tf32(v.w));
    *(uint4*)p = u;
}

// m16n8k8 tf32 MMA
__device__ __forceinline__ void mma8(float d[4],
                                     uint32_t a0, uint32_t a1, uint32_t a2, uint32_t a3,
                                     uint32_t b0, uint32_t b1) {
    asm volatile(
        "mma.sync.aligned.m16n8k8.row.col.f32.tf32.tf32.f32 "
        "{%0,%1,%2,%3}, {%4,%5,%6,%7}, {%8,%9}, {%0,%1,%2,%3};"
        : "+f"(d[0]), "+f"(d[1]), "+f"(d[2]), "+f"(d[3])
        : "r"(a0), "r"(a1), "r"(a2), "r"(a3), "r"(b0), "r"(b1));
}

#define CP16(dst_u32, src_ptr) \
    asm volatile("cp.async.ca.shared.global [%0], [%1], 16;" \
                 :: "r"(dst_u32), "l"(src_ptr))
#define CP_COMMIT() asm volatile("cp.async.commit_group;")
#define CP_WAIT(n)  asm volatile("cp.async.wait_group %0;" :: "n"(n))

// Map token row r (window-major) to element offset of its pixel row in x[4,224,224,256]
__device__ __forceinline__ int xrow_offset(int r) {
    int w   = r / 49;
    int t   = r - w * 49;
    int b   = w >> 10;
    int rem = w & 1023;
    int wh  = rem >> 5;
    int ww  = rem & 31;
    int i   = t / 7;
    int j   = t - i * 7;
    int row = (b * 224 + wh * 7 + i) * 224 + (ww * 7 + j);
    return row << 8;
}

// ===========================================================================
// W transpose + tf32 rounding:  w[K][N] -> wT[N][K]
// ===========================================================================
__global__ void prep_wT(const float* __restrict__ w, int K, int N, int which) {
    float* wT = which ? g_woutT : g_wqkvT;
    int idx = blockIdx.x * 256 + threadIdx.x;
    if (idx < K * N) {
        int k = idx / N;
        int n = idx - k * N;
        wT[(size_t)n * K + k] = __uint_as_float(rna_tf32(w[idx]));
    }
}

// ===========================================================================
// K1: qkv = gather(x) @ w_qkv + b_qkv   via mma.sync tf32, cp.async double-buffer
// CTA 128x128, BK=32, 8 warps (2m x 4n), warp tile 64x32.
// Dynamic smem: As[2][128][36] @ buf*36864, Bs[2] @ +18432, arow @ 73728.
// ===========================================================================
#define K1_SMEM 74240
__global__ __launch_bounds__(256, 2)
void qkv_mma(const float* __restrict__ x, const float* __restrict__ bias)
{
    extern __shared__ char smem[];
    const uint32_t sbase = smem_u32(smem);
    int* arow = (int*)(smem + 73728);

    const int tid  = threadIdx.x;
    const int wid  = tid >> 5;
    const int lane = tid & 31;
    const int m0   = blockIdx.y * 128;
    const int n0   = blockIdx.x * 128;
    if (tid < 128) arow[tid] = xrow_offset(m0 + tid);

    const int wm = (wid >> 2) * 64;
    const int wn = (wid & 3) * 32;
    const int r0 = lane >> 2;
    const int kc = lane & 3;

    float acc[4][4][4];
    #pragma unroll
    for (int i = 0; i < 4; i++)
        #pragma unroll
        for (int j = 0; j < 4; j++)
            #pragma unroll
            for (int q = 0; q < 4; q++) acc[i][j][q] = 0.f;

    // row/col decomposition for this thread's 4 load slots
    int lrow[4], lc4[4];
    #pragma unroll
    for (int i = 0; i < 4; i++) {
        int f = tid + i * 256;
        lrow[i] = f >> 3;
        lc4[i]  = (f & 7) << 2;
    }

    __syncthreads();   // arow visible

    // prologue: load buffer 0, kt=0
    #pragma unroll
    for (int i = 0; i < 4; i++) {
        uint32_t so = (uint32_t)(lrow[i] * 36 + lc4[i]) * 4;
        CP16(sbase + so,          x + arow[lrow[i]] + lc4[i]);
        CP16(sbase + 18432 + so,  g_wqkvT + (size_t)(n0 + lrow[i]) * 256 + lc4[i]);
    }
    CP_COMMIT();

    #pragma unroll
    for (int it = 0; it < 8; it++) {
        if (it < 7) {
            uint32_t bo = (uint32_t)(((it + 1) & 1) * 36864);
            int kt = (it + 1) * 32;
            #pragma unroll
            for (int i = 0; i < 4; i++) {
                uint32_t so = bo + (uint32_t)(lrow[i] * 36 + lc4[i]) * 4;
                CP16(sbase + so,         x + arow[lrow[i]] + kt + lc4[i]);
                CP16(sbase + 18432 + so, g_wqkvT + (size_t)(n0 + lrow[i]) * 256 + kt + lc4[i]);
            }
            CP_COMMIT();
            CP_WAIT(1);
        } else {
            CP_WAIT(0);
        }
        __syncthreads();

        float (*As)[36] = (float (*)[36])(smem + (it & 1) * 36864);
        float (*Bs)[36] = (float (*)[36])(smem + (it & 1) * 36864 + 18432);

        #pragma unroll
        for (int k8 = 0; k8 < 32; k8 += 8) {
            uint32_t a[4][4], b[4][2];
            #pragma unroll
            for (int im = 0; im < 4; im++) {
                int r = wm + im * 16 + r0;
                a[im][0] = __float_as_uint(As[r    ][k8 + kc]);
                a[im][1] = __float_as_uint(As[r + 8][k8 + kc]);
                a[im][2] = __float_as_uint(As[r    ][k8 + kc + 4]);
                a[im][3] = __float_as_uint(As[r + 8][k8 + kc + 4]);
            }
            #pragma unroll
            for (int in_ = 0; in_ < 4; in_++) {
                int n = wn + in_ * 8 + r0;
                b[in_][0] = __float_as_uint(Bs[n][k8 + kc]);
                b[in_][1] = __float_as_uint(Bs[n][k8 + kc + 4]);
            }
            #pragma unroll
            for (int im = 0; im < 4; im++)
                #pragma unroll
                for (int in_ = 0; in_ < 4; in_++)
                    mma8(acc[im][in_], a[im][0], a[im][1], a[im][2], a[im][3],
                         b[in_][0], b[in_][1]);
        }
        __syncthreads();
    }

    #pragma unroll
    for (int im = 0; im < 4; im++) {
        int r = m0 + wm + im * 16 + r0;
        #pragma unroll
        for (int in_ = 0; in_ < 4; in_++) {
            int c = n0 + wn + in_ * 8 + kc * 2;
            float b0 = bias[c], b1 = bias[c + 1];
            float2 o0 = make_float2(acc[im][in_][0] + b0, acc[im][in_][1] + b1);
            float2 o1 = make_float2(acc[im][in_][2] + b0, acc[im][in_][3] + b1);
            *(float2*)(g_qkv + (size_t)r * 768 + c)       = o0;
            *(float2*)(g_qkv + (size_t)(r + 8) * 768 + c) = o1;
        }
    }
}

// ===========================================================================
// K2: attention via mma.sync tf32.
// Block = (window, head), 128 threads, 4 warps. Warp wi owns S rows
// [wi*16, wi*16+16) of the padded 64x56 score matrix. Softmax in registers;
// P (C-layout) -> A-fragment via shuffles; O = P @ V with V staged transposed.
// ===========================================================================
__global__ __launch_bounds__(128)
void attn3(const float* __restrict__ bias_table)
{
    __shared__ float qs[64][36];   // q, pre-scaled 0.5, tf32; rows 49..63 zero
    __shared__ float ks[56][36];   // k, tf32; rows 49..55 zero
    __shared__ float vt[32][60];   // v transposed [d][t], tf32; t 49..55 zero
    __shared__ float bsh[169];

    const int tid  = threadIdx.x;
    const int w    = blockIdx.x;
    const int h    = blockIdx.y;
    const int wi   = tid >> 5;
    const int lane = tid & 31;
    const int r0   = lane >> 2;
    const int kc   = lane & 3;

    // zero pad regions
    for (int i = tid; i < 15 * 36; i += 128) qs[49 + i / 36][i % 36] = 0.f;
    for (int i = tid; i < 7 * 36; i += 128)  ks[49 + i / 36][i % 36] = 0.f;
    for (int i = tid; i < 32 * 60; i += 128) ((float*)vt)[i] = 0.f;
    __syncthreads();

    const float* qb = g_qkv + (size_t)w * 49 * 768 + h * 32;
    for (int idx = tid; idx < 49 * 8; idx += 128) {
        int t  = idx >> 3;
        int d4 = (idx & 7) << 2;
        const float* rp = qb + t * 768 + d4;
        float4 qv = *(const float4*)(rp);
        float4 kv = *(const float4*)(rp + 256);
        float4 vv = *(const float4*)(rp + 512);
        qv.x *= 0.5f; qv.y *= 0.5f; qv.z *= 0.5f; qv.w *= 0.5f;
        sts4_tf32(&qs[t][d4], qv);
        sts4_tf32(&ks[t][d4], kv);
        vt[d4 + 0][t] = __uint_as_float(rna_tf32(vv.x));
        vt[d4 + 1][t] = __uint_as_float(rna_tf32(vv.y));
        vt[d4 + 2][t] = __uint_as_float(rna_tf32(vv.z));
        vt[d4 + 3][t] = __uint_as_float(rna_tf32(vv.w));
    }
    for (int i = tid; i < 169; i += 128) bsh[i] = bias_table[i * 8 + h];
    __syncthreads();

    // ---- S = Q @ K^T  (warp tile 16x56) ----
    float c[7][4];
    #pragma unroll
    for (int nt = 0; nt < 7; nt++)
        #pragma unroll
        for (int q = 0; q < 4; q++) c[nt][q] = 0.f;

    #pragma unroll
    for (int k8 = 0; k8 < 32; k8 += 8) {
        int r = wi * 16 + r0;
        uint32_t a0 = __float_as_uint(qs[r    ][k8 + kc]);
        uint32_t a1 = __float_as_uint(qs[r + 8][k8 + kc]);
        uint32_t a2 = __float_as_uint(qs[r    ][k8 + kc + 4]);
        uint32_t a3 = __float_as_uint(qs[r + 8][k8 + kc + 4]);
        #pragma unroll
        for (int nt = 0; nt < 7; nt++) {
            uint32_t b0 = __float_as_uint(ks[nt * 8 + r0][k8 + kc]);
            uint32_t b1 = __float_as_uint(ks[nt * 8 + r0][k8 + kc + 4]);
            mma8(c[nt], a0, a1, a2, a3, b0, b1);
        }
    }

    // ---- bias + mask, softmax per row (in registers), P -> tf32 ----
    #pragma unroll
    for (int half = 0; half < 2; half++) {
        int q_ = wi * 16 + r0 + half * 8;
        bool qok = q_ < 49;
        int i1 = q_ / 7, j1 = q_ - i1 * 7;
        #pragma unroll
        for (int nt = 0; nt < 7; nt++) {
            #pragma unroll
            for (int e = 0; e < 2; e++) {
                int col = nt * 8 + 2 * kc + e;
                float& v = c[nt][half * 2 + e];
                if (col < 49) {
                    if (qok) {
                        int i2 = col / 7, j2 = col - i2 * 7;
                        v += bsh[(i1 - i2 + 6) * 13 + (j1 - j2 + 6)];
                    }
                } else {
                    v = -1e30f;
                }
            }
        }
        float mx = -1e30f;
        #pragma unroll
        for (int nt = 0; nt < 7; nt++) {
            mx = fmaxf(mx, c[nt][half * 2]);
            mx = fmaxf(mx, c[nt][half * 2 + 1]);
        }
        mx = fmaxf(mx, __shfl_xor_sync(0xffffffffu, mx, 1));
        mx = fmaxf(mx, __shfl_xor_sync(0xffffffffu, mx, 2));
        float s = 0.f;
        #pragma unroll
        for (int nt = 0; nt < 7; nt++) {
            #pragma unroll
            for (int e = 0; e < 2; e++) {
                float p = __expf(c[nt][half * 2 + e] - mx);
                c[nt][half * 2 + e] = p;
                s += p;
            }
        }
        s += __shfl_xor_sync(0xffffffffu, s, 1);
        s += __shfl_xor_sync(0xffffffffu, s, 2);
        float inv = 1.0f / s;
        #pragma unroll
        for (int nt = 0; nt < 7; nt++) {
            #pragma unroll
            for (int e = 0; e < 2; e++)
                c[nt][half * 2 + e] =
                    __uint_as_float(rna_tf32(c[nt][half * 2 + e] * inv));
        }
    }

    // ---- O = P @ V  (warp tile 16x32), A-frag built from C-frag via shfl ----
    float o[4][4];
    #pragma unroll
    for (int jn = 0; jn < 4; jn++)
        #pragma unroll
        for (int q = 0; q < 4; q++) o[jn][q] = 0.f;

    const int s0 = (lane & ~3) | (kc >> 1);
    const int s1 = s0 + 2;
    const bool odd = kc & 1;

    #pragma unroll
    for (int kk = 0; kk < 7; kk++) {
        float e00 = __shfl_sync(0xffffffffu, c[kk][0], s0);
        float e01 = __shfl_sync(0xffffffffu, c[kk][1], s0);
        float e10 = __shfl_sync(0xffffffffu, c[kk][2], s0);
        float e11 = __shfl_sync(0xffffffffu, c[kk][3], s0);
        float f00 = __shfl_sync(0xffffffffu, c[kk][0], s1);
        float f01 = __shfl_sync(0xffffffffu, c[kk][1], s1);
        float f10 = __shfl_sync(0xffffffffu, c[kk][2], s1);
        float f11 = __shfl_sync(0xffffffffu, c[kk][3], s1);
        uint32_t a0 = __float_as_uint(odd ? e01 : e00);   // P[r0][kc]
        uint32_t a1 = __float_as_uint(odd ? e11 : e10);   // P[r0+8][kc]
        uint32_t a2 = __float_as_uint(odd ? f01 : f00);   // P[r0][kc+4]
        uint32_t a3 = __float_as_uint(odd ? f11 : f10);   // P[r0+8][kc+4]
        #pragma unroll
        for (int jn = 0; jn < 4; jn++) {
            uint32_t b0 = __float_as_uint(vt[jn * 8 + r0][kk * 8 + kc]);
            uint32_t b1 = __float_as_uint(vt[jn * 8 + r0][kk * 8 + kc + 4]);
            mma8(o[jn], a0, a1, a2, a3, b0, b1);
        }
    }

    // ---- store O rows < 49 ----
    #pragma unroll
    for (int half = 0; half < 2; half++) {
        int q_ = wi * 16 + r0 + half * 8;
        if (q_ < 49) {
            float* op = g_att + ((size_t)w * 49 + q_) * 256 + h * 32;
            #pragma unroll
            for (int jn = 0; jn < 4; jn++) {
                float2 val = make_float2(o[jn][half * 2 + 0], o[jn][half * 2 + 1]);
                *(float2*)(op + jn * 8 + 2 * kc) = val;
            }
        }
    }
}

// ===========================================================================
// K3: out = LN(g_att @ w_out + b_out + gather(x))  via mma.sync tf32
// CTA 128x256 (full rows), BK=32, 8 warps (2m x 4n), warp tile 64x64.
// ===========================================================================
#define K3_SMEM 56832
__global__ __launch_bounds__(256, 1)
void out_mma(const float* __restrict__ x,
             const float* __restrict__ bout,
             const float* __restrict__ gamma,
             const float* __restrict__ beta,
             float* __restrict__ out)
{
    extern __shared__ char smem[];
    float (*As)[36] = (float (*)[36])(smem);                 // 128 x 36
    float (*Bs)[36] = (float (*)[36])(smem + 18432);         // 256 x 36
    int*   arow     = (int*)(smem + 55296);                  // 128
    float* s1       = (float*)(smem + 55808);                // 128
    float* s2       = (float*)(smem + 56320);                // 128

    const int tid  = threadIdx.x;
    const int wid  = tid >> 5;
    const int lane = tid & 31;
    const int m0   = blockIdx.x * 128;
    if (tid < 128) { arow[tid] = xrow_offset(m0 + tid); s1[tid] = 0.f; s2[tid] = 0.f; }

    const int wm = (wid >> 2) * 64;
    const int wn = (wid & 3) * 64;
    const int r0 = lane >> 2;
    const int kc = lane & 3;

    float acc[4][8][4];
    #pragma unroll
    for (int i = 0; i < 4; i++)
        #pragma unroll
        for (int j = 0; j < 8; j++)
            #pragma unroll
            for (int q = 0; q < 4; q++) acc[i][j][q] = 0.f;

    __syncthreads();

    for (int kt = 0; kt < 256; kt += 32) {
        #pragma unroll
        for (int i = 0; i < 4; i++) {
            int f   = tid + i * 256;
            int row = f >> 3;
            int c4  = (f & 7) << 2;
            float4 v = *(const float4*)(g_att + (size_t)(m0 + row) * 256 + kt + c4);
            sts4_tf32(&As[row][c4], v);
        }
        #pragma unroll
        for (int i = 0; i < 8; i++) {
            int f   = tid + i * 256;
            int row = f >> 3;
            int c4  = (f & 7) << 2;
            float4 b = *(const float4*)(g_woutT + (size_t)row * 256 + kt + c4);
            *(float4*)&Bs[row][c4] = b;
        }
        __syncthreads();

        #pragma unroll
        for (int k8 = 0; k8 < 32; k8 += 8) {
            uint32_t a[4][4], b[8][2];
            #pragma unroll
            for (int im = 0; im < 4; im++) {
                int r = wm + im * 16 + r0;
                a[im][0] = __float_as_uint(As[r    ][k8 + kc]);
                a[im][1] = __float_as_uint(As[r + 8][k8 + kc]);
                a[im][2] = __float_as_uint(As[r    ][k8 + kc + 4]);
                a[im][3] = __float_as_uint(As[r + 8][k8 + kc + 4]);
            }
            #pragma unroll
            for (int in_ = 0; in_ < 8; in_++) {
                int n = wn + in_ * 8 + r0;
                b[in_][0] = __float_as_uint(Bs[n][k8 + kc]);
                b[in_][1] = __float_as_uint(Bs[n][k8 + kc + 4]);
            }
            #pragma unroll
            for (int im = 0; im < 4; im++)
                #pragma unroll
                for (int in_ = 0; in_ < 8; in_++)
                    mma8(acc[im][in_], a[im][0], a[im][1], a[im][2], a[im][3],
                         b[in_][0], b[in_][1]);
        }
        __syncthreads();
    }

    // ---- epilogue: y = acc + bias + residual; LN over full 256-col rows ----
    #pragma unroll
    for (int im = 0; im < 4; im++) {
        #pragma unroll
        for (int half = 0; half < 2; half++) {
            int rl = wm + im * 16 + r0 + half * 8;
            const float* xr = x + arow[rl];
            float p1 = 0.f, p2 = 0.f;
            #pragma unroll
            for (int in_ = 0; in_ < 8; in_++) {
                int c = wn + in_ * 8 + kc * 2;
                float2 xv = *(const float2*)(xr + c);
                float y0 = acc[im][in_][half * 2 + 0] + bout[c]     + xv.x;
                float y1 = acc[im][in_][half * 2 + 1] + bout[c + 1] + xv.y;
                acc[im][in_][half * 2 + 0] = y0;
                acc[im][in_][half * 2 + 1] = y1;
                p1 += y0 + y1;
                p2 += y0 * y0 + y1 * y1;
            }
            p1 += __shfl_xor_sync(0xffffffffu, p1, 1);
            p2 += __shfl_xor_sync(0xffffffffu, p2, 1);
            p1 += __shfl_xor_sync(0xffffffffu, p1, 2);
            p2 += __shfl_xor_sync(0xffffffffu, p2, 2);
            if (kc == 0) {
                atomicAdd(&s1[rl], p1);
                atomicAdd(&s2[rl], p2);
            }
        }
    }
    __syncthreads();

    #pragma unroll
    for (int im = 0; im < 4; im++) {
        #pragma unroll
        for (int half = 0; half < 2; half++) {
            int rl = wm + im * 16 + r0 + half * 8;
            int m  = m0 + rl;
            float mean = s1[rl] * (1.0f / 256.0f);
            float var  = s2[rl] * (1.0f / 256.0f) - mean * mean;
            float rstd = rsqrtf(var + 1e-5f);
            #pragma unroll
            for (int in_ = 0; in_ < 8; in_++) {
                int c = wn + in_ * 8 + kc * 2;
                float y0 = acc[im][in_][half * 2 + 0];
                float y1 = acc[im][in_][half * 2 + 1];
                float2 o = make_float2((y0 - mean) * rstd * gamma[c]     + beta[c],
                                       (y1 - mean) * rstd * gamma[c + 1] + beta[c + 1]);
                *(float2*)(out + (size_t)m * 256 + c) = o;
            }
        }
    }
}

// ===========================================================================
extern "C" void kernel_launch(void* const* d_in, const int* in_sizes, int n_in,
                              void* d_out, int out_size)
{
    const float* x          = (const float*)d_in[0];
    const float* w_qkv      = (const float*)d_in[1];
    const float* b_qkv      = (const float*)d_in[2];
    const float* bias_table = (const float*)d_in[3];
    const float* w_out      = (const float*)d_in[4];
    const float* b_out      = (const float*)d_in[5];
    const float* ln_gamma   = (const float*)d_in[6];
    const float* ln_beta    = (const float*)d_in[7];
    float* out = (float*)d_out;

    cudaFuncSetAttribute(qkv_mma, cudaFuncAttributeMaxDynamicSharedMemorySize, K1_SMEM);
    cudaFuncSetAttribute(out_mma, cudaFuncAttributeMaxDynamicSharedMemorySize, K3_SMEM);

    prep_wT<<<(256 * 768 + 255) / 256, 256>>>(w_qkv, 256, 768, 0);
    prep_wT<<<(256 * 256 + 255) / 256, 256>>>(w_out, 256, 256, 1);
    qkv_mma<<<dim3(6, 1568), 256, K1_SMEM>>>(x, b_qkv);
    attn3<<<dim3(NWIN, HEADS), 128>>>(bias_table);
    out_mma<<<1568, 256, K3_SMEM>>>(x, b_out, ln_gamma, ln_beta, out);
}

// round 5
// speedup vs baseline: 4.2718x; 1.3435x over previous
#include <cuda_runtime.h>
#include <cuda_fp16.h>
#include <cstdint>

#define MTOT  200704
#define NWIN  4096
#define HEADS 8

// Scratch (device globals; no cudaMalloc allowed)
__device__ __half g_xh   [51380224];    // x converted to fp16
__device__ __half g_qkvh [154140672];   // [MTOT][768] fp16
__device__ __half g_atth [51380224];    // [MTOT][256] fp16
__device__ __half g_wqkvTh[768 * 256];  // w_qkv^T [N][K] fp16
__device__ __half g_woutTh[256 * 256];  // w_out^T [N][K] fp16
__device__ float  g_biasmat[8 * 64 * 64]; // per-head bias matrix, masked

// ===========================================================================
// Helpers
// ===========================================================================
__device__ __forceinline__ uint32_t smem_u32(const void* p) {
    uint32_t a;
    asm("{ .reg .u64 t; cvta.to.shared.u64 t, %1; cvt.u32.u64 %0, t; }"
        : "=r"(a) : "l"(p));
    return a;
}

__device__ __forceinline__ uint32_t pack_half2(float a, float b) {
    __half2 h = __floats2half2_rn(a, b);
    return *(uint32_t*)&h;
}

// m16n8k16 fp16 MMA, fp32 accumulate
__device__ __forceinline__ void mma16(float d[4],
                                      uint32_t a0, uint32_t a1, uint32_t a2, uint32_t a3,
                                      uint32_t b0, uint32_t b1) {
    asm volatile(
        "mma.sync.aligned.m16n8k16.row.col.f32.f16.f16.f32 "
        "{%0,%1,%2,%3}, {%4,%5,%6,%7}, {%8,%9}, {%0,%1,%2,%3};"
        : "+f"(d[0]), "+f"(d[1]), "+f"(d[2]), "+f"(d[3])
        : "r"(a0), "r"(a1), "r"(a2), "r"(a3), "r"(b0), "r"(b1));
}

#define CP16(dst_u32, src_ptr) \
    asm volatile("cp.async.ca.shared.global [%0], [%1], 16;" \
                 :: "r"(dst_u32), "l"(src_ptr))
#define CP_COMMIT() asm volatile("cp.async.commit_group;")
#define CP_WAIT(n)  asm volatile("cp.async.wait_group %0;" :: "n"(n))

// Map token row r (window-major) to element offset of its pixel row in x[4,224,224,256]
__device__ __forceinline__ int xrow_offset(int r) {
    int w   = r / 49;
    int t   = r - w * 49;
    int b   = w >> 10;
    int rem = w & 1023;
    int wh  = rem >> 5;
    int ww  = rem & 31;
    int i   = t / 7;
    int j   = t - i * 7;
    int row = (b * 224 + wh * 7 + i) * 224 + (ww * 7 + j);
    return row << 8;
}

// ===========================================================================
// Prep kernels
// ===========================================================================
__global__ void prep_xh(const float4* __restrict__ x4) {
    int idx = blockIdx.x * 256 + threadIdx.x;   // 12845056 total
    float4 v = x4[idx];
    uint2 o = make_uint2(pack_half2(v.x, v.y), pack_half2(v.z, v.w));
    ((uint2*)g_xh)[idx] = o;
}

__global__ void prep_wh(const float* __restrict__ w, int K, int N, int which) {
    __half* wT = which ? g_woutTh : g_wqkvTh;
    int idx = blockIdx.x * 256 + threadIdx.x;
    if (idx < K * N) {
        int k = idx / N;
        int n = idx - k * N;
        wT[(size_t)n * K + k] = __float2half_rn(w[idx]);
    }
}

__global__ void prep_bias(const float* __restrict__ bt) {
    int idx = blockIdx.x * 256 + threadIdx.x;   // 8*64*64 = 32768
    int h = idx >> 12;
    int r = (idx >> 6) & 63;
    int c = idx & 63;
    float v;
    if (c >= 49)      v = -1e30f;
    else if (r >= 49) v = 0.f;
    else {
        int i1 = r / 7, j1 = r - i1 * 7;
        int i2 = c / 7, j2 = c - i2 * 7;
        v = bt[((i1 - i2 + 6) * 13 + (j1 - j2 + 6)) * 8 + h];
    }
    g_biasmat[idx] = v;
}

// ===========================================================================
// K1: qkv = gather(x) @ w_qkv + b_qkv   fp16 mma, cp.async double-buffer
// CTA 128x128, BK=32, 8 warps (2m x 4n), warp tile 64x32.
// smem (bytes): buf0 A[128][40]h @0, B[128][40]h @10240; buf1 @20480; arow @40960
// ===========================================================================
#define K1_SMEM 41472
__global__ __launch_bounds__(256, 2)
void qkv_mma(const float* dummy, const float* __restrict__ bias)
{
    extern __shared__ char smem[];
    const uint32_t sbase = smem_u32(smem);
    int* arow = (int*)(smem + 40960);

    const int tid  = threadIdx.x;
    const int wid  = tid >> 5;
    const int lane = tid & 31;
    const int m0   = blockIdx.y * 128;
    const int n0   = blockIdx.x * 128;
    if (tid < 128) arow[tid] = xrow_offset(m0 + tid);

    const int wm = (wid >> 2) * 64;
    const int wn = (wid & 3) * 32;
    const int r0 = lane >> 2;
    const int kc = lane & 3;

    float acc[4][4][4];
    #pragma unroll
    for (int i = 0; i < 4; i++)
        #pragma unroll
        for (int j = 0; j < 4; j++)
            #pragma unroll
            for (int q = 0; q < 4; q++) acc[i][j][q] = 0.f;

    // this thread's 2 load slots (512 = 128 rows x 4 chunks of 8 halves)
    int lrow[2], lq8[2];
    #pragma unroll
    for (int i = 0; i < 2; i++) {
        int f = tid + i * 256;
        lrow[i] = f >> 2;
        lq8[i]  = (f & 3) << 3;
    }

    __syncthreads();   // arow visible

    // prologue: buffer 0, kt=0
    #pragma unroll
    for (int i = 0; i < 2; i++) {
        uint32_t so = (uint32_t)(lrow[i] * 80 + lq8[i] * 2);
        CP16(sbase + so,         g_xh + arow[lrow[i]] + lq8[i]);
        CP16(sbase + 10240 + so, g_wqkvTh + (size_t)(n0 + lrow[i]) * 256 + lq8[i]);
    }
    CP_COMMIT();

    #pragma unroll
    for (int it = 0; it < 8; it++) {
        if (it < 7) {
            uint32_t bo = (uint32_t)(((it + 1) & 1) * 20480);
            int kt = (it + 1) * 32;
            #pragma unroll
            for (int i = 0; i < 2; i++) {
                uint32_t so = bo + (uint32_t)(lrow[i] * 80 + lq8[i] * 2);
                CP16(sbase + so,         g_xh + arow[lrow[i]] + kt + lq8[i]);
                CP16(sbase + 10240 + so, g_wqkvTh + (size_t)(n0 + lrow[i]) * 256 + kt + lq8[i]);
            }
            CP_COMMIT();
            CP_WAIT(1);
        } else {
            CP_WAIT(0);
        }
        __syncthreads();

        __half (*As)[40] = (__half (*)[40])(smem + (it & 1) * 20480);
        __half (*Bs)[40] = (__half (*)[40])(smem + (it & 1) * 20480 + 10240);

        #pragma unroll
        for (int k16 = 0; k16 < 32; k16 += 16) {
            uint32_t a[4][4], b[4][2];
            #pragma unroll
            for (int im = 0; im < 4; im++) {
                int r = wm + im * 16 + r0;
                a[im][0] = *(uint32_t*)&As[r    ][k16 + 2 * kc];
                a[im][1] = *(uint32_t*)&As[r + 8][k16 + 2 * kc];
                a[im][2] = *(uint32_t*)&As[r    ][k16 + 2 * kc + 8];
                a[im][3] = *(uint32_t*)&As[r + 8][k16 + 2 * kc + 8];
            }
            #pragma unroll
            for (int in_ = 0; in_ < 4; in_++) {
                int n = wn + in_ * 8 + r0;
                b[in_][0] = *(uint32_t*)&Bs[n][k16 + 2 * kc];
                b[in_][1] = *(uint32_t*)&Bs[n][k16 + 2 * kc + 8];
            }
            #pragma unroll
            for (int im = 0; im < 4; im++)
                #pragma unroll
                for (int in_ = 0; in_ < 4; in_++)
                    mma16(acc[im][in_], a[im][0], a[im][1], a[im][2], a[im][3],
                          b[in_][0], b[in_][1]);
        }
        __syncthreads();
    }

    #pragma unroll
    for (int im = 0; im < 4; im++) {
        int r = m0 + wm + im * 16 + r0;
        #pragma unroll
        for (int in_ = 0; in_ < 4; in_++) {
            int c = n0 + wn + in_ * 8 + kc * 2;
            float b0 = bias[c], b1 = bias[c + 1];
            *(uint32_t*)(g_qkvh + (size_t)r * 768 + c) =
                pack_half2(acc[im][in_][0] + b0, acc[im][in_][1] + b1);
            *(uint32_t*)(g_qkvh + (size_t)(r + 8) * 768 + c) =
                pack_half2(acc[im][in_][2] + b0, acc[im][in_][3] + b1);
        }
    }
}

// ===========================================================================
// K2: attention, fp16 mma. Block=(window,head), 4 warps; warp wi owns S rows
// [wi*16, wi*16+16). Bias+mask from precomputed g_biasmat. Softmax in regs.
// P C-frag -> A-frag is a pure register repack (no shuffles for fp16 k16).
// ===========================================================================
__global__ __launch_bounds__(128)
void attn4(const float* dummy)
{
    __shared__ __half qs[64][40];   // rows 49..63 zero
    __shared__ __half ks[56][40];   // rows 49..55 zero
    __shared__ __half vt[32][72];   // [d][t], t 49..63 zero

    const int tid  = threadIdx.x;
    const int w    = blockIdx.x;
    const int h    = blockIdx.y;
    const int wi   = tid >> 5;
    const int lane = tid & 31;
    const int r0   = lane >> 2;
    const int kc   = lane & 3;

    // zero all staging (avoid NaN propagation from stale smem)
    {
        uint4 z = make_uint4(0, 0, 0, 0);
        uint4* p0 = (uint4*)&qs[0][0];
        for (int i = tid; i < 64 * 40 / 8; i += 128) p0[i] = z;
        uint4* p1 = (uint4*)&ks[0][0];
        for (int i = tid; i < 56 * 40 / 8; i += 128) p1[i] = z;
        uint4* p2 = (uint4*)&vt[0][0];
        for (int i = tid; i < 32 * 72 / 8; i += 128) p2[i] = z;
    }
    __syncthreads();

    const __half* qb = g_qkvh + (size_t)w * 49 * 768 + h * 32;
    // 49 rows x (q,k,v) x 4 chunks of 8 halves = 588 slots
    for (int idx = tid; idx < 588; idx += 128) {
        int t    = idx / 12;
        int part = idx - t * 12;
        int sec  = part >> 2;          // 0=q 1=k 2=v
        int c8   = (part & 3) << 3;
        uint4 val = *(const uint4*)(qb + t * 768 + sec * 256 + c8);
        if (sec == 0)      *(uint4*)&qs[t][c8] = val;
        else if (sec == 1) *(uint4*)&ks[t][c8] = val;
        else {
            const __half* hv = (const __half*)&val;
            #pragma unroll
            for (int j = 0; j < 8; j++) vt[c8 + j][t] = hv[j];
        }
    }
    __syncthreads();

    // ---- S = Q @ K^T  (warp tile 16x56; c[7] stays zero as PV padding) ----
    float c[8][4];
    #pragma unroll
    for (int nt = 0; nt < 8; nt++)
        #pragma unroll
        for (int q = 0; q < 4; q++) c[nt][q] = 0.f;

    #pragma unroll
    for (int k16 = 0; k16 < 32; k16 += 16) {
        int r = wi * 16 + r0;
        uint32_t a0 = *(uint32_t*)&qs[r    ][k16 + 2 * kc];
        uint32_t a1 = *(uint32_t*)&qs[r + 8][k16 + 2 * kc];
        uint32_t a2 = *(uint32_t*)&qs[r    ][k16 + 2 * kc + 8];
        uint32_t a3 = *(uint32_t*)&qs[r + 8][k16 + 2 * kc + 8];
        #pragma unroll
        for (int nt = 0; nt < 7; nt++) {
            uint32_t b0 = *(uint32_t*)&ks[nt * 8 + r0][k16 + 2 * kc];
            uint32_t b1 = *(uint32_t*)&ks[nt * 8 + r0][k16 + 2 * kc + 8];
            mma16(c[nt], a0, a1, a2, a3, b0, b1);
        }
    }

    // ---- scale + bias (pre-masked), softmax per row in registers ----
    #pragma unroll
    for (int half_ = 0; half_ < 2; half_++) {
        int q_ = wi * 16 + r0 + half_ * 8;
        const float* bmr = g_biasmat + h * 4096 + q_ * 64;
        #pragma unroll
        for (int nt = 0; nt < 7; nt++) {
            float2 bv = *(const float2*)(bmr + nt * 8 + 2 * kc);
            c[nt][half_ * 2 + 0] = c[nt][half_ * 2 + 0] * 0.5f + bv.x;
            c[nt][half_ * 2 + 1] = c[nt][half_ * 2 + 1] * 0.5f + bv.y;
        }
        float mx = -1e30f;
        #pragma unroll
        for (int nt = 0; nt < 7; nt++) {
            mx = fmaxf(mx, c[nt][half_ * 2]);
            mx = fmaxf(mx, c[nt][half_ * 2 + 1]);
        }
        mx = fmaxf(mx, __shfl_xor_sync(0xffffffffu, mx, 1));
        mx = fmaxf(mx, __shfl_xor_sync(0xffffffffu, mx, 2));
        float s = 0.f;
        #pragma unroll
        for (int nt = 0; nt < 7; nt++) {
            #pragma unroll
            for (int e = 0; e < 2; e++) {
                float p = __expf(c[nt][half_ * 2 + e] - mx);
                c[nt][half_ * 2 + e] = p;
                s += p;
            }
        }
        s += __shfl_xor_sync(0xffffffffu, s, 1);
        s += __shfl_xor_sync(0xffffffffu, s, 2);
        float inv = 1.0f / s;
        #pragma unroll
        for (int nt = 0; nt < 7; nt++) {
            c[nt][half_ * 2 + 0] *= inv;
            c[nt][half_ * 2 + 1] *= inv;
        }
    }

    // ---- O = P @ V  (warp tile 16x32); P A-frags from C-frags, no shuffles ----
    float o[4][4];
    #pragma unroll
    for (int jn = 0; jn < 4; jn++)
        #pragma unroll
        for (int q = 0; q < 4; q++) o[jn][q] = 0.f;

    #pragma unroll
    for (int kt = 0; kt < 4; kt++) {
        uint32_t a0 = pack_half2(c[2 * kt][0],     c[2 * kt][1]);
        uint32_t a1 = pack_half2(c[2 * kt][2],     c[2 * kt][3]);
        uint32_t a2 = pack_half2(c[2 * kt + 1][0], c[2 * kt + 1][1]);
        uint32_t a3 = pack_half2(c[2 * kt + 1][2], c[2 * kt + 1][3]);
        #pragma unroll
        for (int jn = 0; jn < 4; jn++) {
            uint32_t b0 = *(uint32_t*)&vt[jn * 8 + r0][kt * 16 + 2 * kc];
            uint32_t b1 = *(uint32_t*)&vt[jn * 8 + r0][kt * 16 + 2 * kc + 8];
            mma16(o[jn], a0, a1, a2, a3, b0, b1);
        }
    }

    // ---- store O rows < 49 (fp16) ----
    #pragma unroll
    for (int half_ = 0; half_ < 2; half_++) {
        int q_ = wi * 16 + r0 + half_ * 8;
        if (q_ < 49) {
            __half* op = g_atth + ((size_t)w * 49 + q_) * 256 + h * 32;
            #pragma unroll
            for (int jn = 0; jn < 4; jn++)
                *(uint32_t*)(op + jn * 8 + 2 * kc) =
                    pack_half2(o[jn][half_ * 2 + 0], o[jn][half_ * 2 + 1]);
        }
    }
}

// ===========================================================================
// K3: out = LN(g_att @ w_out + b_out + gather(x))  fp16 mma + cp.async
// CTA 128x256 (full rows), BK=32, 8 warps (2m x 4n), warp tile 64x64.
// smem: buf{0,1}: A[128][40]h + B[256][40]h (30720 B each); arow/s1/s2 after.
// ===========================================================================
#define K3_SMEM 62976
__global__ __launch_bounds__(256, 1)
void out_mma(const float* __restrict__ x,
             const float* __restrict__ bout,
             const float* __restrict__ gamma,
             const float* __restrict__ beta,
             float* __restrict__ out)
{
    extern __shared__ char smem[];
    const uint32_t sbase = smem_u32(smem);
    int*   arow = (int*)(smem + 61440);
    float* s1   = (float*)(smem + 61952);
    float* s2   = (float*)(smem + 62464);

    const int tid  = threadIdx.x;
    const int wid  = tid >> 5;
    const int lane = tid & 31;
    const int m0   = blockIdx.x * 128;
    if (tid < 128) { arow[tid] = xrow_offset(m0 + tid); s1[tid] = 0.f; s2[tid] = 0.f; }

    const int wm = (wid >> 2) * 64;
    const int wn = (wid & 3) * 64;
    const int r0 = lane >> 2;
    const int kc = lane & 3;

    float acc[4][8][4];
    #pragma unroll
    for (int i = 0; i < 4; i++)
        #pragma unroll
        for (int j = 0; j < 8; j++)
            #pragma unroll
            for (int q = 0; q < 4; q++) acc[i][j][q] = 0.f;

    __syncthreads();

    // load slots: A 512 (2/thread), B 1024 (4/thread)
    #pragma unroll
    for (int i = 0; i < 2; i++) {
        int f = tid + i * 256;
        int r = f >> 2, q8 = (f & 3) << 3;
        CP16(sbase + (uint32_t)(r * 80 + q8 * 2),
             g_atth + (size_t)(m0 + r) * 256 + q8);
    }
    #pragma unroll
    for (int i = 0; i < 4; i++) {
        int f = tid + i * 256;
        int r = f >> 2, q8 = (f & 3) << 3;
        CP16(sbase + 10240 + (uint32_t)(r * 80 + q8 * 2),
             g_woutTh + (size_t)r * 256 + q8);
    }
    CP_COMMIT();

    #pragma unroll
    for (int it = 0; it < 8; it++) {
        if (it < 7) {
            uint32_t bo = (uint32_t)(((it + 1) & 1) * 30720);
            int kt = (it + 1) * 32;
            #pragma unroll
            for (int i = 0; i < 2; i++) {
                int f = tid + i * 256;
                int r = f >> 2, q8 = (f & 3) << 3;
                CP16(sbase + bo + (uint32_t)(r * 80 + q8 * 2),
                     g_atth + (size_t)(m0 + r) * 256 + kt + q8);
            }
            #pragma unroll
            for (int i = 0; i < 4; i++) {
                int f = tid + i * 256;
                int r = f >> 2, q8 = (f & 3) << 3;
                CP16(sbase + bo + 10240 + (uint32_t)(r * 80 + q8 * 2),
                     g_woutTh + (size_t)r * 256 + kt + q8);
            }
            CP_COMMIT();
            CP_WAIT(1);
        } else {
            CP_WAIT(0);
        }
        __syncthreads();

        __half (*As)[40] = (__half (*)[40])(smem + (it & 1) * 30720);
        __half (*Bs)[40] = (__half (*)[40])(smem + (it & 1) * 30720 + 10240);

        #pragma unroll
        for (int k16 = 0; k16 < 32; k16 += 16) {
            uint32_t a[4][4], b[8][2];
            #pragma unroll
            for (int im = 0; im < 4; im++) {
                int r = wm + im * 16 + r0;
                a[im][0] = *(uint32_t*)&As[r    ][k16 + 2 * kc];
                a[im][1] = *(uint32_t*)&As[r + 8][k16 + 2 * kc];
                a[im][2] = *(uint32_t*)&As[r    ][k16 + 2 * kc + 8];
                a[im][3] = *(uint32_t*)&As[r + 8][k16 + 2 * kc + 8];
            }
            #pragma unroll
            for (int in_ = 0; in_ < 8; in_++) {
                int n = wn + in_ * 8 + r0;
                b[in_][0] = *(uint32_t*)&Bs[n][k16 + 2 * kc];
                b[in_][1] = *(uint32_t*)&Bs[n][k16 + 2 * kc + 8];
            }
            #pragma unroll
            for (int im = 0; im < 4; im++)
                #pragma unroll
                for (int in_ = 0; in_ < 8; in_++)
                    mma16(acc[im][in_], a[im][0], a[im][1], a[im][2], a[im][3],
                          b[in_][0], b[in_][1]);
        }
        __syncthreads();
    }

    // ---- epilogue: y = acc + bias + residual(fp32); LN over full rows ----
    #pragma unroll
    for (int im = 0; im < 4; im++) {
        #pragma unroll
        for (int half_ = 0; half_ < 2; half_++) {
            int rl = wm + im * 16 + r0 + half_ * 8;
            const float* xr = x + arow[rl];
            float p1 = 0.f, p2 = 0.f;
            #pragma unroll
            for (int in_ = 0; in_ < 8; in_++) {
                int c = wn + in_ * 8 + kc * 2;
                float2 xv = *(const float2*)(xr + c);
                float y0 = acc[im][in_][half_ * 2 + 0] + bout[c]     + xv.x;
                float y1 = acc[im][in_][half_ * 2 + 1] + bout[c + 1] + xv.y;
                acc[im][in_][half_ * 2 + 0] = y0;
                acc[im][in_][half_ * 2 + 1] = y1;
                p1 += y0 + y1;
                p2 += y0 * y0 + y1 * y1;
            }
            p1 += __shfl_xor_sync(0xffffffffu, p1, 1);
            p2 += __shfl_xor_sync(0xffffffffu, p2, 1);
            p1 += __shfl_xor_sync(0xffffffffu, p1, 2);
            p2 += __shfl_xor_sync(0xffffffffu, p2, 2);
            if (kc == 0) {
                atomicAdd(&s1[rl], p1);
                atomicAdd(&s2[rl], p2);
            }
        }
    }
    __syncthreads();

    #pragma unroll
    for (int im = 0; im < 4; im++) {
        #pragma unroll
        for (int half_ = 0; half_ < 2; half_++) {
            int rl = wm + im * 16 + r0 + half_ * 8;
            int m  = m0 + rl;
            float mean = s1[rl] * (1.0f / 256.0f);
            float var  = s2[rl] * (1.0f / 256.0f) - mean * mean;
            float rstd = rsqrtf(var + 1e-5f);
            #pragma unroll
            for (int in_ = 0; in_ < 8; in_++) {
                int c = wn + in_ * 8 + kc * 2;
                float y0 = acc[im][in_][half_ * 2 + 0];
                float y1 = acc[im][in_][half_ * 2 + 1];
                float2 o = make_float2((y0 - mean) * rstd * gamma[c]     + beta[c],
                                       (y1 - mean) * rstd * gamma[c + 1] + beta[c + 1]);
                *(float2*)(out + (size_t)m * 256 + c) = o;
            }
        }
    }
}

// ===========================================================================
extern "C" void kernel_launch(void* const* d_in, const int* in_sizes, int n_in,
                              void* d_out, int out_size)
{
    const float* x          = (const float*)d_in[0];
    const float* w_qkv      = (const float*)d_in[1];
    const float* b_qkv      = (const float*)d_in[2];
    const float* bias_table = (const float*)d_in[3];
    const float* w_out      = (const float*)d_in[4];
    const float* b_out      = (const float*)d_in[5];
    const float* ln_gamma   = (const float*)d_in[6];
    const float* ln_beta    = (const float*)d_in[7];
    float* out = (float*)d_out;

    cudaFuncSetAttribute(qkv_mma, cudaFuncAttributeMaxDynamicSharedMemorySize, K1_SMEM);
    cudaFuncSetAttribute(out_mma, cudaFuncAttributeMaxDynamicSharedMemorySize, K3_SMEM);

    prep_xh<<<50176, 256>>>((const float4*)x);
    prep_wh<<<(256 * 768 + 255) / 256, 256>>>(w_qkv, 256, 768, 0);
    prep_wh<<<(256 * 256 + 255) / 256, 256>>>(w_out, 256, 256, 1);
    prep_bias<<<128, 256>>>(bias_table);
    qkv_mma<<<dim3(6, 1568), 256, K1_SMEM>>>(nullptr, b_qkv);
    attn4<<<dim3(NWIN, HEADS), 128>>>(nullptr);
    out_mma<<<1568, 256, K3_SMEM>>>(x, b_out, ln_gamma, ln_beta, out);
}

// round 6
// speedup vs baseline: 4.3198x; 1.0112x over previous
#include <cuda_runtime.h>
#include <cuda_fp16.h>
#include <cstdint>

#define MTOT  200704
#define NWIN  4096
#define HEADS 8

// Scratch (device globals; no cudaMalloc allowed)
__device__ __half g_xh   [51380224];    // x converted to fp16
__device__ __half g_qkvh [154140672];   // [MTOT][768] fp16
__device__ __half g_atth [51380224];    // [MTOT][256] fp16
__device__ __half g_wqkvTh[768 * 256];  // w_qkv^T [N][K] fp16
__device__ __half g_woutTh[256 * 256];  // w_out^T [N][K] fp16
__device__ float  g_biasmat[8 * 64 * 64]; // per-head bias matrix, masked

// ===========================================================================
// Helpers
// ===========================================================================
__device__ __forceinline__ uint32_t smem_u32(const void* p) {
    uint32_t a;
    asm("{ .reg .u64 t; cvta.to.shared.u64 t, %1; cvt.u32.u64 %0, t; }"
        : "=r"(a) : "l"(p));
    return a;
}

__device__ __forceinline__ uint32_t pack_half2(float a, float b) {
    __half2 h = __floats2half2_rn(a, b);
    return *(uint32_t*)&h;
}

// m16n8k16 fp16 MMA, fp32 accumulate
__device__ __forceinline__ void mma16(float d[4],
                                      uint32_t a0, uint32_t a1, uint32_t a2, uint32_t a3,
                                      uint32_t b0, uint32_t b1) {
    asm volatile(
        "mma.sync.aligned.m16n8k16.row.col.f32.f16.f16.f32 "
        "{%0,%1,%2,%3}, {%4,%5,%6,%7}, {%8,%9}, {%0,%1,%2,%3};"
        : "+f"(d[0]), "+f"(d[1]), "+f"(d[2]), "+f"(d[3])
        : "r"(a0), "r"(a1), "r"(a2), "r"(a3), "r"(b0), "r"(b1));
}

__device__ __forceinline__ void ldsm_x4(uint32_t& d0, uint32_t& d1,
                                        uint32_t& d2, uint32_t& d3, uint32_t addr) {
    asm volatile("ldmatrix.sync.aligned.m8n8.x4.shared.b16 {%0,%1,%2,%3}, [%4];"
                 : "=r"(d0), "=r"(d1), "=r"(d2), "=r"(d3) : "r"(addr));
}

#define CP16(dst_u32, src_ptr) \
    asm volatile("cp.async.ca.shared.global [%0], [%1], 16;" \
                 :: "r"(dst_u32), "l"(src_ptr))
#define CP_COMMIT() asm volatile("cp.async.commit_group;")
#define CP_WAIT(n)  asm volatile("cp.async.wait_group %0;" :: "n"(n))

// Map token row r (window-major) to element offset of its pixel row in x[4,224,224,256]
__device__ __forceinline__ int xrow_offset(int r) {
    int w   = r / 49;
    int t   = r - w * 49;
    int b   = w >> 10;
    int rem = w & 1023;
    int wh  = rem >> 5;
    int ww  = rem & 31;
    int i   = t / 7;
    int j   = t - i * 7;
    int row = (b * 224 + wh * 7 + i) * 224 + (ww * 7 + j);
    return row << 8;
}

// ===========================================================================
// Prep kernels
// ===========================================================================
__global__ void prep_xh(const float4* __restrict__ x4) {
    int idx = blockIdx.x * 256 + threadIdx.x;
    float4 v = x4[idx];
    ((uint2*)g_xh)[idx] = make_uint2(pack_half2(v.x, v.y), pack_half2(v.z, v.w));
}

__global__ void prep_wh(const float* __restrict__ w, int K, int N, int which) {
    __half* wT = which ? g_woutTh : g_wqkvTh;
    int idx = blockIdx.x * 256 + threadIdx.x;
    if (idx < K * N) {
        int k = idx / N;
        int n = idx - k * N;
        wT[(size_t)n * K + k] = __float2half_rn(w[idx]);
    }
}

__global__ void prep_bias(const float* __restrict__ bt) {
    int idx = blockIdx.x * 256 + threadIdx.x;   // 8*64*64
    int h = idx >> 12;
    int r = (idx >> 6) & 63;
    int c = idx & 63;
    float v;
    if (c >= 49)      v = -1e30f;
    else if (r >= 49) v = 0.f;
    else {
        int i1 = r / 7, j1 = r - i1 * 7;
        int i2 = c / 7, j2 = c - i2 * 7;
        v = bt[((i1 - i2 + 6) * 13 + (j1 - j2 + 6)) * 8 + h];
    }
    g_biasmat[idx] = v;
}

// ===========================================================================
// K1: qkv = gather(x) @ w_qkv + b_qkv   fp16 mma + ldmatrix + cp.async
// CTA 128x128, BK=32, 8 warps (2m x 4n), warp tile 64x32.
// smem: buf0 A[128][40]h @0, B[128][40]h @10240; buf1 @20480; arow @40960
// ===========================================================================
#define K1_SMEM 41472
__global__ __launch_bounds__(256, 2)
void qkv_mma(const float* dummy, const float* __restrict__ bias)
{
    extern __shared__ char smem[];
    const uint32_t sbase = smem_u32(smem);
    int* arow = (int*)(smem + 40960);

    const int tid  = threadIdx.x;
    const int wid  = tid >> 5;
    const int lane = tid & 31;
    const int m0   = blockIdx.y * 128;
    const int n0   = blockIdx.x * 128;
    if (tid < 128) arow[tid] = xrow_offset(m0 + tid);

    const int wm = (wid >> 2) * 64;
    const int wn = (wid & 3) * 32;
    const int r0 = lane >> 2;
    const int kc = lane & 3;
    const int lj = lane >> 3;
    const int lq = lane & 7;

    // ldmatrix per-lane byte offsets within A / B tiles
    const uint32_t a_off = (uint32_t)((wm + ((lj & 1) << 3) + lq) * 80 + ((lj >> 1) << 4));
    const uint32_t b_off = 10240u + (uint32_t)((wn + (((lj >> 1) & 1) << 3) + lq) * 80 + ((lj & 1) << 4));

    float acc[4][4][4];
    #pragma unroll
    for (int i = 0; i < 4; i++)
        #pragma unroll
        for (int j = 0; j < 4; j++)
            #pragma unroll
            for (int q = 0; q < 4; q++) acc[i][j][q] = 0.f;

    int lrow[2], lq8[2];
    #pragma unroll
    for (int i = 0; i < 2; i++) {
        int f = tid + i * 256;
        lrow[i] = f >> 2;
        lq8[i]  = (f & 3) << 3;
    }

    __syncthreads();

    #pragma unroll
    for (int i = 0; i < 2; i++) {
        uint32_t so = (uint32_t)(lrow[i] * 80 + lq8[i] * 2);
        CP16(sbase + so,         g_xh + arow[lrow[i]] + lq8[i]);
        CP16(sbase + 10240 + so, g_wqkvTh + (size_t)(n0 + lrow[i]) * 256 + lq8[i]);
    }
    CP_COMMIT();

    #pragma unroll
    for (int it = 0; it < 8; it++) {
        if (it < 7) {
            uint32_t bo = (uint32_t)(((it + 1) & 1) * 20480);
            int kt = (it + 1) * 32;
            #pragma unroll
            for (int i = 0; i < 2; i++) {
                uint32_t so = bo + (uint32_t)(lrow[i] * 80 + lq8[i] * 2);
                CP16(sbase + so,         g_xh + arow[lrow[i]] + kt + lq8[i]);
                CP16(sbase + 10240 + so, g_wqkvTh + (size_t)(n0 + lrow[i]) * 256 + kt + lq8[i]);
            }
            CP_COMMIT();
            CP_WAIT(1);
        } else {
            CP_WAIT(0);
        }
        __syncthreads();

        const uint32_t bufb = sbase + (uint32_t)((it & 1) * 20480);

        #pragma unroll
        for (int k16 = 0; k16 < 32; k16 += 16) {
            uint32_t a[4][4], b2[2][4];
            #pragma unroll
            for (int im = 0; im < 4; im++)
                ldsm_x4(a[im][0], a[im][1], a[im][2], a[im][3],
                        bufb + a_off + (uint32_t)(im * 1280 + k16 * 2));
            #pragma unroll
            for (int g = 0; g < 2; g++)
                ldsm_x4(b2[g][0], b2[g][1], b2[g][2], b2[g][3],
                        bufb + b_off + (uint32_t)(g * 1280 + k16 * 2));
            #pragma unroll
            for (int im = 0; im < 4; im++)
                #pragma unroll
                for (int in_ = 0; in_ < 4; in_++)
                    mma16(acc[im][in_], a[im][0], a[im][1], a[im][2], a[im][3],
                          b2[in_ >> 1][(in_ & 1) << 1], b2[in_ >> 1][((in_ & 1) << 1) + 1]);
        }
        __syncthreads();
    }

    #pragma unroll
    for (int im = 0; im < 4; im++) {
        int r = m0 + wm + im * 16 + r0;
        #pragma unroll
        for (int in_ = 0; in_ < 4; in_++) {
            int c = n0 + wn + in_ * 8 + kc * 2;
            float b0 = bias[c], b1 = bias[c + 1];
            *(uint32_t*)(g_qkvh + (size_t)r * 768 + c) =
                pack_half2(acc[im][in_][0] + b0, acc[im][in_][1] + b1);
            *(uint32_t*)(g_qkvh + (size_t)(r + 8) * 768 + c) =
                pack_half2(acc[im][in_][2] + b0, acc[im][in_][3] + b1);
        }
    }
}

// ===========================================================================
// K2: attention, fp16 mma + ldmatrix. Block=(window,head), 4 warps.
// ===========================================================================
__global__ __launch_bounds__(128)
void attn5(const float* dummy)
{
    __shared__ __half qs[64][40];   // rows 49..63 zero
    __shared__ __half ks[64][40];   // rows 49..63 zero
    __shared__ __half vt[32][72];   // [d][t], t 49..71 zero

    const int tid  = threadIdx.x;
    const int w    = blockIdx.x;
    const int h    = blockIdx.y;
    const int wi   = tid >> 5;
    const int lane = tid & 31;
    const int r0   = lane >> 2;
    const int kc   = lane & 3;
    const int lj   = lane >> 3;
    const int lq   = lane & 7;

    {
        uint4 z = make_uint4(0, 0, 0, 0);
        uint4* p0 = (uint4*)&qs[0][0];
        for (int i = tid; i < 64 * 40 / 8; i += 128) p0[i] = z;
        uint4* p1 = (uint4*)&ks[0][0];
        for (int i = tid; i < 64 * 40 / 8; i += 128) p1[i] = z;
        uint4* p2 = (uint4*)&vt[0][0];
        for (int i = tid; i < 32 * 72 / 8; i += 128) p2[i] = z;
    }
    __syncthreads();

    const __half* qb = g_qkvh + (size_t)w * 49 * 768 + h * 32;
    for (int idx = tid; idx < 588; idx += 128) {
        int t    = idx / 12;
        int part = idx - t * 12;
        int sec  = part >> 2;
        int c8   = (part & 3) << 3;
        uint4 val = *(const uint4*)(qb + t * 768 + sec * 256 + c8);
        if (sec == 0)      *(uint4*)&qs[t][c8] = val;
        else if (sec == 1) *(uint4*)&ks[t][c8] = val;
        else {
            const __half* hv = (const __half*)&val;
            #pragma unroll
            for (int j = 0; j < 8; j++) vt[c8 + j][t] = hv[j];
        }
    }
    __syncthreads();

    const uint32_t qsb = smem_u32(&qs[0][0]);
    const uint32_t ksb = smem_u32(&ks[0][0]);
    const uint32_t vtb = smem_u32(&vt[0][0]);

    // ldmatrix lane offsets
    const uint32_t qa_off = (uint32_t)((wi * 16 + ((lj & 1) << 3) + lq) * 80 + ((lj >> 1) << 4));
    const uint32_t kb_off = (uint32_t)(((((lj >> 1) & 1) << 3) + lq) * 80 + ((lj & 1) << 4));
    const uint32_t vb_off = (uint32_t)(((((lj >> 1) & 1) << 3) + lq) * 144 + ((lj & 1) << 4));

    // ---- S = Q @ K^T  (warp tile 16x64; cols 56-63 are exact zeros) ----
    float c[8][4];
    #pragma unroll
    for (int nt = 0; nt < 8; nt++)
        #pragma unroll
        for (int q = 0; q < 4; q++) c[nt][q] = 0.f;

    #pragma unroll
    for (int k16 = 0; k16 < 32; k16 += 16) {
        uint32_t a0, a1, a2, a3;
        ldsm_x4(a0, a1, a2, a3, qsb + qa_off + (uint32_t)(k16 * 2));
        #pragma unroll
        for (int g = 0; g < 4; g++) {
            uint32_t b0, b1, b2, b3;
            ldsm_x4(b0, b1, b2, b3, ksb + kb_off + (uint32_t)(g * 1280 + k16 * 2));
            mma16(c[2 * g],     a0, a1, a2, a3, b0, b1);
            mma16(c[2 * g + 1], a0, a1, a2, a3, b2, b3);
        }
    }

    // ---- scale + bias (pre-masked), softmax per row in registers ----
    #pragma unroll
    for (int half_ = 0; half_ < 2; half_++) {
        int q_ = wi * 16 + r0 + half_ * 8;
        const float* bmr = g_biasmat + h * 4096 + q_ * 64;
        #pragma unroll
        for (int nt = 0; nt < 7; nt++) {
            float2 bv = *(const float2*)(bmr + nt * 8 + 2 * kc);
            c[nt][half_ * 2 + 0] = c[nt][half_ * 2 + 0] * 0.5f + bv.x;
            c[nt][half_ * 2 + 1] = c[nt][half_ * 2 + 1] * 0.5f + bv.y;
        }
        float mx = -1e30f;
        #pragma unroll
        for (int nt = 0; nt < 7; nt++) {
            mx = fmaxf(mx, c[nt][half_ * 2]);
            mx = fmaxf(mx, c[nt][half_ * 2 + 1]);
        }
        mx = fmaxf(mx, __shfl_xor_sync(0xffffffffu, mx, 1));
        mx = fmaxf(mx, __shfl_xor_sync(0xffffffffu, mx, 2));
        float s = 0.f;
        #pragma unroll
        for (int nt = 0; nt < 7; nt++) {
            #pragma unroll
            for (int e = 0; e < 2; e++) {
                float p = __expf(c[nt][half_ * 2 + e] - mx);
                c[nt][half_ * 2 + e] = p;
                s += p;
            }
        }
        s += __shfl_xor_sync(0xffffffffu, s, 1);
        s += __shfl_xor_sync(0xffffffffu, s, 2);
        float inv = 1.0f / s;
        #pragma unroll
        for (int nt = 0; nt < 7; nt++) {
            c[nt][half_ * 2 + 0] *= inv;
            c[nt][half_ * 2 + 1] *= inv;
        }
        // cols 56-63: zero (ks rows zeroed; keep exact zeros for PV padding)
        c[7][half_ * 2 + 0] = 0.f;
        c[7][half_ * 2 + 1] = 0.f;
    }

    // ---- O = P @ V  (warp tile 16x32); P A-frags from C-frags directly ----
    float o[4][4];
    #pragma unroll
    for (int jn = 0; jn < 4; jn++)
        #pragma unroll
        for (int q = 0; q < 4; q++) o[jn][q] = 0.f;

    #pragma unroll
    for (int kt = 0; kt < 4; kt++) {
        uint32_t a0 = pack_half2(c[2 * kt][0],     c[2 * kt][1]);
        uint32_t a1 = pack_half2(c[2 * kt][2],     c[2 * kt][3]);
        uint32_t a2 = pack_half2(c[2 * kt + 1][0], c[2 * kt + 1][1]);
        uint32_t a3 = pack_half2(c[2 * kt + 1][2], c[2 * kt + 1][3]);
        #pragma unroll
        for (int g = 0; g < 2; g++) {
            uint32_t b0, b1, b2, b3;
            ldsm_x4(b0, b1, b2, b3, vtb + vb_off + (uint32_t)(g * 2304 + kt * 32));
            mma16(o[2 * g],     a0, a1, a2, a3, b0, b1);
            mma16(o[2 * g + 1], a0, a1, a2, a3, b2, b3);
        }
    }

    #pragma unroll
    for (int half_ = 0; half_ < 2; half_++) {
        int q_ = wi * 16 + r0 + half_ * 8;
        if (q_ < 49) {
            __half* op = g_atth + ((size_t)w * 49 + q_) * 256 + h * 32;
            #pragma unroll
            for (int jn = 0; jn < 4; jn++)
                *(uint32_t*)(op + jn * 8 + 2 * kc) =
                    pack_half2(o[jn][half_ * 2 + 0], o[jn][half_ * 2 + 1]);
        }
    }
}

// ===========================================================================
// K3: out = LN(g_att @ w_out + b_out + gather(x))  fp16 mma + ldmatrix
// CTA 128x256 (full rows), BK=32, 8 warps (2m x 4n), warp tile 64x64.
// ===========================================================================
#define K3_SMEM 62976
__global__ __launch_bounds__(256, 1)
void out_mma(const float* __restrict__ x,
             const float* __restrict__ bout,
             const float* __restrict__ gamma,
             const float* __restrict__ beta,
             float* __restrict__ out)
{
    extern __shared__ char smem[];
    const uint32_t sbase = smem_u32(smem);
    int*   arow = (int*)(smem + 61440);
    float* s1   = (float*)(smem + 61952);
    float* s2   = (float*)(smem + 62464);

    const int tid  = threadIdx.x;
    const int wid  = tid >> 5;
    const int lane = tid & 31;
    const int m0   = blockIdx.x * 128;
    if (tid < 128) { arow[tid] = xrow_offset(m0 + tid); s1[tid] = 0.f; s2[tid] = 0.f; }

    const int wm = (wid >> 2) * 64;
    const int wn = (wid & 3) * 64;
    const int r0 = lane >> 2;
    const int kc = lane & 3;
    const int lj = lane >> 3;
    const int lq = lane & 7;

    const uint32_t a_off = (uint32_t)((wm + ((lj & 1) << 3) + lq) * 80 + ((lj >> 1) << 4));
    const uint32_t b_off = 10240u + (uint32_t)((wn + (((lj >> 1) & 1) << 3) + lq) * 80 + ((lj & 1) << 4));

    float acc[4][8][4];
    #pragma unroll
    for (int i = 0; i < 4; i++)
        #pragma unroll
        for (int j = 0; j < 8; j++)
            #pragma unroll
            for (int q = 0; q < 4; q++) acc[i][j][q] = 0.f;

    __syncthreads();

    #pragma unroll
    for (int i = 0; i < 2; i++) {
        int f = tid + i * 256;
        int r = f >> 2, q8 = (f & 3) << 3;
        CP16(sbase + (uint32_t)(r * 80 + q8 * 2), g_atth + (size_t)(m0 + r) * 256 + q8);
    }
    #pragma unroll
    for (int i = 0; i < 4; i++) {
        int f = tid + i * 256;
        int r = f >> 2, q8 = (f & 3) << 3;
        CP16(sbase + 10240 + (uint32_t)(r * 80 + q8 * 2), g_woutTh + (size_t)r * 256 + q8);
    }
    CP_COMMIT();

    #pragma unroll
    for (int it = 0; it < 8; it++) {
        if (it < 7) {
            uint32_t bo = (uint32_t)(((it + 1) & 1) * 30720);
            int kt = (it + 1) * 32;
            #pragma unroll
            for (int i = 0; i < 2; i++) {
                int f = tid + i * 256;
                int r = f >> 2, q8 = (f & 3) << 3;
                CP16(sbase + bo + (uint32_t)(r * 80 + q8 * 2),
                     g_atth + (size_t)(m0 + r) * 256 + kt + q8);
            }
            #pragma unroll
            for (int i = 0; i < 4; i++) {
                int f = tid + i * 256;
                int r = f >> 2, q8 = (f & 3) << 3;
                CP16(sbase + bo + 10240 + (uint32_t)(r * 80 + q8 * 2),
                     g_woutTh + (size_t)r * 256 + kt + q8);
            }
            CP_COMMIT();
            CP_WAIT(1);
        } else {
            CP_WAIT(0);
        }
        __syncthreads();

        const uint32_t bufb = sbase + (uint32_t)((it & 1) * 30720);

        #pragma unroll
        for (int k16 = 0; k16 < 32; k16 += 16) {
            uint32_t a[4][4], b2[4][4];
            #pragma unroll
            for (int im = 0; im < 4; im++)
                ldsm_x4(a[im][0], a[im][1], a[im][2], a[im][3],
                        bufb + a_off + (uint32_t)(im * 1280 + k16 * 2));
            #pragma unroll
            for (int g = 0; g < 4; g++)
                ldsm_x4(b2[g][0], b2[g][1], b2[g][2], b2[g][3],
                        bufb + b_off + (uint32_t)(g * 1280 + k16 * 2));
            #pragma unroll
            for (int im = 0; im < 4; im++)
                #pragma unroll
                for (int in_ = 0; in_ < 8; in_++)
                    mma16(acc[im][in_], a[im][0], a[im][1], a[im][2], a[im][3],
                          b2[in_ >> 1][(in_ & 1) << 1], b2[in_ >> 1][((in_ & 1) << 1) + 1]);
        }
        __syncthreads();
    }

    // ---- epilogue: y = acc + bias + residual(fp32); LN over full rows ----
    #pragma unroll
    for (int im = 0; im < 4; im++) {
        #pragma unroll
        for (int half_ = 0; half_ < 2; half_++) {
            int rl = wm + im * 16 + r0 + half_ * 8;
            const float* xr = x + arow[rl];
            float p1 = 0.f, p2 = 0.f;
            #pragma unroll
            for (int in_ = 0; in_ < 8; in_++) {
                int c = wn + in_ * 8 + kc * 2;
                float2 xv = *(const float2*)(xr + c);
                float y0 = acc[im][in_][half_ * 2 + 0] + bout[c]     + xv.x;
                float y1 = acc[im][in_][half_ * 2 + 1] + bout[c + 1] + xv.y;
                acc[im][in_][half_ * 2 + 0] = y0;
                acc[im][in_][half_ * 2 + 1] = y1;
                p1 += y0 + y1;
                p2 += y0 * y0 + y1 * y1;
            }
            p1 += __shfl_xor_sync(0xffffffffu, p1, 1);
            p2 += __shfl_xor_sync(0xffffffffu, p2, 1);
            p1 += __shfl_xor_sync(0xffffffffu, p1, 2);
            p2 += __shfl_xor_sync(0xffffffffu, p2, 2);
            if (kc == 0) {
                atomicAdd(&s1[rl], p1);
                atomicAdd(&s2[rl], p2);
            }
        }
    }
    __syncthreads();

    #pragma unroll
    for (int im = 0; im < 4; im++) {
        #pragma unroll
        for (int half_ = 0; half_ < 2; half_++) {
            int rl = wm + im * 16 + r0 + half_ * 8;
            int m  = m0 + rl;
            float mean = s1[rl] * (1.0f / 256.0f);
            float var  = s2[rl] * (1.0f / 256.0f) - mean * mean;
            float rstd = rsqrtf(var + 1e-5f);
            #pragma unroll
            for (int in_ = 0; in_ < 8; in_++) {
                int c = wn + in_ * 8 + kc * 2;
                float y0 = acc[im][in_][half_ * 2 + 0];
                float y1 = acc[im][in_][half_ * 2 + 1];
                float2 o = make_float2((y0 - mean) * rstd * gamma[c]     + beta[c],
                                       (y1 - mean) * rstd * gamma[c + 1] + beta[c + 1]);
                *(float2*)(out + (size_t)m * 256 + c) = o;
            }
        }
    }
}

// ===========================================================================
extern "C" void kernel_launch(void* const* d_in, const int* in_sizes, int n_in,
                              void* d_out, int out_size)
{
    const float* x          = (const float*)d_in[0];
    const float* w_qkv      = (const float*)d_in[1];
    const float* b_qkv      = (const float*)d_in[2];
    const float* bias_table = (const float*)d_in[3];
    const float* w_out      = (const float*)d_in[4];
    const float* b_out      = (const float*)d_in[5];
    const float* ln_gamma   = (const float*)d_in[6];
    const float* ln_beta    = (const float*)d_in[7];
    float* out = (float*)d_out;

    cudaFuncSetAttribute(qkv_mma, cudaFuncAttributeMaxDynamicSharedMemorySize, K1_SMEM);
    cudaFuncSetAttribute(out_mma, cudaFuncAttributeMaxDynamicSharedMemorySize, K3_SMEM);

    prep_xh<<<50176, 256>>>((const float4*)x);
    prep_wh<<<(256 * 768 + 255) / 256, 256>>>(w_qkv, 256, 768, 0);
    prep_wh<<<(256 * 256 + 255) / 256, 256>>>(w_out, 256, 256, 1);
    prep_bias<<<128, 256>>>(bias_table);
    qkv_mma<<<dim3(6, 1568), 256, K1_SMEM>>>(nullptr, b_qkv);
    attn5<<<dim3(NWIN, HEADS), 128>>>(nullptr);
    out_mma<<<1568, 256, K3_SMEM>>>(x, b_out, ln_gamma, ln_beta, out);
}

// round 8
// speedup vs baseline: 4.7302x; 1.0950x over previous
#include <cuda_runtime.h>
#include <cuda_fp16.h>
#include <cstdint>

#define MTOT  200704
#define NWIN  4096
#define HEADS 8

// Scratch (device globals; no cudaMalloc allowed)
__device__ __half g_xh   [51380224];    // x converted to fp16
__device__ __half g_atth [51380224];    // [MTOT][256] fp16
__device__ __half g_wqkvTh[768 * 256];  // w_qkv^T [N][K] fp16
__device__ __half g_woutTh[256 * 256];  // w_out^T [N][K] fp16
__device__ float  g_biasmat[8 * 64 * 64]; // per-head bias matrix, masked

// ===========================================================================
// Helpers
// ===========================================================================
__device__ __forceinline__ uint32_t smem_u32(const void* p) {
    uint32_t a;
    asm("{ .reg .u64 t; cvta.to.shared.u64 t, %1; cvt.u32.u64 %0, t; }"
        : "=r"(a) : "l"(p));
    return a;
}

__device__ __forceinline__ uint32_t pack_half2(float a, float b) {
    __half2 h = __floats2half2_rn(a, b);
    return *(uint32_t*)&h;
}

// m16n8k16 fp16 MMA, fp32 accumulate
__device__ __forceinline__ void mma16(float d[4],
                                      uint32_t a0, uint32_t a1, uint32_t a2, uint32_t a3,
                                      uint32_t b0, uint32_t b1) {
    asm volatile(
        "mma.sync.aligned.m16n8k16.row.col.f32.f16.f16.f32 "
        "{%0,%1,%2,%3}, {%4,%5,%6,%7}, {%8,%9}, {%0,%1,%2,%3};"
        : "+f"(d[0]), "+f"(d[1]), "+f"(d[2]), "+f"(d[3])
        : "r"(a0), "r"(a1), "r"(a2), "r"(a3), "r"(b0), "r"(b1));
}

__device__ __forceinline__ void ldsm_x4(uint32_t& d0, uint32_t& d1,
                                        uint32_t& d2, uint32_t& d3, uint32_t addr) {
    asm volatile("ldmatrix.sync.aligned.m8n8.x4.shared.b16 {%0,%1,%2,%3}, [%4];"
                 : "=r"(d0), "=r"(d1), "=r"(d2), "=r"(d3) : "r"(addr));
}

__device__ __forceinline__ void ldsm_x4t(uint32_t& d0, uint32_t& d1,
                                         uint32_t& d2, uint32_t& d3, uint32_t addr) {
    asm volatile("ldmatrix.sync.aligned.m8n8.x4.trans.shared.b16 {%0,%1,%2,%3}, [%4];"
                 : "=r"(d0), "=r"(d1), "=r"(d2), "=r"(d3) : "r"(addr));
}

#define CP16(dst_u32, src_ptr) \
    asm volatile("cp.async.ca.shared.global [%0], [%1], 16;" \
                 :: "r"(dst_u32), "l"(src_ptr))
#define CP16Z(dst_u32, src_ptr, nbytes) \
    asm volatile("cp.async.ca.shared.global [%0], [%1], 16, %2;" \
                 :: "r"(dst_u32), "l"(src_ptr), "r"(nbytes))
#define CP_COMMIT() asm volatile("cp.async.commit_group;")
#define CP_WAIT(n)  asm volatile("cp.async.wait_group %0;" :: "n"(n))

// Map token row r (window-major) to element offset of its pixel row in x[4,224,224,256]
__device__ __forceinline__ int xrow_offset(int r) {
    int w   = r / 49;
    int t   = r - w * 49;
    int b   = w >> 10;
    int rem = w & 1023;
    int wh  = rem >> 5;
    int ww  = rem & 31;
    int i   = t / 7;
    int j   = t - i * 7;
    int row = (b * 224 + wh * 7 + i) * 224 + (ww * 7 + j);
    return row << 8;
}

// ===========================================================================
// Prep kernels
// ===========================================================================
__global__ void prep_xh(const float4* __restrict__ x4) {
    int idx = blockIdx.x * 256 + threadIdx.x;
    float4 v = x4[idx];
    ((uint2*)g_xh)[idx] = make_uint2(pack_half2(v.x, v.y), pack_half2(v.z, v.w));
}

__global__ void prep_wh(const float* __restrict__ w, int K, int N, int which) {
    __half* wT = which ? g_woutTh : g_wqkvTh;
    int idx = blockIdx.x * 256 + threadIdx.x;
    if (idx < K * N) {
        int k = idx / N;
        int n = idx - k * N;
        wT[(size_t)n * K + k] = __float2half_rn(w[idx]);
    }
}

__global__ void prep_bias(const float* __restrict__ bt) {
    int idx = blockIdx.x * 256 + threadIdx.x;   // 8*64*64
    int h = idx >> 12;
    int r = (idx >> 6) & 63;
    int c = idx & 63;
    float v;
    if (c >= 49)      v = -1e30f;
    else if (r >= 49) v = 0.f;
    else {
        int i1 = r / 7, j1 = r - i1 * 7;
        int i2 = c / 7, j2 = c - i2 * 7;
        v = bt[((i1 - i2 + 6) * 13 + (j1 - j2 + 6)) * 8 + h];
    }
    g_biasmat[idx] = v;
}

// ===========================================================================
// Fused K1+K2: per-CTA = (4 windows, 1 head).
// Phase A: qkv = gather(x) @ w_qkv[:, head-slices] + bias  (M=256,N=96,K=256)
//   W resident in full; B ldmatrix address advances by it*64 bytes per K-chunk.
// Phase B: windowed attention on the smem-resident q/k/v, write g_atth.
//
// smem layout (bytes):
//   W     [96][264]h   @ 0       (50688)
//   Abuf  2x[256][40]h @ 50688   (2 x 20480)
//   QKV   [256][104]h  @ 50688   (53248)  -- reuses Abuf region after GEMM
//   arow  int[256]     @ 104448
// ===========================================================================
#define FUSED_SMEM 105472
#define OFF_W   0
#define OFF_AB  50688
#define OFF_QKV 50688
#define OFF_AROW 104448

__global__ __launch_bounds__(256, 1)
void qkv_attn(const float* __restrict__ bqkv)
{
    extern __shared__ char smem[];
    const uint32_t sbase = smem_u32(smem);
    int* arow = (int*)(smem + OFF_AROW);

    const int tid  = threadIdx.x;
    const int wid  = tid >> 5;
    const int lane = tid & 31;
    const int h    = blockIdx.x;        // head
    const int wg   = blockIdx.y;        // window group (4 windows)
    const int r0   = lane >> 2;
    const int kc   = lane & 3;
    const int lj   = lane >> 3;
    const int lq   = lane & 7;

    // token-row table: local row -> g_xh offset, or -1 for pad
    if (tid < 256) {
        int aw = tid >> 6, t = tid & 63;
        arow[tid] = (t < 49) ? xrow_offset((wg * 4 + aw) * 49 + t) : -1;
    }

    // ---- weight slice load: 96 rows x 256 halves -> W[96][264] ----
    #pragma unroll
    for (int i = 0; i < 12; i++) {
        int f   = tid + i * 256;
        int row = f >> 5;                 // 0..95
        int q8  = (f & 31) << 3;          // 0..248
        int sec = row >> 5;
        int gn  = sec * 256 + h * 32 + (row & 31);
        CP16(sbase + OFF_W + (uint32_t)(row * 528 + q8 * 2),
             g_wqkvTh + (size_t)gn * 256 + q8);
    }
    CP_COMMIT();

    __syncthreads();   // arow visible for A loads

    // ---- GEMM: warp (my, nx), warp tile 64 x 48 ----
    const int my = wid >> 1;
    const int nx = wid & 1;
    const int wm = my * 64;
    const int wn = nx * 48;

    const uint32_t a_off = (uint32_t)((wm + ((lj & 1) << 3) + lq) * 80 + ((lj >> 1) << 4));
    const uint32_t b_off = OFF_W + (uint32_t)((wn + (((lj >> 1) & 1) << 3) + lq) * 528 + ((lj & 1) << 4));

    float acc[4][6][4];
    #pragma unroll
    for (int i = 0; i < 4; i++)
        #pragma unroll
        for (int j = 0; j < 6; j++)
            #pragma unroll
            for (int q = 0; q < 4; q++) acc[i][j][q] = 0.f;

    // A-load slots: 1024 16B ops / 256 thr = 4
    int lrow[4], lq8[4], lsz[4];
    const __half* lsrc[4];
    #pragma unroll
    for (int i = 0; i < 4; i++) {
        int f = tid + i * 256;
        lrow[i] = f >> 2;
        lq8[i]  = (f & 3) << 3;
        int ar  = arow[lrow[i]];
        lsz[i]  = (ar >= 0) ? 16 : 0;
        lsrc[i] = g_xh + ((ar >= 0) ? ar : 0) + lq8[i];
    }

    // prologue: A buffer 0, kt=0
    #pragma unroll
    for (int i = 0; i < 4; i++)
        CP16Z(sbase + OFF_AB + (uint32_t)(lrow[i] * 80 + lq8[i] * 2), lsrc[i], lsz[i]);
    CP_COMMIT();

    #pragma unroll
    for (int it = 0; it < 8; it++) {
        if (it < 7) {
            uint32_t bo = OFF_AB + (uint32_t)(((it + 1) & 1) * 20480);
            int kt = (it + 1) * 32;
            #pragma unroll
            for (int i = 0; i < 4; i++)
                CP16Z(bo + sbase + (uint32_t)(lrow[i] * 80 + lq8[i] * 2), lsrc[i] + kt, lsz[i]);
            CP_COMMIT();
            CP_WAIT(1);
        } else {
            CP_WAIT(0);
        }
        __syncthreads();

        const uint32_t abuf = sbase + OFF_AB + (uint32_t)((it & 1) * 20480);
        const uint32_t bkof = (uint32_t)(it * 64);   // <-- FIX: advance B by 32 halves per K-chunk

        #pragma unroll
        for (int k16 = 0; k16 < 32; k16 += 16) {
            uint32_t a[4][4], b2[3][4];
            #pragma unroll
            for (int im = 0; im < 4; im++)
                ldsm_x4(a[im][0], a[im][1], a[im][2], a[im][3],
                        abuf + a_off + (uint32_t)(im * 1280 + k16 * 2));
            #pragma unroll
            for (int g = 0; g < 3; g++)
                ldsm_x4(b2[g][0], b2[g][1], b2[g][2], b2[g][3],
                        sbase + b_off + bkof + (uint32_t)(g * 8448 + k16 * 2));
            #pragma unroll
            for (int im = 0; im < 4; im++)
                #pragma unroll
                for (int in_ = 0; in_ < 6; in_++)
                    mma16(acc[im][in_], a[im][0], a[im][1], a[im][2], a[im][3],
                          b2[in_ >> 1][(in_ & 1) << 1], b2[in_ >> 1][((in_ & 1) << 1) + 1]);
        }
        __syncthreads();
    }

    // ---- epilogue: +bias, q-scale, store fp16 into QKV[256][104] ----
    float bias0[6], bias1[6], scl[6];
    #pragma unroll
    for (int in_ = 0; in_ < 6; in_++) {
        int col = wn + in_ * 8 + kc * 2;
        int sec = col >> 5;
        bias0[in_] = bqkv[sec * 256 + h * 32 + (col & 31)];
        bias1[in_] = bqkv[sec * 256 + h * 32 + ((col + 1) & 31)];
        scl[in_]   = (sec == 0) ? 0.5f : 1.0f;
    }
    const uint32_t qkvb = sbase + OFF_QKV;
    #pragma unroll
    for (int im = 0; im < 4; im++) {
        int r_lo = wm + im * 16 + r0;
        #pragma unroll
        for (int in_ = 0; in_ < 6; in_++) {
            int colb = (wn + in_ * 8 + kc * 2) * 2;
            *(uint32_t*)(smem + OFF_QKV + r_lo * 208 + colb) =
                pack_half2((acc[im][in_][0] + bias0[in_]) * scl[in_],
                           (acc[im][in_][1] + bias1[in_]) * scl[in_]);
            *(uint32_t*)(smem + OFF_QKV + (r_lo + 8) * 208 + colb) =
                pack_half2((acc[im][in_][2] + bias0[in_]) * scl[in_],
                           (acc[im][in_][3] + bias1[in_]) * scl[in_]);
        }
    }
    __syncthreads();

    // ================= Phase B: attention =================
    const int aw    = wid >> 1;           // window 0..3
    const int ah    = wid & 1;            // row half
    const int wbase = aw * 64;
    const int base  = wbase + ah * 32;

    const uint32_t qa_off = (uint32_t)((base + ((lj & 1) << 3) + lq) * 208 + ((lj >> 1) << 4));
    const uint32_t kb_off = (uint32_t)((wbase + (((lj >> 1) & 1) << 3) + lq) * 208 + 64 + ((lj & 1) << 4));

    // S = Q @ K^T : warp tile 32 x 64
    float c[2][8][4];
    #pragma unroll
    for (int im = 0; im < 2; im++)
        #pragma unroll
        for (int nt = 0; nt < 8; nt++)
            #pragma unroll
            for (int q = 0; q < 4; q++) c[im][nt][q] = 0.f;

    #pragma unroll
    for (int k16 = 0; k16 < 32; k16 += 16) {
        uint32_t a[2][4];
        #pragma unroll
        for (int im = 0; im < 2; im++)
            ldsm_x4(a[im][0], a[im][1], a[im][2], a[im][3],
                    qkvb + qa_off + (uint32_t)(im * 3328 + k16 * 2));
        #pragma unroll
        for (int g = 0; g < 4; g++) {
            uint32_t b0, b1, b2, b3;
            ldsm_x4(b0, b1, b2, b3, qkvb + kb_off + (uint32_t)(g * 3328 + k16 * 2));
            #pragma unroll
            for (int im = 0; im < 2; im++) {
                mma16(c[im][2 * g],     a[im][0], a[im][1], a[im][2], a[im][3], b0, b1);
                mma16(c[im][2 * g + 1], a[im][0], a[im][1], a[im][2], a[im][3], b2, b3);
            }
        }
    }

    // bias (pre-masked) + register softmax
    #pragma unroll
    for (int im = 0; im < 2; im++) {
        #pragma unroll
        for (int half_ = 0; half_ < 2; half_++) {
            int qrow = ah * 32 + im * 16 + r0 + half_ * 8;
            const float* bmr = g_biasmat + h * 4096 + qrow * 64;
            #pragma unroll
            for (int nt = 0; nt < 8; nt++) {
                float2 bv = *(const float2*)(bmr + nt * 8 + 2 * kc);
                c[im][nt][half_ * 2 + 0] += bv.x;
                c[im][nt][half_ * 2 + 1] += bv.y;
            }
            float mx = -1e30f;
            #pragma unroll
            for (int nt = 0; nt < 8; nt++) {
                mx = fmaxf(mx, c[im][nt][half_ * 2]);
                mx = fmaxf(mx, c[im][nt][half_ * 2 + 1]);
            }
            mx = fmaxf(mx, __shfl_xor_sync(0xffffffffu, mx, 1));
            mx = fmaxf(mx, __shfl_xor_sync(0xffffffffu, mx, 2));
            float s = 0.f;
            #pragma unroll
            for (int nt = 0; nt < 8; nt++) {
                #pragma unroll
                for (int e = 0; e < 2; e++) {
                    float p = __expf(c[im][nt][half_ * 2 + e] - mx);
                    c[im][nt][half_ * 2 + e] = p;
                    s += p;
                }
            }
            s += __shfl_xor_sync(0xffffffffu, s, 1);
            s += __shfl_xor_sync(0xffffffffu, s, 2);
            float inv = 1.0f / s;
            #pragma unroll
            for (int nt = 0; nt < 8; nt++) {
                c[im][nt][half_ * 2 + 0] *= inv;
                c[im][nt][half_ * 2 + 1] *= inv;
            }
        }
    }

    // O = P @ V : V^T B-frags via ldmatrix.trans on v slice [t][d]
    float o[2][4][4];
    #pragma unroll
    for (int im = 0; im < 2; im++)
        #pragma unroll
        for (int jn = 0; jn < 4; jn++)
            #pragma unroll
            for (int q = 0; q < 4; q++) o[im][jn][q] = 0.f;

    const uint32_t vb_off = (uint32_t)((wbase + ((lj & 1) << 3) + lq) * 208 + 128 + ((lj >> 1) << 4));

    #pragma unroll
    for (int kt = 0; kt < 4; kt++) {
        uint32_t vb[2][4];
        #pragma unroll
        for (int g = 0; g < 2; g++)
            ldsm_x4t(vb[g][0], vb[g][1], vb[g][2], vb[g][3],
                     qkvb + vb_off + (uint32_t)(kt * 16 * 208 + g * 32));
        #pragma unroll
        for (int im = 0; im < 2; im++) {
            uint32_t a0 = pack_half2(c[im][2 * kt][0],     c[im][2 * kt][1]);
            uint32_t a1 = pack_half2(c[im][2 * kt][2],     c[im][2 * kt][3]);
            uint32_t a2 = pack_half2(c[im][2 * kt + 1][0], c[im][2 * kt + 1][1]);
            uint32_t a3 = pack_half2(c[im][2 * kt + 1][2], c[im][2 * kt + 1][3]);
            #pragma unroll
            for (int g = 0; g < 2; g++) {
                mma16(o[im][2 * g],     a0, a1, a2, a3, vb[g][0], vb[g][1]);
                mma16(o[im][2 * g + 1], a0, a1, a2, a3, vb[g][2], vb[g][3]);
            }
        }
    }

    // store O
    const int win = wg * 4 + aw;
    #pragma unroll
    for (int im = 0; im < 2; im++) {
        #pragma unroll
        for (int half_ = 0; half_ < 2; half_++) {
            int t_ = ah * 32 + im * 16 + r0 + half_ * 8;
            if (t_ < 49) {
                __half* op = g_atth + ((size_t)win * 49 + t_) * 256 + h * 32;
                #pragma unroll
                for (int jn = 0; jn < 4; jn++)
                    *(uint32_t*)(op + jn * 8 + 2 * kc) =
                        pack_half2(o[im][jn][half_ * 2 + 0], o[im][jn][half_ * 2 + 1]);
            }
        }
    }
}

// ===========================================================================
// K3: out = LN(g_att @ w_out + b_out + gather(x))  fp16 mma + ldmatrix
// CTA 128x256 (full rows), BK=32, 8 warps (2m x 4n), warp tile 64x64.
// ===========================================================================
#define K3_SMEM 62976
__global__ __launch_bounds__(256, 1)
void out_mma(const float* __restrict__ x,
             const float* __restrict__ bout,
             const float* __restrict__ gamma,
             const float* __restrict__ beta,
             float* __restrict__ out)
{
    extern __shared__ char smem[];
    const uint32_t sbase = smem_u32(smem);
    int*   arow = (int*)(smem + 61440);
    float* s1   = (float*)(smem + 61952);
    float* s2   = (float*)(smem + 62464);

    const int tid  = threadIdx.x;
    const int wid  = tid >> 5;
    const int lane = tid & 31;
    const int m0   = blockIdx.x * 128;
    if (tid < 128) { arow[tid] = xrow_offset(m0 + tid); s1[tid] = 0.f; s2[tid] = 0.f; }

    const int wm = (wid >> 2) * 64;
    const int wn = (wid & 3) * 64;
    const int r0 = lane >> 2;
    const int kc = lane & 3;
    const int lj = lane >> 3;
    const int lq = lane & 7;

    const uint32_t a_off = (uint32_t)((wm + ((lj & 1) << 3) + lq) * 80 + ((lj >> 1) << 4));
    const uint32_t b_off = 10240u + (uint32_t)((wn + (((lj >> 1) & 1) << 3) + lq) * 80 + ((lj & 1) << 4));

    float acc[4][8][4];
    #pragma unroll
    for (int i = 0; i < 4; i++)
        #pragma unroll
        for (int j = 0; j < 8; j++)
            #pragma unroll
            for (int q = 0; q < 4; q++) acc[i][j][q] = 0.f;

    __syncthreads();

    #pragma unroll
    for (int i = 0; i < 2; i++) {
        int f = tid + i * 256;
        int r = f >> 2, q8 = (f & 3) << 3;
        CP16(sbase + (uint32_t)(r * 80 + q8 * 2), g_atth + (size_t)(m0 + r) * 256 + q8);
    }
    #pragma unroll
    for (int i = 0; i < 4; i++) {
        int f = tid + i * 256;
        int r = f >> 2, q8 = (f & 3) << 3;
        CP16(sbase + 10240 + (uint32_t)(r * 80 + q8 * 2), g_woutTh + (size_t)r * 256 + q8);
    }
    CP_COMMIT();

    #pragma unroll
    for (int it = 0; it < 8; it++) {
        if (it < 7) {
            uint32_t bo = (uint32_t)(((it + 1) & 1) * 30720);
            int kt = (it + 1) * 32;
            #pragma unroll
            for (int i = 0; i < 2; i++) {
                int f = tid + i * 256;
                int r = f >> 2, q8 = (f & 3) << 3;
                CP16(sbase + bo + (uint32_t)(r * 80 + q8 * 2),
                     g_atth + (size_t)(m0 + r) * 256 + kt + q8);
            }
            #pragma unroll
            for (int i = 0; i < 4; i++) {
                int f = tid + i * 256;
                int r = f >> 2, q8 = (f & 3) << 3;
                CP16(sbase + bo + 10240 + (uint32_t)(r * 80 + q8 * 2),
                     g_woutTh + (size_t)r * 256 + kt + q8);
            }
            CP_COMMIT();
            CP_WAIT(1);
        } else {
            CP_WAIT(0);
        }
        __syncthreads();

        const uint32_t bufb = sbase + (uint32_t)((it & 1) * 30720);

        #pragma unroll
        for (int k16 = 0; k16 < 32; k16 += 16) {
            uint32_t a[4][4], b2[4][4];
            #pragma unroll
            for (int im = 0; im < 4; im++)
                ldsm_x4(a[im][0], a[im][1], a[im][2], a[im][3],
                        bufb + a_off + (uint32_t)(im * 1280 + k16 * 2));
            #pragma unroll
            for (int g = 0; g < 4; g++)
                ldsm_x4(b2[g][0], b2[g][1], b2[g][2], b2[g][3],
                        bufb + b_off + (uint32_t)(g * 1280 + k16 * 2));
            #pragma unroll
            for (int im = 0; im < 4; im++)
                #pragma unroll
                for (int in_ = 0; in_ < 8; in_++)
                    mma16(acc[im][in_], a[im][0], a[im][1], a[im][2], a[im][3],
                          b2[in_ >> 1][(in_ & 1) << 1], b2[in_ >> 1][((in_ & 1) << 1) + 1]);
        }
        __syncthreads();
    }

    // ---- epilogue: y = acc + bias + residual(fp32); LN over full rows ----
    #pragma unroll
    for (int im = 0; im < 4; im++) {
        #pragma unroll
        for (int half_ = 0; half_ < 2; half_++) {
            int rl = wm + im * 16 + r0 + half_ * 8;
            const float* xr = x + arow[rl];
            float p1 = 0.f, p2 = 0.f;
            #pragma unroll
            for (int in_ = 0; in_ < 8; in_++) {
                int c = wn + in_ * 8 + kc * 2;
                float2 xv = *(const float2*)(xr + c);
                float y0 = acc[im][in_][half_ * 2 + 0] + bout[c]     + xv.x;
                float y1 = acc[im][in_][half_ * 2 + 1] + bout[c + 1] + xv.y;
                acc[im][in_][half_ * 2 + 0] = y0;
                acc[im][in_][half_ * 2 + 1] = y1;
                p1 += y0 + y1;
                p2 += y0 * y0 + y1 * y1;
            }
            p1 += __shfl_xor_sync(0xffffffffu, p1, 1);
            p2 += __shfl_xor_sync(0xffffffffu, p2, 1);
            p1 += __shfl_xor_sync(0xffffffffu, p1, 2);
            p2 += __shfl_xor_sync(0xffffffffu, p2, 2);
            if (kc == 0) {
                atomicAdd(&s1[rl], p1);
                atomicAdd(&s2[rl], p2);
            }
        }
    }
    __syncthreads();

    #pragma unroll
    for (int im = 0; im < 4; im++) {
        #pragma unroll
        for (int half_ = 0; half_ < 2; half_++) {
            int rl = wm + im * 16 + r0 + half_ * 8;
            int m  = m0 + rl;
            float mean = s1[rl] * (1.0f / 256.0f);
            float var  = s2[rl] * (1.0f / 256.0f) - mean * mean;
            float rstd = rsqrtf(var + 1e-5f);
            #pragma unroll
            for (int in_ = 0; in_ < 8; in_++) {
                int c = wn + in_ * 8 + kc * 2;
                float y0 = acc[im][in_][half_ * 2 + 0];
                float y1 = acc[im][in_][half_ * 2 + 1];
                float2 o = make_float2((y0 - mean) * rstd * gamma[c]     + beta[c],
                                       (y1 - mean) * rstd * gamma[c + 1] + beta[c + 1]);
                *(float2*)(out + (size_t)m * 256 + c) = o;
            }
        }
    }
}

// ===========================================================================
extern "C" void kernel_launch(void* const* d_in, const int* in_sizes, int n_in,
                              void* d_out, int out_size)
{
    const float* x          = (const float*)d_in[0];
    const float* w_qkv      = (const float*)d_in[1];
    const float* b_qkv      = (const float*)d_in[2];
    const float* bias_table = (const float*)d_in[3];
    const float* w_out      = (const float*)d_in[4];
    const float* b_out      = (const float*)d_in[5];
    const float* ln_gamma   = (const float*)d_in[6];
    const float* ln_beta    = (const float*)d_in[7];
    float* out = (float*)d_out;

    cudaFuncSetAttribute(qkv_attn, cudaFuncAttributeMaxDynamicSharedMemorySize, FUSED_SMEM);
    cudaFuncSetAttribute(out_mma, cudaFuncAttributeMaxDynamicSharedMemorySize, K3_SMEM);

    prep_xh<<<50176, 256>>>((const float4*)x);
    prep_wh<<<(256 * 768 + 255) / 256, 256>>>(w_qkv, 256, 768, 0);
    prep_wh<<<(256 * 256 + 255) / 256, 256>>>(w_out, 256, 256, 1);
    prep_bias<<<128, 256>>>(bias_table);
    qkv_attn<<<dim3(HEADS, NWIN / 4), 256, FUSED_SMEM>>>(b_qkv);
    out_mma<<<1568, 256, K3_SMEM>>>(x, b_out, ln_gamma, ln_beta, out);
}

// round 9
// speedup vs baseline: 5.1275x; 1.0840x over previous
#include <cuda_runtime.h>
#include <cuda_fp16.h>
#include <cstdint>

#define MTOT  200704
#define NWIN  4096
#define HEADS 8

// Scratch (device globals; no cudaMalloc allowed)
__device__ __half g_xh   [51380224];    // x converted to fp16
__device__ __half g_atth [51380224];    // [MTOT][256] fp16
__device__ __half g_wqkvTh[768 * 256];  // w_qkv^T [N][K] fp16
__device__ __half g_woutTh[256 * 256];  // w_out^T [N][K] fp16
__device__ float  g_biasmat[8 * 64 * 64]; // per-head bias matrix, masked

// ===========================================================================
// Helpers
// ===========================================================================
__device__ __forceinline__ uint32_t smem_u32(const void* p) {
    uint32_t a;
    asm("{ .reg .u64 t; cvta.to.shared.u64 t, %1; cvt.u32.u64 %0, t; }"
        : "=r"(a) : "l"(p));
    return a;
}

__device__ __forceinline__ uint32_t pack_half2(float a, float b) {
    __half2 h = __floats2half2_rn(a, b);
    return *(uint32_t*)&h;
}

// m16n8k16 fp16 MMA, fp32 accumulate
__device__ __forceinline__ void mma16(float d[4],
                                      uint32_t a0, uint32_t a1, uint32_t a2, uint32_t a3,
                                      uint32_t b0, uint32_t b1) {
    asm volatile(
        "mma.sync.aligned.m16n8k16.row.col.f32.f16.f16.f32 "
        "{%0,%1,%2,%3}, {%4,%5,%6,%7}, {%8,%9}, {%0,%1,%2,%3};"
        : "+f"(d[0]), "+f"(d[1]), "+f"(d[2]), "+f"(d[3])
        : "r"(a0), "r"(a1), "r"(a2), "r"(a3), "r"(b0), "r"(b1));
}

__device__ __forceinline__ void ldsm_x4(uint32_t& d0, uint32_t& d1,
                                        uint32_t& d2, uint32_t& d3, uint32_t addr) {
    asm volatile("ldmatrix.sync.aligned.m8n8.x4.shared.b16 {%0,%1,%2,%3}, [%4];"
                 : "=r"(d0), "=r"(d1), "=r"(d2), "=r"(d3) : "r"(addr));
}

__device__ __forceinline__ void ldsm_x4t(uint32_t& d0, uint32_t& d1,
                                         uint32_t& d2, uint32_t& d3, uint32_t addr) {
    asm volatile("ldmatrix.sync.aligned.m8n8.x4.trans.shared.b16 {%0,%1,%2,%3}, [%4];"
                 : "=r"(d0), "=r"(d1), "=r"(d2), "=r"(d3) : "r"(addr));
}

#define CP16(dst_u32, src_ptr) \
    asm volatile("cp.async.ca.shared.global [%0], [%1], 16;" \
                 :: "r"(dst_u32), "l"(src_ptr))
#define CP16Z(dst_u32, src_ptr, nbytes) \
    asm volatile("cp.async.ca.shared.global [%0], [%1], 16, %2;" \
                 :: "r"(dst_u32), "l"(src_ptr), "r"(nbytes))
#define CP_COMMIT() asm volatile("cp.async.commit_group;")
#define CP_WAIT(n)  asm volatile("cp.async.wait_group %0;" :: "n"(n))

// Map token row r (window-major) to element offset of its pixel row in x[4,224,224,256]
__device__ __forceinline__ int xrow_offset(int r) {
    int w   = r / 49;
    int t   = r - w * 49;
    int b   = w >> 10;
    int rem = w & 1023;
    int wh  = rem >> 5;
    int ww  = rem & 31;
    int i   = t / 7;
    int j   = t - i * 7;
    int row = (b * 224 + wh * 7 + i) * 224 + (ww * 7 + j);
    return row << 8;
}

// ===========================================================================
// Prep kernels
// ===========================================================================
__global__ void prep_xh(const float4* __restrict__ x4) {
    int idx = blockIdx.x * 256 + threadIdx.x;
    float4 v = x4[idx];
    ((uint2*)g_xh)[idx] = make_uint2(pack_half2(v.x, v.y), pack_half2(v.z, v.w));
}

__global__ void prep_wh(const float* __restrict__ w, int K, int N, int which) {
    __half* wT = which ? g_woutTh : g_wqkvTh;
    int idx = blockIdx.x * 256 + threadIdx.x;
    if (idx < K * N) {
        int k = idx / N;
        int n = idx - k * N;
        wT[(size_t)n * K + k] = __float2half_rn(w[idx]);
    }
}

__global__ void prep_bias(const float* __restrict__ bt) {
    int idx = blockIdx.x * 256 + threadIdx.x;   // 8*64*64
    int h = idx >> 12;
    int r = (idx >> 6) & 63;
    int c = idx & 63;
    float v;
    if (c >= 49)      v = -1e30f;
    else if (r >= 49) v = 0.f;
    else {
        int i1 = r / 7, j1 = r - i1 * 7;
        int i2 = c / 7, j2 = c - i2 * 7;
        v = bt[((i1 - i2 + 6) * 13 + (j1 - j2 + 6)) * 8 + h];
    }
    g_biasmat[idx] = v;
}

// ===========================================================================
// Fused K1+K2: per-CTA = (2 windows, 1 head). Occupancy 2.
// Phase A: qkv = gather(x) @ w_qkv[:, head-slices] + bias  (M=128,N=96,K=256)
// Phase B: windowed attention on smem-resident q/k/v, write g_atth.
//
// smem layout (bytes):
//   W     [96][264]h   @ 0       (50688)
//   Abuf  2x[128][40]h @ 50688   (2 x 10240)
//   QKV   [128][104]h  @ 50688   (26624)  -- aliases Abuf after GEMM
//   arow  int[128]     @ 77312
// total 77824
// ===========================================================================
#define FUSED_SMEM 77824
#define OFF_W    0
#define OFF_AB   50688
#define OFF_QKV  50688
#define OFF_AROW 77312

__global__ __launch_bounds__(256, 2)
void qkv_attn(const float* __restrict__ bqkv)
{
    extern __shared__ char smem[];
    const uint32_t sbase = smem_u32(smem);
    int* arow = (int*)(smem + OFF_AROW);

    const int tid  = threadIdx.x;
    const int wid  = tid >> 5;
    const int lane = tid & 31;
    const int h    = blockIdx.x;        // head
    const int wg   = blockIdx.y;        // window pair
    const int r0   = lane >> 2;
    const int kc   = lane & 3;
    const int lj   = lane >> 3;
    const int lq   = lane & 7;

    // token-row table: local row -> g_xh offset, or -1 for pad
    if (tid < 128) {
        int aw = tid >> 6, t = tid & 63;
        arow[tid] = (t < 49) ? xrow_offset((wg * 2 + aw) * 49 + t) : -1;
    }

    // ---- weight slice load: 96 rows x 256 halves -> W[96][264] ----
    #pragma unroll
    for (int i = 0; i < 12; i++) {
        int f   = tid + i * 256;
        int row = f >> 5;                 // 0..95
        int q8  = (f & 31) << 3;          // 0..248
        int sec = row >> 5;
        int gn  = sec * 256 + h * 32 + (row & 31);
        CP16(sbase + OFF_W + (uint32_t)(row * 528 + q8 * 2),
             g_wqkvTh + (size_t)gn * 256 + q8);
    }
    CP_COMMIT();

    __syncthreads();   // arow visible

    // ---- GEMM: 8 warps = 4m x 2n, warp tile 32 x 48 ----
    const int my = wid >> 1;
    const int nx = wid & 1;
    const int wm = my * 32;
    const int wn = nx * 48;

    const uint32_t a_off = (uint32_t)((wm + ((lj & 1) << 3) + lq) * 80 + ((lj >> 1) << 4));
    const uint32_t b_off = OFF_W + (uint32_t)((wn + (((lj >> 1) & 1) << 3) + lq) * 528 + ((lj & 1) << 4));

    float acc[2][6][4];
    #pragma unroll
    for (int i = 0; i < 2; i++)
        #pragma unroll
        for (int j = 0; j < 6; j++)
            #pragma unroll
            for (int q = 0; q < 4; q++) acc[i][j][q] = 0.f;

    // A-load slots: 512 16B ops / 256 thr = 2
    int lrow[2], lq8[2], lsz[2];
    const __half* lsrc[2];
    #pragma unroll
    for (int i = 0; i < 2; i++) {
        int f = tid + i * 256;
        lrow[i] = f >> 2;
        lq8[i]  = (f & 3) << 3;
        int ar  = arow[lrow[i]];
        lsz[i]  = (ar >= 0) ? 16 : 0;
        lsrc[i] = g_xh + ((ar >= 0) ? ar : 0) + lq8[i];
    }

    // prologue: A buffer 0, kt=0
    #pragma unroll
    for (int i = 0; i < 2; i++)
        CP16Z(sbase + OFF_AB + (uint32_t)(lrow[i] * 80 + lq8[i] * 2), lsrc[i], lsz[i]);
    CP_COMMIT();

    #pragma unroll
    for (int it = 0; it < 8; it++) {
        if (it < 7) {
            uint32_t bo = OFF_AB + (uint32_t)(((it + 1) & 1) * 10240);
            int kt = (it + 1) * 32;
            #pragma unroll
            for (int i = 0; i < 2; i++)
                CP16Z(bo + sbase + (uint32_t)(lrow[i] * 80 + lq8[i] * 2), lsrc[i] + kt, lsz[i]);
            CP_COMMIT();
            CP_WAIT(1);
        } else {
            CP_WAIT(0);
        }
        __syncthreads();

        const uint32_t abuf = sbase + OFF_AB + (uint32_t)((it & 1) * 10240);
        const uint32_t bkof = (uint32_t)(it * 64);   // advance B by 32 halves per K-chunk

        #pragma unroll
        for (int k16 = 0; k16 < 32; k16 += 16) {
            uint32_t a[2][4], b2[3][4];
            #pragma unroll
            for (int im = 0; im < 2; im++)
                ldsm_x4(a[im][0], a[im][1], a[im][2], a[im][3],
                        abuf + a_off + (uint32_t)(im * 1280 + k16 * 2));
            #pragma unroll
            for (int g = 0; g < 3; g++)
                ldsm_x4(b2[g][0], b2[g][1], b2[g][2], b2[g][3],
                        sbase + b_off + bkof + (uint32_t)(g * 8448 + k16 * 2));
            #pragma unroll
            for (int im = 0; im < 2; im++)
                #pragma unroll
                for (int in_ = 0; in_ < 6; in_++)
                    mma16(acc[im][in_], a[im][0], a[im][1], a[im][2], a[im][3],
                          b2[in_ >> 1][(in_ & 1) << 1], b2[in_ >> 1][((in_ & 1) << 1) + 1]);
        }
        __syncthreads();
    }

    // ---- epilogue: +bias, q-scale, store fp16 into QKV[128][104] ----
    float bias0[6], bias1[6], scl[6];
    #pragma unroll
    for (int in_ = 0; in_ < 6; in_++) {
        int col = wn + in_ * 8 + kc * 2;
        int sec = col >> 5;
        bias0[in_] = bqkv[sec * 256 + h * 32 + (col & 31)];
        bias1[in_] = bqkv[sec * 256 + h * 32 + ((col + 1) & 31)];
        scl[in_]   = (sec == 0) ? 0.5f : 1.0f;
    }
    const uint32_t qkvb = sbase + OFF_QKV;
    #pragma unroll
    for (int im = 0; im < 2; im++) {
        int r_lo = wm + im * 16 + r0;
        #pragma unroll
        for (int in_ = 0; in_ < 6; in_++) {
            int colb = (wn + in_ * 8 + kc * 2) * 2;
            *(uint32_t*)(smem + OFF_QKV + r_lo * 208 + colb) =
                pack_half2((acc[im][in_][0] + bias0[in_]) * scl[in_],
                           (acc[im][in_][1] + bias1[in_]) * scl[in_]);
            *(uint32_t*)(smem + OFF_QKV + (r_lo + 8) * 208 + colb) =
                pack_half2((acc[im][in_][2] + bias0[in_]) * scl[in_],
                           (acc[im][in_][3] + bias1[in_]) * scl[in_]);
        }
    }
    __syncthreads();

    // ================= Phase B: attention =================
    // 8 warps: aw = window (0/1), rq = row quarter (0..3); warp owns 16 Q rows.
    const int aw    = wid >> 2;
    const int rq    = wid & 3;
    const int wbase = aw * 64;
    const int base  = wbase + rq * 16;

    const uint32_t qa_off = (uint32_t)((base + ((lj & 1) << 3) + lq) * 208 + ((lj >> 1) << 4));
    const uint32_t kb_off = (uint32_t)((wbase + (((lj >> 1) & 1) << 3) + lq) * 208 + 64 + ((lj & 1) << 4));

    // S = Q @ K^T : warp tile 16 x 64
    float c[8][4];
    #pragma unroll
    for (int nt = 0; nt < 8; nt++)
        #pragma unroll
        for (int q = 0; q < 4; q++) c[nt][q] = 0.f;

    #pragma unroll
    for (int k16 = 0; k16 < 32; k16 += 16) {
        uint32_t a0, a1, a2, a3;
        ldsm_x4(a0, a1, a2, a3, qkvb + qa_off + (uint32_t)(k16 * 2));
        #pragma unroll
        for (int g = 0; g < 4; g++) {
            uint32_t b0, b1, b2, b3;
            ldsm_x4(b0, b1, b2, b3, qkvb + kb_off + (uint32_t)(g * 3328 + k16 * 2));
            mma16(c[2 * g],     a0, a1, a2, a3, b0, b1);
            mma16(c[2 * g + 1], a0, a1, a2, a3, b2, b3);
        }
    }

    // bias (pre-masked) + register softmax
    #pragma unroll
    for (int half_ = 0; half_ < 2; half_++) {
        int qrow = rq * 16 + r0 + half_ * 8;     // within-window row 0..63
        const float* bmr = g_biasmat + h * 4096 + qrow * 64;
        #pragma unroll
        for (int nt = 0; nt < 8; nt++) {
            float2 bv = *(const float2*)(bmr + nt * 8 + 2 * kc);
            c[nt][half_ * 2 + 0] += bv.x;
            c[nt][half_ * 2 + 1] += bv.y;
        }
        float mx = -1e30f;
        #pragma unroll
        for (int nt = 0; nt < 8; nt++) {
            mx = fmaxf(mx, c[nt][half_ * 2]);
            mx = fmaxf(mx, c[nt][half_ * 2 + 1]);
        }
        mx = fmaxf(mx, __shfl_xor_sync(0xffffffffu, mx, 1));
        mx = fmaxf(mx, __shfl_xor_sync(0xffffffffu, mx, 2));
        float s = 0.f;
        #pragma unroll
        for (int nt = 0; nt < 8; nt++) {
            #pragma unroll
            for (int e = 0; e < 2; e++) {
                float p = __expf(c[nt][half_ * 2 + e] - mx);
                c[nt][half_ * 2 + e] = p;
                s += p;
            }
        }
        s += __shfl_xor_sync(0xffffffffu, s, 1);
        s += __shfl_xor_sync(0xffffffffu, s, 2);
        float inv = 1.0f / s;
        #pragma unroll
        for (int nt = 0; nt < 8; nt++) {
            c[nt][half_ * 2 + 0] *= inv;
            c[nt][half_ * 2 + 1] *= inv;
        }
    }

    // O = P @ V : V^T B-frags via ldmatrix.trans on v slice [t][d]
    float o[4][4];
    #pragma unroll
    for (int jn = 0; jn < 4; jn++)
        #pragma unroll
        for (int q = 0; q < 4; q++) o[jn][q] = 0.f;

    const uint32_t vb_off = (uint32_t)((wbase + ((lj & 1) << 3) + lq) * 208 + 128 + ((lj >> 1) << 4));

    #pragma unroll
    for (int kt = 0; kt < 4; kt++) {
        uint32_t vb[2][4];
        #pragma unroll
        for (int g = 0; g < 2; g++)
            ldsm_x4t(vb[g][0], vb[g][1], vb[g][2], vb[g][3],
                     qkvb + vb_off + (uint32_t)(kt * 16 * 208 + g * 32));
        uint32_t a0 = pack_half2(c[2 * kt][0],     c[2 * kt][1]);
        uint32_t a1 = pack_half2(c[2 * kt][2],     c[2 * kt][3]);
        uint32_t a2 = pack_half2(c[2 * kt + 1][0], c[2 * kt + 1][1]);
        uint32_t a3 = pack_half2(c[2 * kt + 1][2], c[2 * kt + 1][3]);
        #pragma unroll
        for (int g = 0; g < 2; g++) {
            mma16(o[2 * g],     a0, a1, a2, a3, vb[g][0], vb[g][1]);
            mma16(o[2 * g + 1], a0, a1, a2, a3, vb[g][2], vb[g][3]);
        }
    }

    // store O
    const int win = wg * 2 + aw;
    #pragma unroll
    for (int half_ = 0; half_ < 2; half_++) {
        int t_ = rq * 16 + r0 + half_ * 8;
        if (t_ < 49) {
            __half* op = g_atth + ((size_t)win * 49 + t_) * 256 + h * 32;
            #pragma unroll
            for (int jn = 0; jn < 4; jn++)
                *(uint32_t*)(op + jn * 8 + 2 * kc) =
                    pack_half2(o[jn][half_ * 2 + 0], o[jn][half_ * 2 + 1]);
        }
    }
}

// ===========================================================================
// K3: out = LN(g_att @ w_out + b_out + gather(x))  fp16 mma + ldmatrix
// CTA 64x256 (full rows), BK=32, 8 warps (2m x 4n), warp tile 32x64. Occ 2.
// smem: buf{0,1}: A[64][40]h (5120) + B[256][40]h (20480), stride 25600;
//       arow @51200, s1 @51456, s2 @51712; total 51968.
// ===========================================================================
#define K3_SMEM 51968
__global__ __launch_bounds__(256, 2)
void out_mma(const float* __restrict__ x,
             const float* __restrict__ bout,
             const float* __restrict__ gamma,
             const float* __restrict__ beta,
             float* __restrict__ out)
{
    extern __shared__ char smem[];
    const uint32_t sbase = smem_u32(smem);
    int*   arow = (int*)(smem + 51200);
    float* s1   = (float*)(smem + 51456);
    float* s2   = (float*)(smem + 51712);

    const int tid  = threadIdx.x;
    const int wid  = tid >> 5;
    const int lane = tid & 31;
    const int m0   = blockIdx.x * 64;
    if (tid < 64) { arow[tid] = xrow_offset(m0 + tid); s1[tid] = 0.f; s2[tid] = 0.f; }

    const int wm = (wid >> 2) * 32;
    const int wn = (wid & 3) * 64;
    const int r0 = lane >> 2;
    const int kc = lane & 3;
    const int lj = lane >> 3;
    const int lq = lane & 7;

    const uint32_t a_off = (uint32_t)((wm + ((lj & 1) << 3) + lq) * 80 + ((lj >> 1) << 4));
    const uint32_t b_off = 5120u + (uint32_t)((wn + (((lj >> 1) & 1) << 3) + lq) * 80 + ((lj & 1) << 4));

    float acc[2][8][4];
    #pragma unroll
    for (int i = 0; i < 2; i++)
        #pragma unroll
        for (int j = 0; j < 8; j++)
            #pragma unroll
            for (int q = 0; q < 4; q++) acc[i][j][q] = 0.f;

    __syncthreads();

    // A: 256 cp ops -> 1/thread; B: 1024 -> 4/thread
    {
        int r = tid >> 2, q8 = (tid & 3) << 3;
        CP16(sbase + (uint32_t)(r * 80 + q8 * 2), g_atth + (size_t)(m0 + r) * 256 + q8);
    }
    #pragma unroll
    for (int i = 0; i < 4; i++) {
        int f = tid + i * 256;
        int r = f >> 2, q8 = (f & 3) << 3;
        CP16(sbase + 5120 + (uint32_t)(r * 80 + q8 * 2), g_woutTh + (size_t)r * 256 + q8);
    }
    CP_COMMIT();

    #pragma unroll
    for (int it = 0; it < 8; it++) {
        if (it < 7) {
            uint32_t bo = (uint32_t)(((it + 1) & 1) * 25600);
            int kt = (it + 1) * 32;
            {
                int r = tid >> 2, q8 = (tid & 3) << 3;
                CP16(sbase + bo + (uint32_t)(r * 80 + q8 * 2),
                     g_atth + (size_t)(m0 + r) * 256 + kt + q8);
            }
            #pragma unroll
            for (int i = 0; i < 4; i++) {
                int f = tid + i * 256;
                int r = f >> 2, q8 = (f & 3) << 3;
                CP16(sbase + bo + 5120 + (uint32_t)(r * 80 + q8 * 2),
                     g_woutTh + (size_t)r * 256 + kt + q8);
            }
            CP_COMMIT();
            CP_WAIT(1);
        } else {
            CP_WAIT(0);
        }
        __syncthreads();

        const uint32_t bufb = sbase + (uint32_t)((it & 1) * 25600);

        #pragma unroll
        for (int k16 = 0; k16 < 32; k16 += 16) {
            uint32_t a[2][4], b2[4][4];
            #pragma unroll
            for (int im = 0; im < 2; im++)
                ldsm_x4(a[im][0], a[im][1], a[im][2], a[im][3],
                        bufb + a_off + (uint32_t)(im * 1280 + k16 * 2));
            #pragma unroll
            for (int g = 0; g < 4; g++)
                ldsm_x4(b2[g][0], b2[g][1], b2[g][2], b2[g][3],
                        bufb + b_off + (uint32_t)(g * 1280 + k16 * 2));
            #pragma unroll
            for (int im = 0; im < 2; im++)
                #pragma unroll
                for (int in_ = 0; in_ < 8; in_++)
                    mma16(acc[im][in_], a[im][0], a[im][1], a[im][2], a[im][3],
                          b2[in_ >> 1][(in_ & 1) << 1], b2[in_ >> 1][((in_ & 1) << 1) + 1]);
        }
        __syncthreads();
    }

    // ---- epilogue: y = acc + bias + residual(fp32); LN over full rows ----
    #pragma unroll
    for (int im = 0; im < 2; im++) {
        #pragma unroll
        for (int half_ = 0; half_ < 2; half_++) {
            int rl = wm + im * 16 + r0 + half_ * 8;
            const float* xr = x + arow[rl];
            float p1 = 0.f, p2 = 0.f;
            #pragma unroll
            for (int in_ = 0; in_ < 8; in_++) {
                int c = wn + in_ * 8 + kc * 2;
                float2 xv = *(const float2*)(xr + c);
                float y0 = acc[im][in_][half_ * 2 + 0] + bout[c]     + xv.x;
                float y1 = acc[im][in_][half_ * 2 + 1] + bout[c + 1] + xv.y;
                acc[im][in_][half_ * 2 + 0] = y0;
                acc[im][in_][half_ * 2 + 1] = y1;
                p1 += y0 + y1;
                p2 += y0 * y0 + y1 * y1;
            }
            p1 += __shfl_xor_sync(0xffffffffu, p1, 1);
            p2 += __shfl_xor_sync(0xffffffffu, p2, 1);
            p1 += __shfl_xor_sync(0xffffffffu, p1, 2);
            p2 += __shfl_xor_sync(0xffffffffu, p2, 2);
            if (kc == 0) {
                atomicAdd(&s1[rl], p1);
                atomicAdd(&s2[rl], p2);
            }
        }
    }
    __syncthreads();

    #pragma unroll
    for (int im = 0; im < 2; im++) {
        #pragma unroll
        for (int half_ = 0; half_ < 2; half_++) {
            int rl = wm + im * 16 + r0 + half_ * 8;
            int m  = m0 + rl;
            float mean = s1[rl] * (1.0f / 256.0f);
            float var  = s2[rl] * (1.0f / 256.0f) - mean * mean;
            float rstd = rsqrtf(var + 1e-5f);
            #pragma unroll
            for (int in_ = 0; in_ < 8; in_++) {
                int c = wn + in_ * 8 + kc * 2;
                float y0 = acc[im][in_][half_ * 2 + 0];
                float y1 = acc[im][in_][half_ * 2 + 1];
                float2 o = make_float2((y0 - mean) * rstd * gamma[c]     + beta[c],
                                       (y1 - mean) * rstd * gamma[c + 1] + beta[c + 1]);
                *(float2*)(out + (size_t)m * 256 + c) = o;
            }
        }
    }
}

// ===========================================================================
extern "C" void kernel_launch(void* const* d_in, const int* in_sizes, int n_in,
                              void* d_out, int out_size)
{
    const float* x          = (const float*)d_in[0];
    const float* w_qkv      = (const float*)d_in[1];
    const float* b_qkv      = (const float*)d_in[2];
    const float* bias_table = (const float*)d_in[3];
    const float* w_out      = (const float*)d_in[4];
    const float* b_out      = (const float*)d_in[5];
    const float* ln_gamma   = (const float*)d_in[6];
    const float* ln_beta    = (const float*)d_in[7];
    float* out = (float*)d_out;

    cudaFuncSetAttribute(qkv_attn, cudaFuncAttributeMaxDynamicSharedMemorySize, FUSED_SMEM);
    cudaFuncSetAttribute(out_mma, cudaFuncAttributeMaxDynamicSharedMemorySize, K3_SMEM);

    prep_xh<<<50176, 256>>>((const float4*)x);
    prep_wh<<<(256 * 768 + 255) / 256, 256>>>(w_qkv, 256, 768, 0);
    prep_wh<<<(256 * 256 + 255) / 256, 256>>>(w_out, 256, 256, 1);
    prep_bias<<<128, 256>>>(bias_table);
    qkv_attn<<<dim3(HEADS, NWIN / 2), 256, FUSED_SMEM>>>(b_qkv);
    out_mma<<<MTOT / 64, 256, K3_SMEM>>>(x, b_out, ln_gamma, ln_beta, out);
}

// round 10
// speedup vs baseline: 5.3371x; 1.0409x over previous
#include <cuda_runtime.h>
#include <cuda_fp16.h>
#include <cstdint>

#define MTOT  200704
#define NWIN  4096
#define HEADS 8
#define NPCTA 296          // persistent CTAs (2 per SM x 148)
#define CPH   37           // CTAs per head (296/8)

// Scratch (device globals; no cudaMalloc allowed)
__device__ __half g_xh   [51380224];    // x converted to fp16
__device__ __half g_atth [51380224];    // [MTOT][256] fp16
__device__ __half g_wqkvTh[768 * 256];  // w_qkv^T [N][K] fp16
__device__ __half g_woutTh[256 * 256];  // w_out^T [N][K] fp16
__device__ float  g_biasmat[8 * 64 * 64]; // per-head bias matrix, masked

// ===========================================================================
// Helpers
// ===========================================================================
__device__ __forceinline__ uint32_t smem_u32(const void* p) {
    uint32_t a;
    asm("{ .reg .u64 t; cvta.to.shared.u64 t, %1; cvt.u32.u64 %0, t; }"
        : "=r"(a) : "l"(p));
    return a;
}

__device__ __forceinline__ uint32_t pack_half2(float a, float b) {
    __half2 h = __floats2half2_rn(a, b);
    return *(uint32_t*)&h;
}

// m16n8k16 fp16 MMA, fp32 accumulate
__device__ __forceinline__ void mma16(float d[4],
                                      uint32_t a0, uint32_t a1, uint32_t a2, uint32_t a3,
                                      uint32_t b0, uint32_t b1) {
    asm volatile(
        "mma.sync.aligned.m16n8k16.row.col.f32.f16.f16.f32 "
        "{%0,%1,%2,%3}, {%4,%5,%6,%7}, {%8,%9}, {%0,%1,%2,%3};"
        : "+f"(d[0]), "+f"(d[1]), "+f"(d[2]), "+f"(d[3])
        : "r"(a0), "r"(a1), "r"(a2), "r"(a3), "r"(b0), "r"(b1));
}

__device__ __forceinline__ void ldsm_x4(uint32_t& d0, uint32_t& d1,
                                        uint32_t& d2, uint32_t& d3, uint32_t addr) {
    asm volatile("ldmatrix.sync.aligned.m8n8.x4.shared.b16 {%0,%1,%2,%3}, [%4];"
                 : "=r"(d0), "=r"(d1), "=r"(d2), "=r"(d3) : "r"(addr));
}

__device__ __forceinline__ void ldsm_x4t(uint32_t& d0, uint32_t& d1,
                                         uint32_t& d2, uint32_t& d3, uint32_t addr) {
    asm volatile("ldmatrix.sync.aligned.m8n8.x4.trans.shared.b16 {%0,%1,%2,%3}, [%4];"
                 : "=r"(d0), "=r"(d1), "=r"(d2), "=r"(d3) : "r"(addr));
}

#define CP16(dst_u32, src_ptr) \
    asm volatile("cp.async.ca.shared.global [%0], [%1], 16;" \
                 :: "r"(dst_u32), "l"(src_ptr))
#define CP16Z(dst_u32, src_ptr, nbytes) \
    asm volatile("cp.async.ca.shared.global [%0], [%1], 16, %2;" \
                 :: "r"(dst_u32), "l"(src_ptr), "r"(nbytes))
#define CP_COMMIT() asm volatile("cp.async.commit_group;")
#define CP_WAIT(n)  asm volatile("cp.async.wait_group %0;" :: "n"(n))

// Map token row r (window-major) to element offset of its pixel row in x[4,224,224,256]
__device__ __forceinline__ int xrow_offset(int r) {
    int w   = r / 49;
    int t   = r - w * 49;
    int b   = w >> 10;
    int rem = w & 1023;
    int wh  = rem >> 5;
    int ww  = rem & 31;
    int i   = t / 7;
    int j   = t - i * 7;
    int row = (b * 224 + wh * 7 + i) * 224 + (ww * 7 + j);
    return row << 8;
}

// ===========================================================================
// Prep kernels
// ===========================================================================
__global__ void prep_xh(const float4* __restrict__ x4) {
    int idx = blockIdx.x * 256 + threadIdx.x;
    float4 v = x4[idx];
    ((uint2*)g_xh)[idx] = make_uint2(pack_half2(v.x, v.y), pack_half2(v.z, v.w));
}

__global__ void prep_wh(const float* __restrict__ w, int K, int N, int which) {
    __half* wT = which ? g_woutTh : g_wqkvTh;
    int idx = blockIdx.x * 256 + threadIdx.x;
    if (idx < K * N) {
        int k = idx / N;
        int n = idx - k * N;
        wT[(size_t)n * K + k] = __float2half_rn(w[idx]);
    }
}

__global__ void prep_bias(const float* __restrict__ bt) {
    int idx = blockIdx.x * 256 + threadIdx.x;   // 8*64*64
    int h = idx >> 12;
    int r = (idx >> 6) & 63;
    int c = idx & 63;
    float v;
    if (c >= 49)      v = -1e30f;
    else if (r >= 49) v = 0.f;
    else {
        int i1 = r / 7, j1 = r - i1 * 7;
        int i2 = c / 7, j2 = c - i2 * 7;
        v = bt[((i1 - i2 + 6) * 13 + (j1 - j2 + 6)) * 8 + h];
    }
    g_biasmat[idx] = v;
}

// ===========================================================================
// Fused K1+K2, PERSISTENT: 296 CTAs; CTA owns head (cta&7), loops window
// pairs wg = (cta>>3), step 37. W-slice loaded ONCE per CTA. Occupancy 2.
//
// smem layout (bytes):
//   W     [96][264]h   @ 0       (50688)
//   Abuf  2x[128][40]h @ 50688   (2 x 10240)
//   QKV   [128][104]h  @ 50688   (26624)  -- aliases Abuf after GEMM
//   arow  int[128]     @ 77312
// ===========================================================================
#define FUSED_SMEM 77824
#define OFF_W    0
#define OFF_AB   50688
#define OFF_QKV  50688
#define OFF_AROW 77312

__global__ __launch_bounds__(256, 2)
void qkv_attn_p(const float* __restrict__ bqkv)
{
    extern __shared__ char smem[];
    const uint32_t sbase = smem_u32(smem);
    int* arow = (int*)(smem + OFF_AROW);

    const int tid  = threadIdx.x;
    const int wid  = tid >> 5;
    const int lane = tid & 31;
    const int cta  = blockIdx.x;
    const int h    = cta & 7;           // head
    const int c0   = cta >> 3;          // first window pair, step CPH
    const int r0   = lane >> 2;
    const int kc   = lane & 3;
    const int lj   = lane >> 3;
    const int lq   = lane & 7;

    // ---- weight slice load ONCE: 96 rows x 256 halves -> W[96][264] ----
    #pragma unroll
    for (int i = 0; i < 12; i++) {
        int f   = tid + i * 256;
        int row = f >> 5;
        int q8  = (f & 31) << 3;
        int sec = row >> 5;
        int gn  = sec * 256 + h * 32 + (row & 31);
        CP16(sbase + OFF_W + (uint32_t)(row * 528 + q8 * 2),
             g_wqkvTh + (size_t)gn * 256 + q8);
    }
    CP_COMMIT();

    // ---- loop-invariant constants ----
    const int my = wid >> 1;
    const int nx = wid & 1;
    const int wm = my * 32;
    const int wn = nx * 48;

    const uint32_t a_off = (uint32_t)((wm + ((lj & 1) << 3) + lq) * 80 + ((lj >> 1) << 4));
    const uint32_t b_off = OFF_W + (uint32_t)((wn + (((lj >> 1) & 1) << 3) + lq) * 528 + ((lj & 1) << 4));

    float bias0[6], bias1[6], scl[6];
    #pragma unroll
    for (int in_ = 0; in_ < 6; in_++) {
        int col = wn + in_ * 8 + kc * 2;
        int sec = col >> 5;
        bias0[in_] = bqkv[sec * 256 + h * 32 + (col & 31)];
        bias1[in_] = bqkv[sec * 256 + h * 32 + ((col + 1) & 31)];
        scl[in_]   = (sec == 0) ? 0.5f : 1.0f;
    }

    // attention constants
    const int aw    = wid >> 2;
    const int rq    = wid & 3;
    const int wbase = aw * 64;
    const uint32_t qkvb   = sbase + OFF_QKV;
    const uint32_t qa_off = (uint32_t)(((wbase + rq * 16) + ((lj & 1) << 3) + lq) * 208 + ((lj >> 1) << 4));
    const uint32_t kb_off = (uint32_t)((wbase + (((lj >> 1) & 1) << 3) + lq) * 208 + 64 + ((lj & 1) << 4));
    const uint32_t vb_off = (uint32_t)((wbase + ((lj & 1) << 3) + lq) * 208 + 128 + ((lj >> 1) << 4));
    const float* bmr0 = g_biasmat + h * 4096 + (rq * 16 + r0) * 64;

    for (int wg = c0; wg < NWIN / 2; wg += CPH) {
        __syncthreads();   // QKV/Abuf alias + arow reuse barrier

        if (tid < 128) {
            int aw_ = tid >> 6, t = tid & 63;
            arow[tid] = (t < 49) ? xrow_offset((wg * 2 + aw_) * 49 + t) : -1;
        }
        __syncthreads();

        // ---- GEMM: 8 warps = 4m x 2n, warp tile 32 x 48 ----
        float acc[2][6][4];
        #pragma unroll
        for (int i = 0; i < 2; i++)
            #pragma unroll
            for (int j = 0; j < 6; j++)
                #pragma unroll
                for (int q = 0; q < 4; q++) acc[i][j][q] = 0.f;

        int lrow[2], lq8[2], lsz[2];
        const __half* lsrc[2];
        #pragma unroll
        for (int i = 0; i < 2; i++) {
            int f = tid + i * 256;
            lrow[i] = f >> 2;
            lq8[i]  = (f & 3) << 3;
            int ar  = arow[lrow[i]];
            lsz[i]  = (ar >= 0) ? 16 : 0;
            lsrc[i] = g_xh + ((ar >= 0) ? ar : 0) + lq8[i];
        }

        #pragma unroll
        for (int i = 0; i < 2; i++)
            CP16Z(sbase + OFF_AB + (uint32_t)(lrow[i] * 80 + lq8[i] * 2), lsrc[i], lsz[i]);
        CP_COMMIT();

        #pragma unroll
        for (int it = 0; it < 8; it++) {
            if (it < 7) {
                uint32_t bo = OFF_AB + (uint32_t)(((it + 1) & 1) * 10240);
                int kt = (it + 1) * 32;
                #pragma unroll
                for (int i = 0; i < 2; i++)
                    CP16Z(bo + sbase + (uint32_t)(lrow[i] * 80 + lq8[i] * 2), lsrc[i] + kt, lsz[i]);
                CP_COMMIT();
                CP_WAIT(1);
            } else {
                CP_WAIT(0);
            }
            __syncthreads();

            const uint32_t abuf = sbase + OFF_AB + (uint32_t)((it & 1) * 10240);
            const uint32_t bkof = (uint32_t)(it * 64);

            #pragma unroll
            for (int k16 = 0; k16 < 32; k16 += 16) {
                uint32_t a[2][4], b2[3][4];
                #pragma unroll
                for (int im = 0; im < 2; im++)
                    ldsm_x4(a[im][0], a[im][1], a[im][2], a[im][3],
                            abuf + a_off + (uint32_t)(im * 1280 + k16 * 2));
                #pragma unroll
                for (int g = 0; g < 3; g++)
                    ldsm_x4(b2[g][0], b2[g][1], b2[g][2], b2[g][3],
                            sbase + b_off + bkof + (uint32_t)(g * 8448 + k16 * 2));
                #pragma unroll
                for (int im = 0; im < 2; im++)
                    #pragma unroll
                    for (int in_ = 0; in_ < 6; in_++)
                        mma16(acc[im][in_], a[im][0], a[im][1], a[im][2], a[im][3],
                              b2[in_ >> 1][(in_ & 1) << 1], b2[in_ >> 1][((in_ & 1) << 1) + 1]);
            }
            __syncthreads();
        }

        // ---- epilogue: +bias, q-scale, store fp16 into QKV[128][104] ----
        #pragma unroll
        for (int im = 0; im < 2; im++) {
            int r_lo = wm + im * 16 + r0;
            #pragma unroll
            for (int in_ = 0; in_ < 6; in_++) {
                int colb = (wn + in_ * 8 + kc * 2) * 2;
                *(uint32_t*)(smem + OFF_QKV + r_lo * 208 + colb) =
                    pack_half2((acc[im][in_][0] + bias0[in_]) * scl[in_],
                               (acc[im][in_][1] + bias1[in_]) * scl[in_]);
                *(uint32_t*)(smem + OFF_QKV + (r_lo + 8) * 208 + colb) =
                    pack_half2((acc[im][in_][2] + bias0[in_]) * scl[in_],
                               (acc[im][in_][3] + bias1[in_]) * scl[in_]);
            }
        }
        __syncthreads();

        // ================= Phase B: attention =================
        // S = Q @ K^T : warp tile 16 x 64
        float c[8][4];
        #pragma unroll
        for (int nt = 0; nt < 8; nt++)
            #pragma unroll
            for (int q = 0; q < 4; q++) c[nt][q] = 0.f;

        #pragma unroll
        for (int k16 = 0; k16 < 32; k16 += 16) {
            uint32_t a0, a1, a2, a3;
            ldsm_x4(a0, a1, a2, a3, qkvb + qa_off + (uint32_t)(k16 * 2));
            #pragma unroll
            for (int g = 0; g < 4; g++) {
                uint32_t b0, b1, b2, b3;
                ldsm_x4(b0, b1, b2, b3, qkvb + kb_off + (uint32_t)(g * 3328 + k16 * 2));
                mma16(c[2 * g],     a0, a1, a2, a3, b0, b1);
                mma16(c[2 * g + 1], a0, a1, a2, a3, b2, b3);
            }
        }

        // bias (pre-masked) + register softmax
        #pragma unroll
        for (int half_ = 0; half_ < 2; half_++) {
            const float* bmr = bmr0 + half_ * 8 * 64;
            #pragma unroll
            for (int nt = 0; nt < 8; nt++) {
                float2 bv = *(const float2*)(bmr + nt * 8 + 2 * kc);
                c[nt][half_ * 2 + 0] += bv.x;
                c[nt][half_ * 2 + 1] += bv.y;
            }
            float mx = -1e30f;
            #pragma unroll
            for (int nt = 0; nt < 8; nt++) {
                mx = fmaxf(mx, c[nt][half_ * 2]);
                mx = fmaxf(mx, c[nt][half_ * 2 + 1]);
            }
            mx = fmaxf(mx, __shfl_xor_sync(0xffffffffu, mx, 1));
            mx = fmaxf(mx, __shfl_xor_sync(0xffffffffu, mx, 2));
            float s = 0.f;
            #pragma unroll
            for (int nt = 0; nt < 8; nt++) {
                #pragma unroll
                for (int e = 0; e < 2; e++) {
                    float p = __expf(c[nt][half_ * 2 + e] - mx);
                    c[nt][half_ * 2 + e] = p;
                    s += p;
                }
            }
            s += __shfl_xor_sync(0xffffffffu, s, 1);
            s += __shfl_xor_sync(0xffffffffu, s, 2);
            float inv = 1.0f / s;
            #pragma unroll
            for (int nt = 0; nt < 8; nt++) {
                c[nt][half_ * 2 + 0] *= inv;
                c[nt][half_ * 2 + 1] *= inv;
            }
        }

        // O = P @ V : V^T B-frags via ldmatrix.trans on v slice [t][d]
        float o[4][4];
        #pragma unroll
        for (int jn = 0; jn < 4; jn++)
            #pragma unroll
            for (int q = 0; q < 4; q++) o[jn][q] = 0.f;

        #pragma unroll
        for (int kt = 0; kt < 4; kt++) {
            uint32_t vb[2][4];
            #pragma unroll
            for (int g = 0; g < 2; g++)
                ldsm_x4t(vb[g][0], vb[g][1], vb[g][2], vb[g][3],
                         qkvb + vb_off + (uint32_t)(kt * 16 * 208 + g * 32));
            uint32_t a0 = pack_half2(c[2 * kt][0],     c[2 * kt][1]);
            uint32_t a1 = pack_half2(c[2 * kt][2],     c[2 * kt][3]);
            uint32_t a2 = pack_half2(c[2 * kt + 1][0], c[2 * kt + 1][1]);
            uint32_t a3 = pack_half2(c[2 * kt + 1][2], c[2 * kt + 1][3]);
            #pragma unroll
            for (int g = 0; g < 2; g++) {
                mma16(o[2 * g],     a0, a1, a2, a3, vb[g][0], vb[g][1]);
                mma16(o[2 * g + 1], a0, a1, a2, a3, vb[g][2], vb[g][3]);
            }
        }

        // store O
        const int win = wg * 2 + aw;
        #pragma unroll
        for (int half_ = 0; half_ < 2; half_++) {
            int t_ = rq * 16 + r0 + half_ * 8;
            if (t_ < 49) {
                __half* op = g_atth + ((size_t)win * 49 + t_) * 256 + h * 32;
                #pragma unroll
                for (int jn = 0; jn < 4; jn++)
                    *(uint32_t*)(op + jn * 8 + 2 * kc) =
                        pack_half2(o[jn][half_ * 2 + 0], o[jn][half_ * 2 + 1]);
            }
        }
    }
}

// ===========================================================================
// K3: out = LN(g_att @ w_out + b_out + gather(x))  fp16 mma + ldmatrix
// CTA 64x256 (full rows), BK=32, 8 warps (2m x 4n), warp tile 32x64. Occ 2.
// ===========================================================================
#define K3_SMEM 51968
__global__ __launch_bounds__(256, 2)
void out_mma(const float* __restrict__ x,
             const float* __restrict__ bout,
             const float* __restrict__ gamma,
             const float* __restrict__ beta,
             float* __restrict__ out)
{
    extern __shared__ char smem[];
    const uint32_t sbase = smem_u32(smem);
    int*   arow = (int*)(smem + 51200);
    float* s1   = (float*)(smem + 51456);
    float* s2   = (float*)(smem + 51712);

    const int tid  = threadIdx.x;
    const int wid  = tid >> 5;
    const int lane = tid & 31;
    const int m0   = blockIdx.x * 64;
    if (tid < 64) { arow[tid] = xrow_offset(m0 + tid); s1[tid] = 0.f; s2[tid] = 0.f; }

    const int wm = (wid >> 2) * 32;
    const int wn = (wid & 3) * 64;
    const int r0 = lane >> 2;
    const int kc = lane & 3;
    const int lj = lane >> 3;
    const int lq = lane & 7;

    const uint32_t a_off = (uint32_t)((wm + ((lj & 1) << 3) + lq) * 80 + ((lj >> 1) << 4));
    const uint32_t b_off = 5120u + (uint32_t)((wn + (((lj >> 1) & 1) << 3) + lq) * 80 + ((lj & 1) << 4));

    float acc[2][8][4];
    #pragma unroll
    for (int i = 0; i < 2; i++)
        #pragma unroll
        for (int j = 0; j < 8; j++)
            #pragma unroll
            for (int q = 0; q < 4; q++) acc[i][j][q] = 0.f;

    __syncthreads();

    {
        int r = tid >> 2, q8 = (tid & 3) << 3;
        CP16(sbase + (uint32_t)(r * 80 + q8 * 2), g_atth + (size_t)(m0 + r) * 256 + q8);
    }
    #pragma unroll
    for (int i = 0; i < 4; i++) {
        int f = tid + i * 256;
        int r = f >> 2, q8 = (f & 3) << 3;
        CP16(sbase + 5120 + (uint32_t)(r * 80 + q8 * 2), g_woutTh + (size_t)r * 256 + q8);
    }
    CP_COMMIT();

    #pragma unroll
    for (int it = 0; it < 8; it++) {
        if (it < 7) {
            uint32_t bo = (uint32_t)(((it + 1) & 1) * 25600);
            int kt = (it + 1) * 32;
            {
                int r = tid >> 2, q8 = (tid & 3) << 3;
                CP16(sbase + bo + (uint32_t)(r * 80 + q8 * 2),
                     g_atth + (size_t)(m0 + r) * 256 + kt + q8);
            }
            #pragma unroll
            for (int i = 0; i < 4; i++) {
                int f = tid + i * 256;
                int r = f >> 2, q8 = (f & 3) << 3;
                CP16(sbase + bo + 5120 + (uint32_t)(r * 80 + q8 * 2),
                     g_woutTh + (size_t)r * 256 + kt + q8);
            }
            CP_COMMIT();
            CP_WAIT(1);
        } else {
            CP_WAIT(0);
        }
        __syncthreads();

        const uint32_t bufb = sbase + (uint32_t)((it & 1) * 25600);

        #pragma unroll
        for (int k16 = 0; k16 < 32; k16 += 16) {
            uint32_t a[2][4], b2[4][4];
            #pragma unroll
            for (int im = 0; im < 2; im++)
                ldsm_x4(a[im][0], a[im][1], a[im][2], a[im][3],
                        bufb + a_off + (uint32_t)(im * 1280 + k16 * 2));
            #pragma unroll
            for (int g = 0; g < 4; g++)
                ldsm_x4(b2[g][0], b2[g][1], b2[g][2], b2[g][3],
                        bufb + b_off + (uint32_t)(g * 1280 + k16 * 2));
            #pragma unroll
            for (int im = 0; im < 2; im++)
                #pragma unroll
                for (int in_ = 0; in_ < 8; in_++)
                    mma16(acc[im][in_], a[im][0], a[im][1], a[im][2], a[im][3],
                          b2[in_ >> 1][(in_ & 1) << 1], b2[in_ >> 1][((in_ & 1) << 1) + 1]);
        }
        __syncthreads();
    }

    // ---- epilogue: y = acc + bias + residual(fp32); LN over full rows ----
    #pragma unroll
    for (int im = 0; im < 2; im++) {
        #pragma unroll
        for (int half_ = 0; half_ < 2; half_++) {
            int rl = wm + im * 16 + r0 + half_ * 8;
            const float* xr = x + arow[rl];
            float p1 = 0.f, p2 = 0.f;
            #pragma unroll
            for (int in_ = 0; in_ < 8; in_++) {
                int c = wn + in_ * 8 + kc * 2;
                float2 xv = *(const float2*)(xr + c);
                float y0 = acc[im][in_][half_ * 2 + 0] + bout[c]     + xv.x;
                float y1 = acc[im][in_][half_ * 2 + 1] + bout[c + 1] + xv.y;
                acc[im][in_][half_ * 2 + 0] = y0;
                acc[im][in_][half_ * 2 + 1] = y1;
                p1 += y0 + y1;
                p2 += y0 * y0 + y1 * y1;
            }
            p1 += __shfl_xor_sync(0xffffffffu, p1, 1);
            p2 += __shfl_xor_sync(0xffffffffu, p2, 1);
            p1 += __shfl_xor_sync(0xffffffffu, p1, 2);
            p2 += __shfl_xor_sync(0xffffffffu, p2, 2);
            if (kc == 0) {
                atomicAdd(&s1[rl], p1);
                atomicAdd(&s2[rl], p2);
            }
        }
    }
    __syncthreads();

    #pragma unroll
    for (int im = 0; im < 2; im++) {
        #pragma unroll
        for (int half_ = 0; half_ < 2; half_++) {
            int rl = wm + im * 16 + r0 + half_ * 8;
            int m  = m0 + rl;
            float mean = s1[rl] * (1.0f / 256.0f);
            float var  = s2[rl] * (1.0f / 256.0f) - mean * mean;
            float rstd = rsqrtf(var + 1e-5f);
            #pragma unroll
            for (int in_ = 0; in_ < 8; in_++) {
                int c = wn + in_ * 8 + kc * 2;
                float y0 = acc[im][in_][half_ * 2 + 0];
                float y1 = acc[im][in_][half_ * 2 + 1];
                float2 o = make_float2((y0 - mean) * rstd * gamma[c]     + beta[c],
                                       (y1 - mean) * rstd * gamma[c + 1] + beta[c + 1]);
                *(float2*)(out + (size_t)m * 256 + c) = o;
            }
        }
    }
}

// ===========================================================================
extern "C" void kernel_launch(void* const* d_in, const int* in_sizes, int n_in,
                              void* d_out, int out_size)
{
    const float* x          = (const float*)d_in[0];
    const float* w_qkv      = (const float*)d_in[1];
    const float* b_qkv      = (const float*)d_in[2];
    const float* bias_table = (const float*)d_in[3];
    const float* w_out      = (const float*)d_in[4];
    const float* b_out      = (const float*)d_in[5];
    const float* ln_gamma   = (const float*)d_in[6];
    const float* ln_beta    = (const float*)d_in[7];
    float* out = (float*)d_out;

    cudaFuncSetAttribute(qkv_attn_p, cudaFuncAttributeMaxDynamicSharedMemorySize, FUSED_SMEM);
    cudaFuncSetAttribute(out_mma, cudaFuncAttributeMaxDynamicSharedMemorySize, K3_SMEM);

    prep_xh<<<50176, 256>>>((const float4*)x);
    prep_wh<<<(256 * 768 + 255) / 256, 256>>>(w_qkv, 256, 768, 0);
    prep_wh<<<(256 * 256 + 255) / 256, 256>>>(w_out, 256, 256, 1);
    prep_bias<<<128, 256>>>(bias_table);
    qkv_attn_p<<<NPCTA, 256, FUSED_SMEM>>>(b_qkv);
    out_mma<<<MTOT / 64, 256, K3_SMEM>>>(x, b_out, ln_gamma, ln_beta, out);
}

// round 11
// speedup vs baseline: 5.7020x; 1.0684x over previous
#include <cuda_runtime.h>
#include <cuda_fp16.h>
#include <cstdint>

#define MTOT  200704
#define NWIN  4096
#define HEADS 8
#define NPCTA 296          // persistent CTAs (2 per SM x 148)
#define CPH   37           // CTAs per head (296/8)

// Scratch (device globals; no cudaMalloc allowed)
__device__ __half g_xh   [51380224];    // x converted to fp16
__device__ __half g_atth [51380224];    // [MTOT][256] fp16
__device__ __half g_wqkvTh[768 * 256];  // w_qkv^T [N][K] fp16
__device__ __half g_woutTh[256 * 256];  // w_out^T [N][K] fp16
__device__ float  g_biasmat[8 * 64 * 64]; // per-head bias matrix, masked

// ===========================================================================
// Helpers
// ===========================================================================
__device__ __forceinline__ uint32_t smem_u32(const void* p) {
    uint32_t a;
    asm("{ .reg .u64 t; cvta.to.shared.u64 t, %1; cvt.u32.u64 %0, t; }"
        : "=r"(a) : "l"(p));
    return a;
}

__device__ __forceinline__ uint32_t pack_half2(float a, float b) {
    __half2 h = __floats2half2_rn(a, b);
    return *(uint32_t*)&h;
}

// m16n8k16 fp16 MMA, fp32 accumulate
__device__ __forceinline__ void mma16(float d[4],
                                      uint32_t a0, uint32_t a1, uint32_t a2, uint32_t a3,
                                      uint32_t b0, uint32_t b1) {
    asm volatile(
        "mma.sync.aligned.m16n8k16.row.col.f32.f16.f16.f32 "
        "{%0,%1,%2,%3}, {%4,%5,%6,%7}, {%8,%9}, {%0,%1,%2,%3};"
        : "+f"(d[0]), "+f"(d[1]), "+f"(d[2]), "+f"(d[3])
        : "r"(a0), "r"(a1), "r"(a2), "r"(a3), "r"(b0), "r"(b1));
}

__device__ __forceinline__ void ldsm_x4(uint32_t& d0, uint32_t& d1,
                                        uint32_t& d2, uint32_t& d3, uint32_t addr) {
    asm volatile("ldmatrix.sync.aligned.m8n8.x4.shared.b16 {%0,%1,%2,%3}, [%4];"
                 : "=r"(d0), "=r"(d1), "=r"(d2), "=r"(d3) : "r"(addr));
}

__device__ __forceinline__ void ldsm_x4t(uint32_t& d0, uint32_t& d1,
                                         uint32_t& d2, uint32_t& d3, uint32_t addr) {
    asm volatile("ldmatrix.sync.aligned.m8n8.x4.trans.shared.b16 {%0,%1,%2,%3}, [%4];"
                 : "=r"(d0), "=r"(d1), "=r"(d2), "=r"(d3) : "r"(addr));
}

#define CP16(dst_u32, src_ptr) \
    asm volatile("cp.async.ca.shared.global [%0], [%1], 16;" \
                 :: "r"(dst_u32), "l"(src_ptr))
#define CP16Z(dst_u32, src_ptr, nbytes) \
    asm volatile("cp.async.ca.shared.global [%0], [%1], 16, %2;" \
                 :: "r"(dst_u32), "l"(src_ptr), "r"(nbytes))
#define CP_COMMIT() asm volatile("cp.async.commit_group;")
#define CP_WAIT(n)  asm volatile("cp.async.wait_group %0;" :: "n"(n))

// Map token row r (window-major) to element offset of its pixel row in x[4,224,224,256]
__device__ __forceinline__ int xrow_offset(int r) {
    int w   = r / 49;
    int t   = r - w * 49;
    int b   = w >> 10;
    int rem = w & 1023;
    int wh  = rem >> 5;
    int ww  = rem & 31;
    int i   = t / 7;
    int j   = t - i * 7;
    int row = (b * 224 + wh * 7 + i) * 224 + (ww * 7 + j);
    return row << 8;
}

// ===========================================================================
// Prep kernels
// ===========================================================================
__global__ void prep_xh(const float4* __restrict__ x4) {
    int idx = blockIdx.x * 256 + threadIdx.x;
    float4 v = x4[idx];
    ((uint2*)g_xh)[idx] = make_uint2(pack_half2(v.x, v.y), pack_half2(v.z, v.w));
}

__global__ void prep_wh(const float* __restrict__ w, int K, int N, int which) {
    __half* wT = which ? g_woutTh : g_wqkvTh;
    int idx = blockIdx.x * 256 + threadIdx.x;
    if (idx < K * N) {
        int k = idx / N;
        int n = idx - k * N;
        wT[(size_t)n * K + k] = __float2half_rn(w[idx]);
    }
}

__global__ void prep_bias(const float* __restrict__ bt) {
    int idx = blockIdx.x * 256 + threadIdx.x;   // 8*64*64
    int h = idx >> 12;
    int r = (idx >> 6) & 63;
    int c = idx & 63;
    float v;
    if (c >= 49)      v = -1e30f;
    else if (r >= 49) v = 0.f;
    else {
        int i1 = r / 7, j1 = r - i1 * 7;
        int i2 = c / 7, j2 = c - i2 * 7;
        v = bt[((i1 - i2 + 6) * 13 + (j1 - j2 + 6)) * 8 + h];
    }
    g_biasmat[idx] = v;
}

// ===========================================================================
// Fused K1+K2, PERSISTENT, BK=64: 296 CTAs; CTA owns head (cta&7), loops
// window pairs. W-slice loaded once. Occupancy 2.
//
// smem layout (bytes):
//   W     [96][264]h    @ 0       (50688)
//   Abuf  2x[128][72]h  @ 50688   (2 x 18432)
//   QKV   [128][104]h   @ 50688   (26624)  -- aliases Abuf after GEMM
//   arow  int[128]      @ 87552
// total 88064
// ===========================================================================
#define FUSED_SMEM 88064
#define OFF_W    0
#define OFF_AB   50688
#define OFF_QKV  50688
#define OFF_AROW 87552

__global__ __launch_bounds__(256, 2)
void qkv_attn_p(const float* __restrict__ bqkv)
{
    extern __shared__ char smem[];
    const uint32_t sbase = smem_u32(smem);
    int* arow = (int*)(smem + OFF_AROW);

    const int tid  = threadIdx.x;
    const int wid  = tid >> 5;
    const int lane = tid & 31;
    const int cta  = blockIdx.x;
    const int h    = cta & 7;
    const int c0   = cta >> 3;
    const int r0   = lane >> 2;
    const int kc   = lane & 3;
    const int lj   = lane >> 3;
    const int lq   = lane & 7;

    // ---- weight slice load ONCE: 96 rows x 256 halves -> W[96][264] ----
    #pragma unroll
    for (int i = 0; i < 12; i++) {
        int f   = tid + i * 256;
        int row = f >> 5;
        int q8  = (f & 31) << 3;
        int sec = row >> 5;
        int gn  = sec * 256 + h * 32 + (row & 31);
        CP16(sbase + OFF_W + (uint32_t)(row * 528 + q8 * 2),
             g_wqkvTh + (size_t)gn * 256 + q8);
    }
    CP_COMMIT();

    // ---- loop-invariant constants ----
    const int my = wid >> 1;
    const int nx = wid & 1;
    const int wm = my * 32;
    const int wn = nx * 48;

    const uint32_t a_off = (uint32_t)((wm + ((lj & 1) << 3) + lq) * 144 + ((lj >> 1) << 4));
    const uint32_t b_off = OFF_W + (uint32_t)((wn + (((lj >> 1) & 1) << 3) + lq) * 528 + ((lj & 1) << 4));

    float bias0[6], bias1[6], scl[6];
    #pragma unroll
    for (int in_ = 0; in_ < 6; in_++) {
        int col = wn + in_ * 8 + kc * 2;
        int sec = col >> 5;
        bias0[in_] = bqkv[sec * 256 + h * 32 + (col & 31)];
        bias1[in_] = bqkv[sec * 256 + h * 32 + ((col + 1) & 31)];
        scl[in_]   = (sec == 0) ? 0.5f : 1.0f;
    }

    // attention constants
    const int aw    = wid >> 2;
    const int rq    = wid & 3;
    const int wbase = aw * 64;
    const uint32_t qkvb   = sbase + OFF_QKV;
    const uint32_t qa_off = (uint32_t)(((wbase + rq * 16) + ((lj & 1) << 3) + lq) * 208 + ((lj >> 1) << 4));
    const uint32_t kb_off = (uint32_t)((wbase + (((lj >> 1) & 1) << 3) + lq) * 208 + 64 + ((lj & 1) << 4));
    const uint32_t vb_off = (uint32_t)((wbase + ((lj & 1) << 3) + lq) * 208 + 128 + ((lj >> 1) << 4));
    const float* bmr0 = g_biasmat + h * 4096 + (rq * 16 + r0) * 64;

    for (int wg = c0; wg < NWIN / 2; wg += CPH) {
        __syncthreads();   // QKV/Abuf alias + arow reuse barrier

        if (tid < 128) {
            int aw_ = tid >> 6, t = tid & 63;
            arow[tid] = (t < 49) ? xrow_offset((wg * 2 + aw_) * 49 + t) : -1;
        }
        __syncthreads();

        // ---- GEMM: 8 warps = 4m x 2n, warp tile 32 x 48, BK=64 ----
        float acc[2][6][4];
        #pragma unroll
        for (int i = 0; i < 2; i++)
            #pragma unroll
            for (int j = 0; j < 6; j++)
                #pragma unroll
                for (int q = 0; q < 4; q++) acc[i][j][q] = 0.f;

        // A-load slots: 128 rows x 8 chunks = 1024 ops -> 4/thread
        int lrow[4], lq8[4], lsz[4];
        const __half* lsrc[4];
        #pragma unroll
        for (int i = 0; i < 4; i++) {
            int f = tid + i * 256;
            lrow[i] = f >> 3;
            lq8[i]  = (f & 7) << 3;
            int ar  = arow[lrow[i]];
            lsz[i]  = (ar >= 0) ? 16 : 0;
            lsrc[i] = g_xh + ((ar >= 0) ? ar : 0) + lq8[i];
        }

        #pragma unroll
        for (int i = 0; i < 4; i++)
            CP16Z(sbase + OFF_AB + (uint32_t)(lrow[i] * 144 + lq8[i] * 2), lsrc[i], lsz[i]);
        CP_COMMIT();

        #pragma unroll
        for (int it = 0; it < 4; it++) {
            if (it < 3) {
                uint32_t bo = OFF_AB + (uint32_t)(((it + 1) & 1) * 18432);
                int kt = (it + 1) * 64;
                #pragma unroll
                for (int i = 0; i < 4; i++)
                    CP16Z(bo + sbase + (uint32_t)(lrow[i] * 144 + lq8[i] * 2), lsrc[i] + kt, lsz[i]);
                CP_COMMIT();
                CP_WAIT(1);
            } else {
                CP_WAIT(0);
            }
            __syncthreads();

            const uint32_t abuf = sbase + OFF_AB + (uint32_t)((it & 1) * 18432);
            const uint32_t bkof = (uint32_t)(it * 128);   // 64 halves per K-chunk

            #pragma unroll
            for (int k16 = 0; k16 < 64; k16 += 16) {
                uint32_t a[2][4], b2[3][4];
                #pragma unroll
                for (int im = 0; im < 2; im++)
                    ldsm_x4(a[im][0], a[im][1], a[im][2], a[im][3],
                            abuf + a_off + (uint32_t)(im * 2304 + k16 * 2));
                #pragma unroll
                for (int g = 0; g < 3; g++)
                    ldsm_x4(b2[g][0], b2[g][1], b2[g][2], b2[g][3],
                            sbase + b_off + bkof + (uint32_t)(g * 8448 + k16 * 2));
                #pragma unroll
                for (int im = 0; im < 2; im++)
                    #pragma unroll
                    for (int in_ = 0; in_ < 6; in_++)
                        mma16(acc[im][in_], a[im][0], a[im][1], a[im][2], a[im][3],
                              b2[in_ >> 1][(in_ & 1) << 1], b2[in_ >> 1][((in_ & 1) << 1) + 1]);
            }
            __syncthreads();
        }

        // ---- epilogue: +bias, q-scale, store fp16 into QKV[128][104] ----
        #pragma unroll
        for (int im = 0; im < 2; im++) {
            int r_lo = wm + im * 16 + r0;
            #pragma unroll
            for (int in_ = 0; in_ < 6; in_++) {
                int colb = (wn + in_ * 8 + kc * 2) * 2;
                *(uint32_t*)(smem + OFF_QKV + r_lo * 208 + colb) =
                    pack_half2((acc[im][in_][0] + bias0[in_]) * scl[in_],
                               (acc[im][in_][1] + bias1[in_]) * scl[in_]);
                *(uint32_t*)(smem + OFF_QKV + (r_lo + 8) * 208 + colb) =
                    pack_half2((acc[im][in_][2] + bias0[in_]) * scl[in_],
                               (acc[im][in_][3] + bias1[in_]) * scl[in_]);
            }
        }
        __syncthreads();

        // ================= Phase B: attention =================
        float c[8][4];
        #pragma unroll
        for (int nt = 0; nt < 8; nt++)
            #pragma unroll
            for (int q = 0; q < 4; q++) c[nt][q] = 0.f;

        #pragma unroll
        for (int k16 = 0; k16 < 32; k16 += 16) {
            uint32_t a0, a1, a2, a3;
            ldsm_x4(a0, a1, a2, a3, qkvb + qa_off + (uint32_t)(k16 * 2));
            #pragma unroll
            for (int g = 0; g < 4; g++) {
                uint32_t b0, b1, b2, b3;
                ldsm_x4(b0, b1, b2, b3, qkvb + kb_off + (uint32_t)(g * 3328 + k16 * 2));
                mma16(c[2 * g],     a0, a1, a2, a3, b0, b1);
                mma16(c[2 * g + 1], a0, a1, a2, a3, b2, b3);
            }
        }

        // bias (pre-masked) + register softmax
        #pragma unroll
        for (int half_ = 0; half_ < 2; half_++) {
            const float* bmr = bmr0 + half_ * 8 * 64;
            #pragma unroll
            for (int nt = 0; nt < 8; nt++) {
                float2 bv = *(const float2*)(bmr + nt * 8 + 2 * kc);
                c[nt][half_ * 2 + 0] += bv.x;
                c[nt][half_ * 2 + 1] += bv.y;
            }
            float mx = -1e30f;
            #pragma unroll
            for (int nt = 0; nt < 8; nt++) {
                mx = fmaxf(mx, c[nt][half_ * 2]);
                mx = fmaxf(mx, c[nt][half_ * 2 + 1]);
            }
            mx = fmaxf(mx, __shfl_xor_sync(0xffffffffu, mx, 1));
            mx = fmaxf(mx, __shfl_xor_sync(0xffffffffu, mx, 2));
            float s = 0.f;
            #pragma unroll
            for (int nt = 0; nt < 8; nt++) {
                #pragma unroll
                for (int e = 0; e < 2; e++) {
                    float p = __expf(c[nt][half_ * 2 + e] - mx);
                    c[nt][half_ * 2 + e] = p;
                    s += p;
                }
            }
            s += __shfl_xor_sync(0xffffffffu, s, 1);
            s += __shfl_xor_sync(0xffffffffu, s, 2);
            float inv = 1.0f / s;
            #pragma unroll
            for (int nt = 0; nt < 8; nt++) {
                c[nt][half_ * 2 + 0] *= inv;
                c[nt][half_ * 2 + 1] *= inv;
            }
        }

        // O = P @ V
        float o[4][4];
        #pragma unroll
        for (int jn = 0; jn < 4; jn++)
            #pragma unroll
            for (int q = 0; q < 4; q++) o[jn][q] = 0.f;

        #pragma unroll
        for (int kt = 0; kt < 4; kt++) {
            uint32_t vb[2][4];
            #pragma unroll
            for (int g = 0; g < 2; g++)
                ldsm_x4t(vb[g][0], vb[g][1], vb[g][2], vb[g][3],
                         qkvb + vb_off + (uint32_t)(kt * 16 * 208 + g * 32));
            uint32_t a0 = pack_half2(c[2 * kt][0],     c[2 * kt][1]);
            uint32_t a1 = pack_half2(c[2 * kt][2],     c[2 * kt][3]);
            uint32_t a2 = pack_half2(c[2 * kt + 1][0], c[2 * kt + 1][1]);
            uint32_t a3 = pack_half2(c[2 * kt + 1][2], c[2 * kt + 1][3]);
            #pragma unroll
            for (int g = 0; g < 2; g++) {
                mma16(o[2 * g],     a0, a1, a2, a3, vb[g][0], vb[g][1]);
                mma16(o[2 * g + 1], a0, a1, a2, a3, vb[g][2], vb[g][3]);
            }
        }

        // store O
        const int win = wg * 2 + aw;
        #pragma unroll
        for (int half_ = 0; half_ < 2; half_++) {
            int t_ = rq * 16 + r0 + half_ * 8;
            if (t_ < 49) {
                __half* op = g_atth + ((size_t)win * 49 + t_) * 256 + h * 32;
                #pragma unroll
                for (int jn = 0; jn < 4; jn++)
                    *(uint32_t*)(op + jn * 8 + 2 * kc) =
                        pack_half2(o[jn][half_ * 2 + 0], o[jn][half_ * 2 + 1]);
            }
        }
    }
}

// ===========================================================================
// K3: out = LN(g_att @ w_out + b_out + gather(x))  fp16 mma + ldmatrix, BK=64
// CTA 64x256 (full rows), 8 warps (2m x 4n), warp tile 32x64. Occ 2.
// smem: buf{0,1}: A[64][72]h (9216) + B[256][72]h (36864), stride 46080;
//       arow @92160, s1 @92416, s2 @92672; total 92928.
// ===========================================================================
#define K3_SMEM 92928
__global__ __launch_bounds__(256, 2)
void out_mma(const float* __restrict__ x,
             const float* __restrict__ bout,
             const float* __restrict__ gamma,
             const float* __restrict__ beta,
             float* __restrict__ out)
{
    extern __shared__ char smem[];
    const uint32_t sbase = smem_u32(smem);
    int*   arow = (int*)(smem + 92160);
    float* s1   = (float*)(smem + 92416);
    float* s2   = (float*)(smem + 92672);

    const int tid  = threadIdx.x;
    const int wid  = tid >> 5;
    const int lane = tid & 31;
    const int m0   = blockIdx.x * 64;
    if (tid < 64) { arow[tid] = xrow_offset(m0 + tid); s1[tid] = 0.f; s2[tid] = 0.f; }

    const int wm = (wid >> 2) * 32;
    const int wn = (wid & 3) * 64;
    const int r0 = lane >> 2;
    const int kc = lane & 3;
    const int lj = lane >> 3;
    const int lq = lane & 7;

    const uint32_t a_off = (uint32_t)((wm + ((lj & 1) << 3) + lq) * 144 + ((lj >> 1) << 4));
    const uint32_t b_off = 9216u + (uint32_t)((wn + (((lj >> 1) & 1) << 3) + lq) * 144 + ((lj & 1) << 4));

    float acc[2][8][4];
    #pragma unroll
    for (int i = 0; i < 2; i++)
        #pragma unroll
        for (int j = 0; j < 8; j++)
            #pragma unroll
            for (int q = 0; q < 4; q++) acc[i][j][q] = 0.f;

    __syncthreads();

    // A: 64 rows x 8 chunks = 512 ops -> 2/thread; B: 256 x 8 = 2048 -> 8/thread
    #pragma unroll
    for (int i = 0; i < 2; i++) {
        int f = tid + i * 256;
        int r = f >> 3, q8 = (f & 7) << 3;
        CP16(sbase + (uint32_t)(r * 144 + q8 * 2), g_atth + (size_t)(m0 + r) * 256 + q8);
    }
    #pragma unroll
    for (int i = 0; i < 8; i++) {
        int f = tid + i * 256;
        int r = f >> 3, q8 = (f & 7) << 3;
        CP16(sbase + 9216 + (uint32_t)(r * 144 + q8 * 2), g_woutTh + (size_t)r * 256 + q8);
    }
    CP_COMMIT();

    #pragma unroll
    for (int it = 0; it < 4; it++) {
        if (it < 3) {
            uint32_t bo = (uint32_t)(((it + 1) & 1) * 46080);
            int kt = (it + 1) * 64;
            #pragma unroll
            for (int i = 0; i < 2; i++) {
                int f = tid + i * 256;
                int r = f >> 3, q8 = (f & 7) << 3;
                CP16(sbase + bo + (uint32_t)(r * 144 + q8 * 2),
                     g_atth + (size_t)(m0 + r) * 256 + kt + q8);
            }
            #pragma unroll
            for (int i = 0; i < 8; i++) {
                int f = tid + i * 256;
                int r = f >> 3, q8 = (f & 7) << 3;
                CP16(sbase + bo + 9216 + (uint32_t)(r * 144 + q8 * 2),
                     g_woutTh + (size_t)r * 256 + kt + q8);
            }
            CP_COMMIT();
            CP_WAIT(1);
        } else {
            CP_WAIT(0);
        }
        __syncthreads();

        const uint32_t bufb = sbase + (uint32_t)((it & 1) * 46080);

        #pragma unroll
        for (int k16 = 0; k16 < 64; k16 += 16) {
            uint32_t a[2][4], b2[4][4];
            #pragma unroll
            for (int im = 0; im < 2; im++)
                ldsm_x4(a[im][0], a[im][1], a[im][2], a[im][3],
                        bufb + a_off + (uint32_t)(im * 2304 + k16 * 2));
            #pragma unroll
            for (int g = 0; g < 4; g++)
                ldsm_x4(b2[g][0], b2[g][1], b2[g][2], b2[g][3],
                        bufb + b_off + (uint32_t)(g * 2304 + k16 * 2));
            #pragma unroll
            for (int im = 0; im < 2; im++)
                #pragma unroll
                for (int in_ = 0; in_ < 8; in_++)
                    mma16(acc[im][in_], a[im][0], a[im][1], a[im][2], a[im][3],
                          b2[in_ >> 1][(in_ & 1) << 1], b2[in_ >> 1][((in_ & 1) << 1) + 1]);
        }
        __syncthreads();
    }

    // ---- epilogue: y = acc + bias + residual(fp32); LN over full rows ----
    #pragma unroll
    for (int im = 0; im < 2; im++) {
        #pragma unroll
        for (int half_ = 0; half_ < 2; half_++) {
            int rl = wm + im * 16 + r0 + half_ * 8;
            const float* xr = x + arow[rl];
            float p1 = 0.f, p2 = 0.f;
            #pragma unroll
            for (int in_ = 0; in_ < 8; in_++) {
                int c = wn + in_ * 8 + kc * 2;
                float2 xv = *(const float2*)(xr + c);
                float y0 = acc[im][in_][half_ * 2 + 0] + bout[c]     + xv.x;
                float y1 = acc[im][in_][half_ * 2 + 1] + bout[c + 1] + xv.y;
                acc[im][in_][half_ * 2 + 0] = y0;
                acc[im][in_][half_ * 2 + 1] = y1;
                p1 += y0 + y1;
                p2 += y0 * y0 + y1 * y1;
            }
            p1 += __shfl_xor_sync(0xffffffffu, p1, 1);
            p2 += __shfl_xor_sync(0xffffffffu, p2, 1);
            p1 += __shfl_xor_sync(0xffffffffu, p1, 2);
            p2 += __shfl_xor_sync(0xffffffffu, p2, 2);
            if (kc == 0) {
                atomicAdd(&s1[rl], p1);
                atomicAdd(&s2[rl], p2);
            }
        }
    }
    __syncthreads();

    #pragma unroll
    for (int im = 0; im < 2; im++) {
        #pragma unroll
        for (int half_ = 0; half_ < 2; half_++) {
            int rl = wm + im * 16 + r0 + half_ * 8;
            int m  = m0 + rl;
            float mean = s1[rl] * (1.0f / 256.0f);
            float var  = s2[rl] * (1.0f / 256.0f) - mean * mean;
            float rstd = rsqrtf(var + 1e-5f);
            #pragma unroll
            for (int in_ = 0; in_ < 8; in_++) {
                int c = wn + in_ * 8 + kc * 2;
                float y0 = acc[im][in_][half_ * 2 + 0];
                float y1 = acc[im][in_][half_ * 2 + 1];
                float2 o = make_float2((y0 - mean) * rstd * gamma[c]     + beta[c],
                                       (y1 - mean) * rstd * gamma[c + 1] + beta[c + 1]);
                *(float2*)(out + (size_t)m * 256 + c) = o;
            }
        }
    }
}

// ===========================================================================
extern "C" void kernel_launch(void* const* d_in, const int* in_sizes, int n_in,
                              void* d_out, int out_size)
{
    const float* x          = (const float*)d_in[0];
    const float* w_qkv      = (const float*)d_in[1];
    const float* b_qkv      = (const float*)d_in[2];
    const float* bias_table = (const float*)d_in[3];
    const float* w_out      = (const float*)d_in[4];
    const float* b_out      = (const float*)d_in[5];
    const float* ln_gamma   = (const float*)d_in[6];
    const float* ln_beta    = (const float*)d_in[7];
    float* out = (float*)d_out;

    cudaFuncSetAttribute(qkv_attn_p, cudaFuncAttributeMaxDynamicSharedMemorySize, FUSED_SMEM);
    cudaFuncSetAttribute(out_mma, cudaFuncAttributeMaxDynamicSharedMemorySize, K3_SMEM);

    prep_xh<<<50176, 256>>>((const float4*)x);
    prep_wh<<<(256 * 768 + 255) / 256, 256>>>(w_qkv, 256, 768, 0);
    prep_wh<<<(256 * 256 + 255) / 256, 256>>>(w_out, 256, 256, 1);
    prep_bias<<<128, 256>>>(bias_table);
    qkv_attn_p<<<NPCTA, 256, FUSED_SMEM>>>(b_qkv);
    out_mma<<<MTOT / 64, 256, K3_SMEM>>>(x, b_out, ln_gamma, ln_beta, out);
}